// round 2
// baseline (speedup 1.0000x reference)
#include <cuda_runtime.h>
#include <cstdint>

// ---------------------------------------------------------------------------
// GraphSAGE with LSTM aggregation, 3 layers.
//   layer l:  neigh = x[src2d]            [N,16,128]  (gather)
//             aggr  = LSTM_last(neigh)    [N,128]     (16 sequential steps)
//             y     = aggr@Wl^T + bl + x@Wr^T  (+ReLU for layers 1,2)
//
// Per LSTM step: G[m,0:512] = concat(x_t[m], h[m]) @ [Wih|Whh]^T + (bih+bhh)
// computed by a tiled fp32 GEMM using packed fma.rn.f32x2 (2 FMA/lane),
// then a pointwise LSTM state update.
// ---------------------------------------------------------------------------

#define NN   50000
#define DEG  16
#define FDIM 128
#define GDIM 512

// scratch (static __device__ arrays: allocation-free per harness rules)
__device__ float g_H [NN * FDIM];   // LSTM hidden state / aggr
__device__ float g_C [NN * FDIM];   // LSTM cell state
__device__ float g_G [NN * GDIM];   // gate pre-activations
__device__ float g_A1[NN * FDIM];   // layer-1 output
__device__ float g_A2[NN * FDIM];   // layer-2 output

// ---- packed f32x2 helpers --------------------------------------------------
__device__ __forceinline__ unsigned long long pack2(float x, float y) {
    unsigned long long r;
    unsigned int xi = __float_as_uint(x), yi = __float_as_uint(y);
    asm("mov.b64 %0, {%1, %2};" : "=l"(r) : "r"(xi), "r"(yi));
    return r;
}
__device__ __forceinline__ unsigned long long fma2(unsigned long long a,
                                                   unsigned long long b,
                                                   unsigned long long c) {
    unsigned long long d;
    asm("fma.rn.f32x2 %0, %1, %2, %3;" : "=l"(d) : "l"(a), "l"(b), "l"(c));
    return d;
}
__device__ __forceinline__ float2 unpack2(unsigned long long v) {
    unsigned int lo, hi;
    asm("mov.b64 {%0, %1}, %2;" : "=r"(lo), "=r"(hi) : "l"(v));
    return make_float2(__uint_as_float(lo), __uint_as_float(hi));
}

// ---------------------------------------------------------------------------
// gates GEMM: G[m, n] = sum_{k<128} X[src[m*16+t]][k] * Wih[n][k]
//                     + sum_{k<128} g_H[m][k]         * Whh[n][k]
//                     + bih[n] + bhh[n]
// Tile: BM=64, BN=128, BK=16; 256 threads; per-thread 4(m) x 8(n) outputs
// held as 4x4 packed f32x2 accumulators.
// ---------------------------------------------------------------------------
__global__ __launch_bounds__(256)
void gates_kernel(const float* __restrict__ X, const int* __restrict__ src, int t,
                  const float* __restrict__ Wih, const float* __restrict__ Whh,
                  const float* __restrict__ bih, const float* __restrict__ bhh)
{
    __shared__ float As[16][72];    // [k][m], padded
    __shared__ float Bs[16][136];   // [k][n], padded

    const int tid = threadIdx.x;
    const int m0 = blockIdx.x * 64;
    const int n0 = blockIdx.y * 128;
    const int tm = tid & 15;        // 16 m-groups
    const int tn = tid >> 4;        // 16 n-groups

    unsigned long long acc[4][4];
#pragma unroll
    for (int i = 0; i < 4; i++)
#pragma unroll
        for (int j = 0; j < 4; j++) acc[i][j] = 0ull;

    // A loader: threads 0..127, each loads 8 consecutive k of one row
    const int mA  = tid >> 1;
    const int kA0 = (tid & 1) * 8;
    const float* arowx = nullptr;
    const float* arowh = nullptr;
    if (tid < 128) {
        int node = m0 + mA;
        if (node < NN) {
            arowx = X + (size_t)src[node * DEG + t] * FDIM;
            arowh = g_H + (size_t)node * FDIM;
        }
    }
    // B loader: all 256 threads, each loads 8 consecutive k of one weight row
    const int nB  = tid >> 1;
    const int kB0 = (tid & 1) * 8;
    const float* browi = Wih + (size_t)(n0 + nB) * FDIM;
    const float* browh = Whh + (size_t)(n0 + nB) * FDIM;

    for (int k0 = 0; k0 < 256; k0 += 16) {
        float4 a0 = make_float4(0.f, 0.f, 0.f, 0.f), a1 = a0;
        if (tid < 128 && arowx) {
            const float* ar = (k0 < 128) ? (arowx + k0) : (arowh + k0 - 128);
            a0 = *(const float4*)(ar + kA0);
            a1 = *(const float4*)(ar + kA0 + 4);
        }
        const float* br = (k0 < 128) ? (browi + k0) : (browh + k0 - 128);
        float4 b0 = *(const float4*)(br + kB0);
        float4 b1 = *(const float4*)(br + kB0 + 4);

        __syncthreads();
        if (tid < 128) {
            As[kA0 + 0][mA] = a0.x; As[kA0 + 1][mA] = a0.y;
            As[kA0 + 2][mA] = a0.z; As[kA0 + 3][mA] = a0.w;
            As[kA0 + 4][mA] = a1.x; As[kA0 + 5][mA] = a1.y;
            As[kA0 + 6][mA] = a1.z; As[kA0 + 7][mA] = a1.w;
        }
        Bs[kB0 + 0][nB] = b0.x; Bs[kB0 + 1][nB] = b0.y;
        Bs[kB0 + 2][nB] = b0.z; Bs[kB0 + 3][nB] = b0.w;
        Bs[kB0 + 4][nB] = b1.x; Bs[kB0 + 5][nB] = b1.y;
        Bs[kB0 + 6][nB] = b1.z; Bs[kB0 + 7][nB] = b1.w;
        __syncthreads();

#pragma unroll
        for (int kk = 0; kk < 16; kk++) {
            float4 av = *(const float4*)(&As[kk][tm * 4]);
            unsigned long long ap[4];
            ap[0] = pack2(av.x, av.x); ap[1] = pack2(av.y, av.y);
            ap[2] = pack2(av.z, av.z); ap[3] = pack2(av.w, av.w);
            const unsigned long long* bp =
                (const unsigned long long*)(&Bs[kk][tn * 8]);
            unsigned long long bq0 = bp[0], bq1 = bp[1], bq2 = bp[2], bq3 = bp[3];
#pragma unroll
            for (int i = 0; i < 4; i++) {
                acc[i][0] = fma2(ap[i], bq0, acc[i][0]);
                acc[i][1] = fma2(ap[i], bq1, acc[i][1]);
                acc[i][2] = fma2(ap[i], bq2, acc[i][2]);
                acc[i][3] = fma2(ap[i], bq3, acc[i][3]);
            }
        }
    }

#pragma unroll
    for (int i = 0; i < 4; i++) {
        int m = m0 + tm * 4 + i;
        if (m >= NN) continue;
        float* gout = g_G + (size_t)m * GDIM + n0 + tn * 8;
#pragma unroll
        for (int j = 0; j < 4; j++) {
            float2 v = unpack2(acc[i][j]);
            int n = n0 + tn * 8 + 2 * j;
            gout[2 * j + 0] = v.x + bih[n + 0] + bhh[n + 0];
            gout[2 * j + 1] = v.y + bih[n + 1] + bhh[n + 1];
        }
    }
}

// ---------------------------------------------------------------------------
// pointwise LSTM state update (gate order i,f,g,o)
// ---------------------------------------------------------------------------
__global__ void lstm_update_kernel()
{
    int idx = blockIdx.x * blockDim.x + threadIdx.x;
    if (idx >= NN * FDIM) return;
    int m = idx >> 7, j = idx & 127;
    const float* g = g_G + (size_t)m * GDIM;
    float gi = g[j], gf = g[j + 128], gg = g[j + 256], go = g[j + 384];
    float si = 1.f / (1.f + expf(-gi));
    float sf = 1.f / (1.f + expf(-gf));
    float so = 1.f / (1.f + expf(-go));
    float c  = sf * g_C[idx] + si * tanhf(gg);
    g_C[idx] = c;
    g_H[idx] = so * tanhf(c);
}

__global__ void zero_hc_kernel()
{
    int idx = blockIdx.x * blockDim.x + threadIdx.x;
    if (idx >= NN * FDIM) return;
    g_H[idx] = 0.f;
    g_C[idx] = 0.f;
}

// ---------------------------------------------------------------------------
// output GEMM: Out[m, n] = aggr[m]@Wl[n] + X[m]@Wr[n] + bl[n]  (opt ReLU)
// aggr = g_H (final LSTM h). BN=128 tile covers Fo<=128 with guards.
// ---------------------------------------------------------------------------
template<bool RELU>
__global__ __launch_bounds__(256)
void out_kernel(const float* __restrict__ X,
                const float* __restrict__ Wl, const float* __restrict__ Wr,
                const float* __restrict__ bl, float* __restrict__ Out, int Fo)
{
    __shared__ float As[16][72];
    __shared__ float Bs[16][136];

    const int tid = threadIdx.x;
    const int m0 = blockIdx.x * 64;
    const int tm = tid & 15;
    const int tn = tid >> 4;

    unsigned long long acc[4][4];
#pragma unroll
    for (int i = 0; i < 4; i++)
#pragma unroll
        for (int j = 0; j < 4; j++) acc[i][j] = 0ull;

    const int mA  = tid >> 1;
    const int kA0 = (tid & 1) * 8;
    const float* arowa = nullptr;   // aggr (g_H)
    const float* arowx = nullptr;   // layer input
    if (tid < 128) {
        int node = m0 + mA;
        if (node < NN) {
            arowa = g_H + (size_t)node * FDIM;
            arowx = X + (size_t)node * FDIM;
        }
    }
    const int nB  = tid >> 1;
    const int kB0 = (tid & 1) * 8;
    const bool nb_ok = (nB < Fo);
    const float* browl = Wl + (size_t)nB * FDIM;
    const float* browr = Wr + (size_t)nB * FDIM;

    for (int k0 = 0; k0 < 256; k0 += 16) {
        float4 a0 = make_float4(0.f, 0.f, 0.f, 0.f), a1 = a0;
        if (tid < 128 && arowa) {
            const float* ar = (k0 < 128) ? (arowa + k0) : (arowx + k0 - 128);
            a0 = *(const float4*)(ar + kA0);
            a1 = *(const float4*)(ar + kA0 + 4);
        }
        float4 b0 = make_float4(0.f, 0.f, 0.f, 0.f), b1 = b0;
        if (nb_ok) {
            const float* br = (k0 < 128) ? (browl + k0) : (browr + k0 - 128);
            b0 = *(const float4*)(br + kB0);
            b1 = *(const float4*)(br + kB0 + 4);
        }

        __syncthreads();
        if (tid < 128) {
            As[kA0 + 0][mA] = a0.x; As[kA0 + 1][mA] = a0.y;
            As[kA0 + 2][mA] = a0.z; As[kA0 + 3][mA] = a0.w;
            As[kA0 + 4][mA] = a1.x; As[kA0 + 5][mA] = a1.y;
            As[kA0 + 6][mA] = a1.z; As[kA0 + 7][mA] = a1.w;
        }
        Bs[kB0 + 0][nB] = b0.x; Bs[kB0 + 1][nB] = b0.y;
        Bs[kB0 + 2][nB] = b0.z; Bs[kB0 + 3][nB] = b0.w;
        Bs[kB0 + 4][nB] = b1.x; Bs[kB0 + 5][nB] = b1.y;
        Bs[kB0 + 6][nB] = b1.z; Bs[kB0 + 7][nB] = b1.w;
        __syncthreads();

#pragma unroll
        for (int kk = 0; kk < 16; kk++) {
            float4 av = *(const float4*)(&As[kk][tm * 4]);
            unsigned long long ap[4];
            ap[0] = pack2(av.x, av.x); ap[1] = pack2(av.y, av.y);
            ap[2] = pack2(av.z, av.z); ap[3] = pack2(av.w, av.w);
            const unsigned long long* bp =
                (const unsigned long long*)(&Bs[kk][tn * 8]);
            unsigned long long bq0 = bp[0], bq1 = bp[1], bq2 = bp[2], bq3 = bp[3];
#pragma unroll
            for (int i = 0; i < 4; i++) {
                acc[i][0] = fma2(ap[i], bq0, acc[i][0]);
                acc[i][1] = fma2(ap[i], bq1, acc[i][1]);
                acc[i][2] = fma2(ap[i], bq2, acc[i][2]);
                acc[i][3] = fma2(ap[i], bq3, acc[i][3]);
            }
        }
    }

#pragma unroll
    for (int i = 0; i < 4; i++) {
        int m = m0 + tm * 4 + i;
        if (m >= NN) continue;
#pragma unroll
        for (int j = 0; j < 4; j++) {
            float2 v = unpack2(acc[i][j]);
            int n = tn * 8 + 2 * j;
            if (n < Fo) {
                float o0 = v.x + bl[n];
                if (RELU) o0 = fmaxf(o0, 0.f);
                Out[(size_t)m * Fo + n] = o0;
            }
            if (n + 1 < Fo) {
                float o1 = v.y + bl[n + 1];
                if (RELU) o1 = fmaxf(o1, 0.f);
                Out[(size_t)m * Fo + n + 1] = o1;
            }
        }
    }
}

// ---------------------------------------------------------------------------
// host launcher
// ---------------------------------------------------------------------------
extern "C" void kernel_launch(void* const* d_in, const int* in_sizes, int n_in,
                              void* d_out, int out_size)
{
    (void)in_sizes; (void)n_in; (void)out_size;
    const float* x   = (const float*)d_in[0];
    const int*   src = (const int*)d_in[1];   // edge_index row 0 = src (E=800000)

    const float* P[21];
    for (int i = 0; i < 21; i++) P[i] = (const float*)d_in[2 + i];
    // per layer: W_ih, W_hh, b_ih, b_hh, Wl, bl, Wr

    float *a1 = nullptr, *a2 = nullptr;
    cudaGetSymbolAddress((void**)&a1, g_A1);
    cudaGetSymbolAddress((void**)&a2, g_A2);

    const dim3 blk(256);
    const dim3 gGates((NN + 63) / 64, 4);
    const dim3 gOut((NN + 63) / 64, 1);
    const int upBlocks = (NN * FDIM + 255) / 256;

    const float* Xin = x;
    for (int l = 0; l < 3; l++) {
        const float* Wih = P[7 * l + 0];
        const float* Whh = P[7 * l + 1];
        const float* bih = P[7 * l + 2];
        const float* bhh = P[7 * l + 3];
        const float* Wl  = P[7 * l + 4];
        const float* bl  = P[7 * l + 5];
        const float* Wr  = P[7 * l + 6];

        zero_hc_kernel<<<upBlocks, blk>>>();
        for (int t = 0; t < DEG; t++) {
            gates_kernel<<<gGates, blk>>>(Xin, src, t, Wih, Whh, bih, bhh);
            lstm_update_kernel<<<upBlocks, blk>>>();
        }
        if (l == 0) {
            out_kernel<true><<<gOut, blk>>>(Xin, Wl, Wr, bl, a1, 128);
            Xin = a1;
        } else if (l == 1) {
            out_kernel<true><<<gOut, blk>>>(Xin, Wl, Wr, bl, a2, 128);
            Xin = a2;
        } else {
            out_kernel<false><<<gOut, blk>>>(Xin, Wl, Wr, bl, (float*)d_out, 64);
        }
    }
}

// round 5
// speedup vs baseline: 1.0017x; 1.0017x over previous
#include <cuda_runtime.h>
#include <cstdint>

// ---------------------------------------------------------------------------
// GraphSAGE with LSTM aggregation, 3 layers.
//   layer l:  neigh = x[src2d]            [N,16,128]  (gather)
//             aggr  = LSTM_last(neigh)    [N,128]     (16 sequential steps)
//             y     = aggr@Wl^T + bl + x@Wr^T  (+ReLU for layers 1,2)
//
// Per LSTM step: G[m,0:512] = concat(x_t[m], h[m]) @ [Wih|Whh]^T + (bih+bhh)
// computed by a tiled fp32 GEMM using packed fma.rn.f32x2 (2 FMA/lane),
// then a pointwise LSTM state update.
// ---------------------------------------------------------------------------

#define NN   50000
#define DEG  16
#define FDIM 128
#define GDIM 512

// scratch (static __device__ arrays: allocation-free per harness rules)
__device__ float g_H [NN * FDIM];   // LSTM hidden state / aggr
__device__ float g_C [NN * FDIM];   // LSTM cell state
__device__ float g_G [NN * GDIM];   // gate pre-activations
__device__ float g_A1[NN * FDIM];   // layer-1 output
__device__ float g_A2[NN * FDIM];   // layer-2 output

// ---- packed f32x2 helpers --------------------------------------------------
__device__ __forceinline__ unsigned long long pack2(float x, float y) {
    unsigned long long r;
    unsigned int xi = __float_as_uint(x), yi = __float_as_uint(y);
    asm("mov.b64 %0, {%1, %2};" : "=l"(r) : "r"(xi), "r"(yi));
    return r;
}
__device__ __forceinline__ unsigned long long fma2(unsigned long long a,
                                                   unsigned long long b,
                                                   unsigned long long c) {
    unsigned long long d;
    asm("fma.rn.f32x2 %0, %1, %2, %3;" : "=l"(d) : "l"(a), "l"(b), "l"(c));
    return d;
}
__device__ __forceinline__ float2 unpack2(unsigned long long v) {
    unsigned int lo, hi;
    asm("mov.b64 {%0, %1}, %2;" : "=r"(lo), "=r"(hi) : "l"(v));
    return make_float2(__uint_as_float(lo), __uint_as_float(hi));
}

// ---------------------------------------------------------------------------
// gates GEMM: G[m, n] = sum_{k<128} X[src[m*16+t]][k] * Wih[n][k]
//                     + sum_{k<128} g_H[m][k]         * Whh[n][k]
//                     + bih[n] + bhh[n]
// Tile: BM=64, BN=128, BK=16; 256 threads; per-thread 4(m) x 8(n) outputs
// held as 4x4 packed f32x2 accumulators.
// ---------------------------------------------------------------------------
__global__ __launch_bounds__(256)
void gates_kernel(const float* __restrict__ X, const int* __restrict__ src, int t,
                  const float* __restrict__ Wih, const float* __restrict__ Whh,
                  const float* __restrict__ bih, const float* __restrict__ bhh)
{
    __shared__ float As[16][72];    // [k][m], padded
    __shared__ float Bs[16][136];   // [k][n], padded

    const int tid = threadIdx.x;
    const int m0 = blockIdx.x * 64;
    const int n0 = blockIdx.y * 128;
    const int tm = tid & 15;        // 16 m-groups
    const int tn = tid >> 4;        // 16 n-groups

    unsigned long long acc[4][4];
#pragma unroll
    for (int i = 0; i < 4; i++)
#pragma unroll
        for (int j = 0; j < 4; j++) acc[i][j] = 0ull;

    // A loader: threads 0..127, each loads 8 consecutive k of one row
    const int mA  = tid >> 1;
    const int kA0 = (tid & 1) * 8;
    const float* arowx = nullptr;
    const float* arowh = nullptr;
    if (tid < 128) {
        int node = m0 + mA;
        if (node < NN) {
            arowx = X + (size_t)src[node * DEG + t] * FDIM;
            arowh = g_H + (size_t)node * FDIM;
        }
    }
    // B loader: all 256 threads, each loads 8 consecutive k of one weight row
    const int nB  = tid >> 1;
    const int kB0 = (tid & 1) * 8;
    const float* browi = Wih + (size_t)(n0 + nB) * FDIM;
    const float* browh = Whh + (size_t)(n0 + nB) * FDIM;

    for (int k0 = 0; k0 < 256; k0 += 16) {
        float4 a0 = make_float4(0.f, 0.f, 0.f, 0.f), a1 = a0;
        if (tid < 128 && arowx) {
            const float* ar = (k0 < 128) ? (arowx + k0) : (arowh + k0 - 128);
            a0 = *(const float4*)(ar + kA0);
            a1 = *(const float4*)(ar + kA0 + 4);
        }
        const float* br = (k0 < 128) ? (browi + k0) : (browh + k0 - 128);
        float4 b0 = *(const float4*)(br + kB0);
        float4 b1 = *(const float4*)(br + kB0 + 4);

        __syncthreads();
        if (tid < 128) {
            As[kA0 + 0][mA] = a0.x; As[kA0 + 1][mA] = a0.y;
            As[kA0 + 2][mA] = a0.z; As[kA0 + 3][mA] = a0.w;
            As[kA0 + 4][mA] = a1.x; As[kA0 + 5][mA] = a1.y;
            As[kA0 + 6][mA] = a1.z; As[kA0 + 7][mA] = a1.w;
        }
        Bs[kB0 + 0][nB] = b0.x; Bs[kB0 + 1][nB] = b0.y;
        Bs[kB0 + 2][nB] = b0.z; Bs[kB0 + 3][nB] = b0.w;
        Bs[kB0 + 4][nB] = b1.x; Bs[kB0 + 5][nB] = b1.y;
        Bs[kB0 + 6][nB] = b1.z; Bs[kB0 + 7][nB] = b1.w;
        __syncthreads();

#pragma unroll
        for (int kk = 0; kk < 16; kk++) {
            float4 av = *(const float4*)(&As[kk][tm * 4]);
            unsigned long long ap[4];
            ap[0] = pack2(av.x, av.x); ap[1] = pack2(av.y, av.y);
            ap[2] = pack2(av.z, av.z); ap[3] = pack2(av.w, av.w);
            const unsigned long long* bp =
                (const unsigned long long*)(&Bs[kk][tn * 8]);
            unsigned long long bq0 = bp[0], bq1 = bp[1], bq2 = bp[2], bq3 = bp[3];
#pragma unroll
            for (int i = 0; i < 4; i++) {
                acc[i][0] = fma2(ap[i], bq0, acc[i][0]);
                acc[i][1] = fma2(ap[i], bq1, acc[i][1]);
                acc[i][2] = fma2(ap[i], bq2, acc[i][2]);
                acc[i][3] = fma2(ap[i], bq3, acc[i][3]);
            }
        }
    }

#pragma unroll
    for (int i = 0; i < 4; i++) {
        int m = m0 + tm * 4 + i;
        if (m >= NN) continue;
        float* gout = g_G + (size_t)m * GDIM + n0 + tn * 8;
#pragma unroll
        for (int j = 0; j < 4; j++) {
            float2 v = unpack2(acc[i][j]);
            int n = n0 + tn * 8 + 2 * j;
            gout[2 * j + 0] = v.x + bih[n + 0] + bhh[n + 0];
            gout[2 * j + 1] = v.y + bih[n + 1] + bhh[n + 1];
        }
    }
}

// ---------------------------------------------------------------------------
// pointwise LSTM state update (gate order i,f,g,o)
// ---------------------------------------------------------------------------
__global__ void lstm_update_kernel()
{
    int idx = blockIdx.x * blockDim.x + threadIdx.x;
    if (idx >= NN * FDIM) return;
    int m = idx >> 7, j = idx & 127;
    const float* g = g_G + (size_t)m * GDIM;
    float gi = g[j], gf = g[j + 128], gg = g[j + 256], go = g[j + 384];
    float si = 1.f / (1.f + expf(-gi));
    float sf = 1.f / (1.f + expf(-gf));
    float so = 1.f / (1.f + expf(-go));
    float c  = sf * g_C[idx] + si * tanhf(gg);
    g_C[idx] = c;
    g_H[idx] = so * tanhf(c);
}

__global__ void zero_hc_kernel()
{
    int idx = blockIdx.x * blockDim.x + threadIdx.x;
    if (idx >= NN * FDIM) return;
    g_H[idx] = 0.f;
    g_C[idx] = 0.f;
}

// ---------------------------------------------------------------------------
// output GEMM: Out[m, n] = aggr[m]@Wl[n] + X[m]@Wr[n] + bl[n]  (opt ReLU)
// aggr = g_H (final LSTM h). BN=128 tile covers Fo<=128 with guards.
// ---------------------------------------------------------------------------
template<bool RELU>
__global__ __launch_bounds__(256)
void out_kernel(const float* __restrict__ X,
                const float* __restrict__ Wl, const float* __restrict__ Wr,
                const float* __restrict__ bl, float* __restrict__ Out, int Fo)
{
    __shared__ float As[16][72];
    __shared__ float Bs[16][136];

    const int tid = threadIdx.x;
    const int m0 = blockIdx.x * 64;
    const int tm = tid & 15;
    const int tn = tid >> 4;

    unsigned long long acc[4][4];
#pragma unroll
    for (int i = 0; i < 4; i++)
#pragma unroll
        for (int j = 0; j < 4; j++) acc[i][j] = 0ull;

    const int mA  = tid >> 1;
    const int kA0 = (tid & 1) * 8;
    const float* arowa = nullptr;   // aggr (g_H)
    const float* arowx = nullptr;   // layer input
    if (tid < 128) {
        int node = m0 + mA;
        if (node < NN) {
            arowa = g_H + (size_t)node * FDIM;
            arowx = X + (size_t)node * FDIM;
        }
    }
    const int nB  = tid >> 1;
    const int kB0 = (tid & 1) * 8;
    const bool nb_ok = (nB < Fo);
    const float* browl = Wl + (size_t)nB * FDIM;
    const float* browr = Wr + (size_t)nB * FDIM;

    for (int k0 = 0; k0 < 256; k0 += 16) {
        float4 a0 = make_float4(0.f, 0.f, 0.f, 0.f), a1 = a0;
        if (tid < 128 && arowa) {
            const float* ar = (k0 < 128) ? (arowa + k0) : (arowx + k0 - 128);
            a0 = *(const float4*)(ar + kA0);
            a1 = *(const float4*)(ar + kA0 + 4);
        }
        float4 b0 = make_float4(0.f, 0.f, 0.f, 0.f), b1 = b0;
        if (nb_ok) {
            const float* br = (k0 < 128) ? (browl + k0) : (browr + k0 - 128);
            b0 = *(const float4*)(br + kB0);
            b1 = *(const float4*)(br + kB0 + 4);
        }

        __syncthreads();
        if (tid < 128) {
            As[kA0 + 0][mA] = a0.x; As[kA0 + 1][mA] = a0.y;
            As[kA0 + 2][mA] = a0.z; As[kA0 + 3][mA] = a0.w;
            As[kA0 + 4][mA] = a1.x; As[kA0 + 5][mA] = a1.y;
            As[kA0 + 6][mA] = a1.z; As[kA0 + 7][mA] = a1.w;
        }
        Bs[kB0 + 0][nB] = b0.x; Bs[kB0 + 1][nB] = b0.y;
        Bs[kB0 + 2][nB] = b0.z; Bs[kB0 + 3][nB] = b0.w;
        Bs[kB0 + 4][nB] = b1.x; Bs[kB0 + 5][nB] = b1.y;
        Bs[kB0 + 6][nB] = b1.z; Bs[kB0 + 7][nB] = b1.w;
        __syncthreads();

#pragma unroll
        for (int kk = 0; kk < 16; kk++) {
            float4 av = *(const float4*)(&As[kk][tm * 4]);
            unsigned long long ap[4];
            ap[0] = pack2(av.x, av.x); ap[1] = pack2(av.y, av.y);
            ap[2] = pack2(av.z, av.z); ap[3] = pack2(av.w, av.w);
            const unsigned long long* bp =
                (const unsigned long long*)(&Bs[kk][tn * 8]);
            unsigned long long bq0 = bp[0], bq1 = bp[1], bq2 = bp[2], bq3 = bp[3];
#pragma unroll
            for (int i = 0; i < 4; i++) {
                acc[i][0] = fma2(ap[i], bq0, acc[i][0]);
                acc[i][1] = fma2(ap[i], bq1, acc[i][1]);
                acc[i][2] = fma2(ap[i], bq2, acc[i][2]);
                acc[i][3] = fma2(ap[i], bq3, acc[i][3]);
            }
        }
    }

#pragma unroll
    for (int i = 0; i < 4; i++) {
        int m = m0 + tm * 4 + i;
        if (m >= NN) continue;
#pragma unroll
        for (int j = 0; j < 4; j++) {
            float2 v = unpack2(acc[i][j]);
            int n = tn * 8 + 2 * j;
            if (n < Fo) {
                float o0 = v.x + bl[n];
                if (RELU) o0 = fmaxf(o0, 0.f);
                Out[(size_t)m * Fo + n] = o0;
            }
            if (n + 1 < Fo) {
                float o1 = v.y + bl[n + 1];
                if (RELU) o1 = fmaxf(o1, 0.f);
                Out[(size_t)m * Fo + n + 1] = o1;
            }
        }
    }
}

// ---------------------------------------------------------------------------
// host launcher
// ---------------------------------------------------------------------------
extern "C" void kernel_launch(void* const* d_in, const int* in_sizes, int n_in,
                              void* d_out, int out_size)
{
    (void)in_sizes; (void)n_in; (void)out_size;
    const float* x   = (const float*)d_in[0];
    const int*   src = (const int*)d_in[1];   // edge_index row 0 = src (E=800000)

    const float* P[21];
    for (int i = 0; i < 21; i++) P[i] = (const float*)d_in[2 + i];
    // per layer: W_ih, W_hh, b_ih, b_hh, Wl, bl, Wr

    float *a1 = nullptr, *a2 = nullptr;
    cudaGetSymbolAddress((void**)&a1, g_A1);
    cudaGetSymbolAddress((void**)&a2, g_A2);

    const dim3 blk(256);
    const dim3 gGates((NN + 63) / 64, 4);
    const dim3 gOut((NN + 63) / 64, 1);
    const int upBlocks = (NN * FDIM + 255) / 256;

    const float* Xin = x;
    for (int l = 0; l < 3; l++) {
        const float* Wih = P[7 * l + 0];
        const float* Whh = P[7 * l + 1];
        const float* bih = P[7 * l + 2];
        const float* bhh = P[7 * l + 3];
        const float* Wl  = P[7 * l + 4];
        const float* bl  = P[7 * l + 5];
        const float* Wr  = P[7 * l + 6];

        zero_hc_kernel<<<upBlocks, blk>>>();
        for (int t = 0; t < DEG; t++) {
            gates_kernel<<<gGates, blk>>>(Xin, src, t, Wih, Whh, bih, bhh);
            lstm_update_kernel<<<upBlocks, blk>>>();
        }
        if (l == 0) {
            out_kernel<true><<<gOut, blk>>>(Xin, Wl, Wr, bl, a1, 128);
            Xin = a1;
        } else if (l == 1) {
            out_kernel<true><<<gOut, blk>>>(Xin, Wl, Wr, bl, a2, 128);
            Xin = a2;
        } else {
            out_kernel<false><<<gOut, blk>>>(Xin, Wl, Wr, bl, (float*)d_out, 64);
        }
    }
}

// round 6
// speedup vs baseline: 2.7909x; 2.7862x over previous
#include <cuda_runtime.h>
#include <cstdint>

// ---------------------------------------------------------------------------
// GraphSAGE with LSTM aggregation, 3 layers — round 5.
//
// Per layer:
//   1) transpose Whh -> Wt[128][512]
//   2) P = X @ Wih^T + (bih+bhh)                 [50000, 512]   (one GEMM)
//   3) fused LSTM: each block owns 32 nodes, runs all 16 steps:
//        G = gather(P[src[m,t]]) + h @ Wt   (h in smem, Wt streamed cp.async)
//        pointwise update in-register, h back to smem
//   4) out = lin_l(h_final) + lin_r(X) (+ReLU)
// ---------------------------------------------------------------------------

#define NN   50000
#define DEG  16
#define FDIM 128
#define GDIM 512
#define BM   32          // nodes per block in fused kernel

__device__ float g_H [NN * FDIM];     // final aggr per layer
__device__ float g_P [NN * GDIM];     // precomputed input projection + bias
__device__ float g_Wt[FDIM * GDIM];   // Whh transposed: [k][n]
__device__ float g_A1[NN * FDIM];
__device__ float g_A2[NN * FDIM];

// ---- packed f32x2 helpers --------------------------------------------------
__device__ __forceinline__ unsigned long long pack2(float x, float y) {
    unsigned long long r;
    unsigned int xi = __float_as_uint(x), yi = __float_as_uint(y);
    asm("mov.b64 %0, {%1, %2};" : "=l"(r) : "r"(xi), "r"(yi));
    return r;
}
__device__ __forceinline__ unsigned long long fma2(unsigned long long a,
                                                   unsigned long long b,
                                                   unsigned long long c) {
    unsigned long long d;
    asm("fma.rn.f32x2 %0, %1, %2, %3;" : "=l"(d) : "l"(a), "l"(b), "l"(c));
    return d;
}
__device__ __forceinline__ float2 unpack2(unsigned long long v) {
    unsigned int lo, hi;
    asm("mov.b64 {%0, %1}, %2;" : "=r"(lo), "=r"(hi) : "l"(v));
    return make_float2(__uint_as_float(lo), __uint_as_float(hi));
}

// ---- fast activations ------------------------------------------------------
__device__ __forceinline__ float fsig(float x) {
    return __fdividef(1.f, 1.f + __expf(-x));
}
__device__ __forceinline__ float ftanh(float x) {
    float xx = fminf(fmaxf(x, -20.f), 20.f);
    float e = __expf(2.f * xx);
    return __fdividef(e - 1.f, e + 1.f);
}

// ---- cp.async helpers ------------------------------------------------------
__device__ __forceinline__ void cp16(uint32_t saddr, const void* gaddr) {
    asm volatile("cp.async.cg.shared.global [%0], [%1], 16;"
                 :: "r"(saddr), "l"(gaddr));
}
__device__ __forceinline__ void cp_commit() {
    asm volatile("cp.async.commit_group;");
}
__device__ __forceinline__ void cp_wait1() {
    asm volatile("cp.async.wait_group 1;");
}
__device__ __forceinline__ void cp_wait0() {
    asm volatile("cp.async.wait_group 0;");
}

// ---------------------------------------------------------------------------
// Whh [512][128] -> Wt [128][512]
// ---------------------------------------------------------------------------
__global__ void transpose_whh(const float* __restrict__ Whh)
{
    int idx = blockIdx.x * blockDim.x + threadIdx.x;
    if (idx >= FDIM * GDIM) return;
    int k = idx >> 9, n = idx & 511;
    g_Wt[idx] = Whh[n * FDIM + k];
}

// ---------------------------------------------------------------------------
// P = X @ Wih^T + (bih + bhh).  M=50000, N=512, K=128.
// BM=64, BN=128, BK=16; 256 threads; 4x8 per-thread via f32x2.
// ---------------------------------------------------------------------------
__global__ __launch_bounds__(256)
void pre_kernel(const float* __restrict__ X, const float* __restrict__ Wih,
                const float* __restrict__ bih, const float* __restrict__ bhh)
{
    __shared__ float As[16][72];
    __shared__ float Bs[16][136];

    const int tid = threadIdx.x;
    const int m0 = blockIdx.x * 64;
    const int n0 = blockIdx.y * 128;
    const int tm = tid & 15;
    const int tn = tid >> 4;

    unsigned long long acc[4][4];
#pragma unroll
    for (int i = 0; i < 4; i++)
#pragma unroll
        for (int j = 0; j < 4; j++) acc[i][j] = 0ull;

    const int mA  = tid >> 1;
    const int kA0 = (tid & 1) * 8;
    const float* arow = nullptr;
    if (tid < 128) {
        int node = m0 + mA;
        if (node < NN) arow = X + (size_t)node * FDIM;
    }
    const int nB  = tid >> 1;
    const int kB0 = (tid & 1) * 8;
    const float* brow = Wih + (size_t)(n0 + nB) * FDIM;

    for (int k0 = 0; k0 < 128; k0 += 16) {
        float4 a0 = make_float4(0.f, 0.f, 0.f, 0.f), a1 = a0;
        if (tid < 128 && arow) {
            a0 = *(const float4*)(arow + k0 + kA0);
            a1 = *(const float4*)(arow + k0 + kA0 + 4);
        }
        float4 b0 = *(const float4*)(brow + k0 + kB0);
        float4 b1 = *(const float4*)(brow + k0 + kB0 + 4);

        __syncthreads();
        if (tid < 128) {
            As[kA0 + 0][mA] = a0.x; As[kA0 + 1][mA] = a0.y;
            As[kA0 + 2][mA] = a0.z; As[kA0 + 3][mA] = a0.w;
            As[kA0 + 4][mA] = a1.x; As[kA0 + 5][mA] = a1.y;
            As[kA0 + 6][mA] = a1.z; As[kA0 + 7][mA] = a1.w;
        }
        Bs[kB0 + 0][nB] = b0.x; Bs[kB0 + 1][nB] = b0.y;
        Bs[kB0 + 2][nB] = b0.z; Bs[kB0 + 3][nB] = b0.w;
        Bs[kB0 + 4][nB] = b1.x; Bs[kB0 + 5][nB] = b1.y;
        Bs[kB0 + 6][nB] = b1.z; Bs[kB0 + 7][nB] = b1.w;
        __syncthreads();

#pragma unroll
        for (int kk = 0; kk < 16; kk++) {
            float4 av = *(const float4*)(&As[kk][tm * 4]);
            unsigned long long ap[4];
            ap[0] = pack2(av.x, av.x); ap[1] = pack2(av.y, av.y);
            ap[2] = pack2(av.z, av.z); ap[3] = pack2(av.w, av.w);
            const unsigned long long* bp =
                (const unsigned long long*)(&Bs[kk][tn * 8]);
            unsigned long long bq0 = bp[0], bq1 = bp[1], bq2 = bp[2], bq3 = bp[3];
#pragma unroll
            for (int i = 0; i < 4; i++) {
                acc[i][0] = fma2(ap[i], bq0, acc[i][0]);
                acc[i][1] = fma2(ap[i], bq1, acc[i][1]);
                acc[i][2] = fma2(ap[i], bq2, acc[i][2]);
                acc[i][3] = fma2(ap[i], bq3, acc[i][3]);
            }
        }
    }

#pragma unroll
    for (int i = 0; i < 4; i++) {
        int m = m0 + tm * 4 + i;
        if (m >= NN) continue;
        float* gout = g_P + (size_t)m * GDIM + n0 + tn * 8;
#pragma unroll
        for (int j = 0; j < 4; j++) {
            float2 v = unpack2(acc[i][j]);
            int n = n0 + tn * 8 + 2 * j;
            gout[2 * j + 0] = v.x + bih[n + 0] + bhh[n + 0];
            gout[2 * j + 1] = v.y + bih[n + 1] + bhh[n + 1];
        }
    }
}

// ---------------------------------------------------------------------------
// Fused 16-step LSTM. Block = 32 nodes, 256 threads.
// Thread (tm = tid>>6 in 0..3, tn = tid&63) computes gate columns
// {2tn, 2tn+1} x 4 gates for 8 rows (tm*8 .. tm*8+7).
// smem: Hs[128][36] (h, [k][m]), Cs[32][128] (c), Bs 2 x [16][512] (Wt chunks),
//       Ss[32*16] (src).
// ---------------------------------------------------------------------------
#define HS_PAD   36
#define HS_SIZE  (FDIM * HS_PAD)            // 4608 floats
#define CS_SIZE  (BM * FDIM)                // 4096 floats
#define BS_SIZE  (16 * GDIM)                // 8192 floats per buffer
#define SMEM_FUSED_BYTES ((HS_SIZE + CS_SIZE + 2 * BS_SIZE) * 4 + BM * DEG * 4)

__global__ __launch_bounds__(256, 2)
void fused_lstm_kernel(const int* __restrict__ src)
{
    extern __shared__ float sm[];
    float* Hs = sm;                          // [128][36]
    float* Cs = Hs + HS_SIZE;                // [32][128]
    float* Bs = Cs + CS_SIZE;                // 2 x [16][512]
    int*   Ss = (int*)(Bs + 2 * BS_SIZE);    // [32*16]

    const int tid = threadIdx.x;
    const int tm  = tid >> 6;                // 0..3
    const int tn  = tid & 63;                // 0..63
    const int m0  = blockIdx.x * BM;

    for (int i = tid; i < BM * DEG; i += 256) {
        int node = m0 + i / DEG;
        Ss[i] = (node < NN) ? src[node * DEG + i % DEG] : 0;
    }
    for (int i = tid; i < HS_SIZE; i += 256) Hs[i] = 0.f;
    for (int i = tid; i < CS_SIZE; i += 256) Cs[i] = 0.f;
    __syncthreads();

    const uint32_t bsAddr = (uint32_t)__cvta_generic_to_shared(Bs);

    unsigned long long acc[8][4];

#pragma unroll 1
    for (int t = 0; t < DEG; t++) {
        // init acc from gathered P rows (issues 32 independent 8B loads)
#pragma unroll
        for (int i = 0; i < 8; i++) {
            int m = tm * 8 + i;
            bool ok = (m0 + m) < NN;
            const unsigned long long* p =
                (const unsigned long long*)(g_P + (size_t)Ss[m * DEG + t] * GDIM) + tn;
#pragma unroll
            for (int g = 0; g < 4; g++)
                acc[i][g] = ok ? p[g * 64] : 0ull;
        }

        // stage chunk 0 into buf 0 (linear 32KB copy, cp.async)
        {
            const float* gsrc = g_Wt;        // chunk 0 rows
#pragma unroll
            for (int r = 0; r < 8; r++) {
                int q = tid + 256 * r;       // float4 index 0..2047
                cp16(bsAddr + (uint32_t)q * 16, gsrc + q * 4);
            }
            cp_commit();
        }

#pragma unroll 1
        for (int c = 0; c < 8; c++) {
            if (c < 7) {
                const float* gsrc = g_Wt + (size_t)(c + 1) * 16 * GDIM;
                uint32_t sb = bsAddr + (uint32_t)(((c + 1) & 1) * BS_SIZE) * 4;
#pragma unroll
                for (int r = 0; r < 8; r++) {
                    int q = tid + 256 * r;
                    cp16(sb + (uint32_t)q * 16, gsrc + q * 4);
                }
                cp_commit();
                cp_wait1();
            } else {
                cp_wait0();
            }
            __syncthreads();

            const float* B = Bs + (c & 1) * BS_SIZE;
#pragma unroll
            for (int kk = 0; kk < 16; kk++) {
                int k = c * 16 + kk;
                const float4* hp = (const float4*)(Hs + k * HS_PAD + tm * 8);
                float4 a0 = hp[0], a1 = hp[1];
                unsigned long long ap[8];
                ap[0] = pack2(a0.x, a0.x); ap[1] = pack2(a0.y, a0.y);
                ap[2] = pack2(a0.z, a0.z); ap[3] = pack2(a0.w, a0.w);
                ap[4] = pack2(a1.x, a1.x); ap[5] = pack2(a1.y, a1.y);
                ap[6] = pack2(a1.z, a1.z); ap[7] = pack2(a1.w, a1.w);
                const unsigned long long* bp =
                    (const unsigned long long*)(B + kk * GDIM) + tn;
                unsigned long long b0 = bp[0], b1 = bp[64], b2 = bp[128], b3 = bp[192];
#pragma unroll
                for (int i = 0; i < 8; i++) {
                    acc[i][0] = fma2(ap[i], b0, acc[i][0]);
                    acc[i][1] = fma2(ap[i], b1, acc[i][1]);
                    acc[i][2] = fma2(ap[i], b2, acc[i][2]);
                    acc[i][3] = fma2(ap[i], b3, acc[i][3]);
                }
            }
            __syncthreads();   // everyone done reading buf (c&1) before restage
        }

        // pointwise LSTM update (gate order i,f,g,o)
        const bool last = (t == DEG - 1);
#pragma unroll
        for (int i = 0; i < 8; i++) {
            int m = tm * 8 + i;
            float2 vi = unpack2(acc[i][0]);
            float2 vf = unpack2(acc[i][1]);
            float2 vg = unpack2(acc[i][2]);
            float2 vo = unpack2(acc[i][3]);
            float2 cc = *(float2*)(Cs + m * FDIM + 2 * tn);
            float c0 = fsig(vf.x) * cc.x + fsig(vi.x) * ftanh(vg.x);
            float c1 = fsig(vf.y) * cc.y + fsig(vi.y) * ftanh(vg.y);
            *(float2*)(Cs + m * FDIM + 2 * tn) = make_float2(c0, c1);
            float h0 = fsig(vo.x) * ftanh(c0);
            float h1 = fsig(vo.y) * ftanh(c1);
            Hs[(2 * tn)     * HS_PAD + m] = h0;
            Hs[(2 * tn + 1) * HS_PAD + m] = h1;
            if (last && (m0 + m) < NN) {
                *(float2*)(g_H + (size_t)(m0 + m) * FDIM + 2 * tn) =
                    make_float2(h0, h1);
            }
        }
        __syncthreads();       // Hs/Cs updated before next step's staging/compute
    }
}

// ---------------------------------------------------------------------------
// output GEMM: Out[m, n] = aggr[m]@Wl[n] + X[m]@Wr[n] + bl[n]  (opt ReLU)
// ---------------------------------------------------------------------------
template<bool RELU>
__global__ __launch_bounds__(256)
void out_kernel(const float* __restrict__ X,
                const float* __restrict__ Wl, const float* __restrict__ Wr,
                const float* __restrict__ bl, float* __restrict__ Out, int Fo)
{
    __shared__ float As[16][72];
    __shared__ float Bs[16][136];

    const int tid = threadIdx.x;
    const int m0 = blockIdx.x * 64;
    const int tm = tid & 15;
    const int tn = tid >> 4;

    unsigned long long acc[4][4];
#pragma unroll
    for (int i = 0; i < 4; i++)
#pragma unroll
        for (int j = 0; j < 4; j++) acc[i][j] = 0ull;

    const int mA  = tid >> 1;
    const int kA0 = (tid & 1) * 8;
    const float* arowa = nullptr;
    const float* arowx = nullptr;
    if (tid < 128) {
        int node = m0 + mA;
        if (node < NN) {
            arowa = g_H + (size_t)node * FDIM;
            arowx = X + (size_t)node * FDIM;
        }
    }
    const int nB  = tid >> 1;
    const int kB0 = (tid & 1) * 8;
    const bool nb_ok = (nB < Fo);
    const float* browl = Wl + (size_t)nB * FDIM;
    const float* browr = Wr + (size_t)nB * FDIM;

    for (int k0 = 0; k0 < 256; k0 += 16) {
        float4 a0 = make_float4(0.f, 0.f, 0.f, 0.f), a1 = a0;
        if (tid < 128 && arowa) {
            const float* ar = (k0 < 128) ? (arowa + k0) : (arowx + k0 - 128);
            a0 = *(const float4*)(ar + kA0);
            a1 = *(const float4*)(ar + kA0 + 4);
        }
        float4 b0 = make_float4(0.f, 0.f, 0.f, 0.f), b1 = b0;
        if (nb_ok) {
            const float* br = (k0 < 128) ? (browl + k0) : (browr + k0 - 128);
            b0 = *(const float4*)(br + kB0);
            b1 = *(const float4*)(br + kB0 + 4);
        }

        __syncthreads();
        if (tid < 128) {
            As[kA0 + 0][mA] = a0.x; As[kA0 + 1][mA] = a0.y;
            As[kA0 + 2][mA] = a0.z; As[kA0 + 3][mA] = a0.w;
            As[kA0 + 4][mA] = a1.x; As[kA0 + 5][mA] = a1.y;
            As[kA0 + 6][mA] = a1.z; As[kA0 + 7][mA] = a1.w;
        }
        Bs[kB0 + 0][nB] = b0.x; Bs[kB0 + 1][nB] = b0.y;
        Bs[kB0 + 2][nB] = b0.z; Bs[kB0 + 3][nB] = b0.w;
        Bs[kB0 + 4][nB] = b1.x; Bs[kB0 + 5][nB] = b1.y;
        Bs[kB0 + 6][nB] = b1.z; Bs[kB0 + 7][nB] = b1.w;
        __syncthreads();

#pragma unroll
        for (int kk = 0; kk < 16; kk++) {
            float4 av = *(const float4*)(&As[kk][tm * 4]);
            unsigned long long ap[4];
            ap[0] = pack2(av.x, av.x); ap[1] = pack2(av.y, av.y);
            ap[2] = pack2(av.z, av.z); ap[3] = pack2(av.w, av.w);
            const unsigned long long* bp =
                (const unsigned long long*)(&Bs[kk][tn * 8]);
            unsigned long long bq0 = bp[0], bq1 = bp[1], bq2 = bp[2], bq3 = bp[3];
#pragma unroll
            for (int i = 0; i < 4; i++) {
                acc[i][0] = fma2(ap[i], bq0, acc[i][0]);
                acc[i][1] = fma2(ap[i], bq1, acc[i][1]);
                acc[i][2] = fma2(ap[i], bq2, acc[i][2]);
                acc[i][3] = fma2(ap[i], bq3, acc[i][3]);
            }
        }
    }

#pragma unroll
    for (int i = 0; i < 4; i++) {
        int m = m0 + tm * 4 + i;
        if (m >= NN) continue;
#pragma unroll
        for (int j = 0; j < 4; j++) {
            float2 v = unpack2(acc[i][j]);
            int n = tn * 8 + 2 * j;
            if (n < Fo) {
                float o0 = v.x + bl[n];
                if (RELU) o0 = fmaxf(o0, 0.f);
                Out[(size_t)m * Fo + n] = o0;
            }
            if (n + 1 < Fo) {
                float o1 = v.y + bl[n + 1];
                if (RELU) o1 = fmaxf(o1, 0.f);
                Out[(size_t)m * Fo + n + 1] = o1;
            }
        }
    }
}

// ---------------------------------------------------------------------------
// host launcher
// ---------------------------------------------------------------------------
extern "C" void kernel_launch(void* const* d_in, const int* in_sizes, int n_in,
                              void* d_out, int out_size)
{
    (void)in_sizes; (void)n_in; (void)out_size;
    const float* x   = (const float*)d_in[0];
    const int*   src = (const int*)d_in[1];

    const float* P[21];
    for (int i = 0; i < 21; i++) P[i] = (const float*)d_in[2 + i];

    float *a1 = nullptr, *a2 = nullptr;
    cudaGetSymbolAddress((void**)&a1, g_A1);
    cudaGetSymbolAddress((void**)&a2, g_A2);

    static bool attr_set = false;
    if (!attr_set) {
        cudaFuncSetAttribute(fused_lstm_kernel,
                             cudaFuncAttributeMaxDynamicSharedMemorySize,
                             SMEM_FUSED_BYTES);
        attr_set = true;
    }

    const dim3 blk(256);
    const dim3 gPre((NN + 63) / 64, 4);
    const dim3 gOut((NN + 63) / 64, 1);
    const int  gFused = (NN + BM - 1) / BM;
    const int  gTr = (FDIM * GDIM + 255) / 256;

    const float* Xin = x;
    for (int l = 0; l < 3; l++) {
        const float* Wih = P[7 * l + 0];
        const float* Whh = P[7 * l + 1];
        const float* bih = P[7 * l + 2];
        const float* bhh = P[7 * l + 3];
        const float* Wl  = P[7 * l + 4];
        const float* bl  = P[7 * l + 5];
        const float* Wr  = P[7 * l + 6];

        transpose_whh<<<gTr, blk>>>(Whh);
        pre_kernel<<<gPre, blk>>>(Xin, Wih, bih, bhh);
        fused_lstm_kernel<<<gFused, blk, SMEM_FUSED_BYTES>>>(src);

        if (l == 0) {
            out_kernel<true><<<gOut, blk>>>(Xin, Wl, Wr, bl, a1, 128);
            Xin = a1;
        } else if (l == 1) {
            out_kernel<true><<<gOut, blk>>>(Xin, Wl, Wr, bl, a2, 128);
            Xin = a2;
        } else {
            out_kernel<false><<<gOut, blk>>>(Xin, Wl, Wr, bl, (float*)d_out, 64);
        }
    }
}

// round 8
// speedup vs baseline: 4.9596x; 1.7771x over previous
#include <cuda_runtime.h>
#include <cuda_fp16.h>
#include <cstdint>

// ---------------------------------------------------------------------------
// GraphSAGE with LSTM aggregation, 3 layers — round 7.
// Recurrence via legacy mma.sync.m16n8k16 (f16 in, f32 acc) — compiles for
// plain sm_103 (tcgen05 is arch-specific and rejected by this harness).
//
// Per layer:
//   1) conv_whh: Whh -> fp16, gate-permuted rows, padded [512][136] in g_Whf
//   2) pre_kernel: P = X @ Wih^T + (bih+bhh)            [50000, 512]
//   3) fused_lstm_mma: block = 64 nodes, 16 steps:
//        D = (h_hi + h_lo)(fp16 split) @ Whh^T(fp16)  via mma.sync, f32 acc
//        G = gather(P) + D; pointwise in fp32; h -> fp16 hi/lo (dbl-buffered)
//   4) out_kernel: lin_l(h_final) + lin_r(X) (+ReLU)
// ---------------------------------------------------------------------------

#define NN   50000
#define DEG  16
#define FDIM 128
#define GDIM 512
#define BMF  64

__device__ float  g_H [NN * FDIM];
__device__ float  g_P [NN * GDIM];
__device__ float  g_A1[NN * FDIM];
__device__ float  g_A2[NN * FDIM];
__device__ __half g_Whf[GDIM * 136];     // fp16 Whh, permuted+padded rows

// SMEM layout of fused kernel (bytes):
#define SM_B     0                        // 512*136*2 = 139264
#define SM_A     139264                   // 2 bufs x 34816 (hi 17408 + lo 17408)
#define SM_SS    (139264 + 69632)         // 208896: 64*16 ints = 4096
#define SM_TOTAL (208896 + 4096)          // 212992

// ---- packed f32x2 helpers (pre/out kernels) --------------------------------
__device__ __forceinline__ unsigned long long pack2(float x, float y) {
    unsigned long long r;
    unsigned int xi = __float_as_uint(x), yi = __float_as_uint(y);
    asm("mov.b64 %0, {%1, %2};" : "=l"(r) : "r"(xi), "r"(yi));
    return r;
}
__device__ __forceinline__ unsigned long long fma2(unsigned long long a,
                                                   unsigned long long b,
                                                   unsigned long long c) {
    unsigned long long d;
    asm("fma.rn.f32x2 %0, %1, %2, %3;" : "=l"(d) : "l"(a), "l"(b), "l"(c));
    return d;
}
__device__ __forceinline__ float2 unpack2(unsigned long long v) {
    unsigned int lo, hi;
    asm("mov.b64 {%0, %1}, %2;" : "=r"(lo), "=r"(hi) : "l"(v));
    return make_float2(__uint_as_float(lo), __uint_as_float(hi));
}

// ---- activations (exp-based; proven 3.4e-7 accurate in R5) -----------------
__device__ __forceinline__ float fsig(float x) {
    return __fdividef(1.f, 1.f + __expf(-x));
}
__device__ __forceinline__ float ftanh(float x) {
    float xx = fminf(fmaxf(x, -20.f), 20.f);
    float e = __expf(2.f * xx);
    return __fdividef(e - 1.f, e + 1.f);
}

// ---- cp.async --------------------------------------------------------------
__device__ __forceinline__ void cp16(uint32_t saddr, const void* gaddr) {
    asm volatile("cp.async.cg.shared.global [%0], [%1], 16;"
                 :: "r"(saddr), "l"(gaddr));
}
__device__ __forceinline__ void cp_commit() { asm volatile("cp.async.commit_group;"); }
__device__ __forceinline__ void cp_wait0()  { asm volatile("cp.async.wait_group 0;"); }

// ---- mma.sync m16n8k16 f16 -> f32 ------------------------------------------
__device__ __forceinline__ void mma16816(float* d, const uint32_t* a,
                                         uint32_t b0, uint32_t b1) {
    asm volatile(
        "mma.sync.aligned.m16n8k16.row.col.f32.f16.f16.f32 "
        "{%0,%1,%2,%3},{%4,%5,%6,%7},{%8,%9},{%0,%1,%2,%3};"
        : "+f"(d[0]), "+f"(d[1]), "+f"(d[2]), "+f"(d[3])
        : "r"(a[0]), "r"(a[1]), "r"(a[2]), "r"(a[3]), "r"(b0), "r"(b1));
}

__device__ __forceinline__ uint32_t packh2(__half a, __half b) {
    return ((uint32_t)__half_as_ushort(b) << 16) | (uint32_t)__half_as_ushort(a);
}

// ---------------------------------------------------------------------------
// Whh [512][128] fp32 -> g_Whf fp16, gate-permuted, row-padded to 136 halfs.
// Permuted row n = w*64 + g*16 + f  <-  Whh row g*128 + w*16 + f
// ---------------------------------------------------------------------------
__global__ void conv_whh(const float* __restrict__ Whh)
{
    int idx = blockIdx.x * blockDim.x + threadIdx.x;
    if (idx >= GDIM * FDIM) return;
    int n = idx >> 7, k = idx & 127;
    int w = n >> 6, g = (n >> 4) & 3, f = n & 15;
    int row = g * 128 + w * 16 + f;
    g_Whf[n * 136 + k] = __float2half_rn(Whh[(size_t)row * FDIM + k]);
}

// ---------------------------------------------------------------------------
// P = X @ Wih^T + (bih + bhh)   (R5-proven SIMT f32x2 GEMM)
// ---------------------------------------------------------------------------
__global__ __launch_bounds__(256)
void pre_kernel(const float* __restrict__ X, const float* __restrict__ Wih,
                const float* __restrict__ bih, const float* __restrict__ bhh)
{
    __shared__ float As[16][72];
    __shared__ float Bs[16][136];

    const int tid = threadIdx.x;
    const int m0 = blockIdx.x * 64;
    const int n0 = blockIdx.y * 128;
    const int tm = tid & 15;
    const int tn = tid >> 4;

    unsigned long long acc[4][4];
#pragma unroll
    for (int i = 0; i < 4; i++)
#pragma unroll
        for (int j = 0; j < 4; j++) acc[i][j] = 0ull;

    const int mA  = tid >> 1;
    const int kA0 = (tid & 1) * 8;
    const float* arow = nullptr;
    if (tid < 128) {
        int node = m0 + mA;
        if (node < NN) arow = X + (size_t)node * FDIM;
    }
    const int nB  = tid >> 1;
    const int kB0 = (tid & 1) * 8;
    const float* brow = Wih + (size_t)(n0 + nB) * FDIM;

    for (int k0 = 0; k0 < 128; k0 += 16) {
        float4 a0 = make_float4(0.f, 0.f, 0.f, 0.f), a1 = a0;
        if (tid < 128 && arow) {
            a0 = *(const float4*)(arow + k0 + kA0);
            a1 = *(const float4*)(arow + k0 + kA0 + 4);
        }
        float4 b0 = *(const float4*)(brow + k0 + kB0);
        float4 b1 = *(const float4*)(brow + k0 + kB0 + 4);

        __syncthreads();
        if (tid < 128) {
            As[kA0 + 0][mA] = a0.x; As[kA0 + 1][mA] = a0.y;
            As[kA0 + 2][mA] = a0.z; As[kA0 + 3][mA] = a0.w;
            As[kA0 + 4][mA] = a1.x; As[kA0 + 5][mA] = a1.y;
            As[kA0 + 6][mA] = a1.z; As[kA0 + 7][mA] = a1.w;
        }
        Bs[kB0 + 0][nB] = b0.x; Bs[kB0 + 1][nB] = b0.y;
        Bs[kB0 + 2][nB] = b0.z; Bs[kB0 + 3][nB] = b0.w;
        Bs[kB0 + 4][nB] = b1.x; Bs[kB0 + 5][nB] = b1.y;
        Bs[kB0 + 6][nB] = b1.z; Bs[kB0 + 7][nB] = b1.w;
        __syncthreads();

#pragma unroll
        for (int kk = 0; kk < 16; kk++) {
            float4 av = *(const float4*)(&As[kk][tm * 4]);
            unsigned long long ap[4];
            ap[0] = pack2(av.x, av.x); ap[1] = pack2(av.y, av.y);
            ap[2] = pack2(av.z, av.z); ap[3] = pack2(av.w, av.w);
            const unsigned long long* bp =
                (const unsigned long long*)(&Bs[kk][tn * 8]);
            unsigned long long bq0 = bp[0], bq1 = bp[1], bq2 = bp[2], bq3 = bp[3];
#pragma unroll
            for (int i = 0; i < 4; i++) {
                acc[i][0] = fma2(ap[i], bq0, acc[i][0]);
                acc[i][1] = fma2(ap[i], bq1, acc[i][1]);
                acc[i][2] = fma2(ap[i], bq2, acc[i][2]);
                acc[i][3] = fma2(ap[i], bq3, acc[i][3]);
            }
        }
    }

#pragma unroll
    for (int i = 0; i < 4; i++) {
        int m = m0 + tm * 4 + i;
        if (m >= NN) continue;
        float* gout = g_P + (size_t)m * GDIM + n0 + tn * 8;
#pragma unroll
        for (int j = 0; j < 4; j++) {
            float2 v = unpack2(acc[i][j]);
            int n = n0 + tn * 8 + 2 * j;
            gout[2 * j + 0] = v.x + bih[n + 0] + bhh[n + 0];
            gout[2 * j + 1] = v.y + bih[n + 1] + bhh[n + 1];
        }
    }
}

// ---------------------------------------------------------------------------
// Fused LSTM on mma.sync. 782 blocks x 256 threads, 1 CTA/SM.
// Warp w owns features [w*16, w*16+16) x 4 gates = 64 permuted N-cols,
// over all 64 nodes. A (h) fp16 hi/lo, double-buffered by step parity.
// ---------------------------------------------------------------------------
__global__ __launch_bounds__(256, 1)
void fused_lstm_mma(const int* __restrict__ src)
{
    extern __shared__ char sm[];
    const uint32_t* Bw = (const uint32_t*)(sm + SM_B);  // [n][k] halfs, 68 words/row
    int* Ss = (int*)(sm + SM_SS);

    const int tid  = threadIdx.x;
    const int wid  = tid >> 5;
    const int lane = tid & 31;
    const int grp  = lane >> 2;
    const int tig  = lane & 3;
    const int m0   = blockIdx.x * BMF;

    // stage fp16 Whh image (139264 B) via cp.async
    {
        const uint4* gsrc = (const uint4*)g_Whf;
        uint32_t bAddr = (uint32_t)__cvta_generic_to_shared(sm + SM_B);
#pragma unroll
        for (int r = 0; r < 34; r++) {
            int q = tid + 256 * r;
            cp16(bAddr + (uint32_t)q * 16, gsrc + q);
        }
        cp_commit();
    }
    for (int i = tid; i < BMF * DEG; i += 256) {
        int node = m0 + i / DEG;
        Ss[i] = (node < NN) ? src[node * DEG + i % DEG] : 0;
    }
    __syncthreads();

    float c[32];
#pragma unroll
    for (int i = 0; i < 32; i++) c[i] = 0.f;

#pragma unroll 1
    for (int t = 0; t < DEG; t++) {
        const uint32_t* Ar = (const uint32_t*)(sm + SM_A + (t & 1) * 34816);
        uint32_t*       Aw = (uint32_t*)(sm + SM_A + ((t + 1) & 1) * 34816);

#pragma unroll
        for (int mc = 0; mc < 2; mc++) {
#pragma unroll
            for (int mt = 0; mt < 2; mt++) {
                const int rbase = mc * 32 + mt * 16 + grp;

                // P prefetch: gates g, feature pair cols (issued before mma)
                float2 Pv[2][8];
#pragma unroll
                for (int d = 0; d < 2; d++) {
                    int rl = rbase + d * 8;
                    const float* pr = g_P + (size_t)Ss[rl * DEG + t] * GDIM
                                          + wid * 16 + 2 * tig;
#pragma unroll
                    for (int g = 0; g < 4; g++) {
                        Pv[d][g * 2 + 0] = *(const float2*)(pr + g * 128);
                        Pv[d][g * 2 + 1] = *(const float2*)(pr + g * 128 + 8);
                    }
                }

                float acc[8][4];
#pragma unroll
                for (int i = 0; i < 8; i++) {
                    acc[i][0] = 0.f; acc[i][1] = 0.f;
                    acc[i][2] = 0.f; acc[i][3] = 0.f;
                }

                if (t > 0) {
#pragma unroll
                    for (int kt = 0; kt < 8; kt++) {
                        const int aw = rbase * 68 + kt * 8 + tig;
                        uint32_t a_hi[4], a_lo[4];
                        a_hi[0] = Ar[aw];        a_hi[1] = Ar[aw + 544];
                        a_hi[2] = Ar[aw + 4];    a_hi[3] = Ar[aw + 548];
                        a_lo[0] = Ar[aw + 4352]; a_lo[1] = Ar[aw + 4896];
                        a_lo[2] = Ar[aw + 4356]; a_lo[3] = Ar[aw + 4900];

                        uint32_t breg[8][2];
#pragma unroll
                        for (int nt = 0; nt < 8; nt++) {
                            int bw = (wid * 64 + nt * 8 + grp) * 68 + kt * 8 + tig;
                            breg[nt][0] = Bw[bw];
                            breg[nt][1] = Bw[bw + 4];
                        }
#pragma unroll
                        for (int nt = 0; nt < 8; nt++)
                            mma16816(acc[nt], a_hi, breg[nt][0], breg[nt][1]);
#pragma unroll
                        for (int nt = 0; nt < 8; nt++)
                            mma16816(acc[nt], a_lo, breg[nt][0], breg[nt][1]);
                    }
                }

                // pointwise LSTM update (gate order i,f,g,o)
#pragma unroll
                for (int d = 0; d < 2; d++) {
                    const int rl = rbase + d * 8;
                    const int node = m0 + rl;
#pragma unroll
                    for (int fh = 0; fh < 2; fh++) {
                        float hv[2];
#pragma unroll
                        for (int j = 0; j < 2; j++) {
                            float pi = j ? Pv[d][0 + fh].y : Pv[d][0 + fh].x;
                            float pf = j ? Pv[d][2 + fh].y : Pv[d][2 + fh].x;
                            float pg = j ? Pv[d][4 + fh].y : Pv[d][4 + fh].x;
                            float po = j ? Pv[d][6 + fh].y : Pv[d][6 + fh].x;
                            float gi = acc[0 + fh][d * 2 + j] + pi;
                            float gf = acc[2 + fh][d * 2 + j] + pf;
                            float gg = acc[4 + fh][d * 2 + j] + pg;
                            float go = acc[6 + fh][d * 2 + j] + po;
                            const int ci = ((mc * 2 + mt) * 2 + d) * 4 + fh * 2 + j;
                            float cn = fsig(gf) * c[ci] + fsig(gi) * ftanh(gg);
                            c[ci] = cn;
                            hv[j] = fsig(go) * ftanh(cn);
                        }
                        __half h0 = __float2half_rn(hv[0]);
                        __half h1 = __float2half_rn(hv[1]);
                        float  l0 = hv[0] - __half2float(h0);
                        float  l1 = hv[1] - __half2float(h1);
                        const int awi = rl * 68 + wid * 8 + fh * 4 + tig;
                        Aw[awi]        = packh2(h0, h1);
                        Aw[awi + 4352] = packh2(__float2half_rn(l0),
                                                __float2half_rn(l1));
                        if (t == DEG - 1 && node < NN) {
                            *(float2*)(g_H + (size_t)node * FDIM
                                       + wid * 16 + fh * 8 + 2 * tig) =
                                make_float2(hv[0], hv[1]);
                        }
                    }
                }
            }
        }
        if (t == 0) cp_wait0();     // B image resident before first mma (t=1)
        __syncthreads();            // A buffer handoff
    }
}

// ---------------------------------------------------------------------------
// output GEMM: Out[m, n] = aggr[m]@Wl[n] + X[m]@Wr[n] + bl[n]  (opt ReLU)
// ---------------------------------------------------------------------------
template<bool RELU>
__global__ __launch_bounds__(256)
void out_kernel(const float* __restrict__ X,
                const float* __restrict__ Wl, const float* __restrict__ Wr,
                const float* __restrict__ bl, float* __restrict__ Out, int Fo)
{
    __shared__ float As[16][72];
    __shared__ float Bs[16][136];

    const int tid = threadIdx.x;
    const int m0 = blockIdx.x * 64;
    const int tm = tid & 15;
    const int tn = tid >> 4;

    unsigned long long acc[4][4];
#pragma unroll
    for (int i = 0; i < 4; i++)
#pragma unroll
        for (int j = 0; j < 4; j++) acc[i][j] = 0ull;

    const int mA  = tid >> 1;
    const int kA0 = (tid & 1) * 8;
    const float* arowa = nullptr;
    const float* arowx = nullptr;
    if (tid < 128) {
        int node = m0 + mA;
        if (node < NN) {
            arowa = g_H + (size_t)node * FDIM;
            arowx = X + (size_t)node * FDIM;
        }
    }
    const int nB  = tid >> 1;
    const int kB0 = (tid & 1) * 8;
    const bool nb_ok = (nB < Fo);
    const float* browl = Wl + (size_t)nB * FDIM;
    const float* browr = Wr + (size_t)nB * FDIM;

    for (int k0 = 0; k0 < 256; k0 += 16) {
        float4 a0 = make_float4(0.f, 0.f, 0.f, 0.f), a1 = a0;
        if (tid < 128 && arowa) {
            const float* ar = (k0 < 128) ? (arowa + k0) : (arowx + k0 - 128);
            a0 = *(const float4*)(ar + kA0);
            a1 = *(const float4*)(ar + kA0 + 4);
        }
        float4 b0 = make_float4(0.f, 0.f, 0.f, 0.f), b1 = b0;
        if (nb_ok) {
            const float* br = (k0 < 128) ? (browl + k0) : (browr + k0 - 128);
            b0 = *(const float4*)(br + kB0);
            b1 = *(const float4*)(br + kB0 + 4);
        }

        __syncthreads();
        if (tid < 128) {
            As[kA0 + 0][mA] = a0.x; As[kA0 + 1][mA] = a0.y;
            As[kA0 + 2][mA] = a0.z; As[kA0 + 3][mA] = a0.w;
            As[kA0 + 4][mA] = a1.x; As[kA0 + 5][mA] = a1.y;
            As[kA0 + 6][mA] = a1.z; As[kA0 + 7][mA] = a1.w;
        }
        Bs[kB0 + 0][nB] = b0.x; Bs[kB0 + 1][nB] = b0.y;
        Bs[kB0 + 2][nB] = b0.z; Bs[kB0 + 3][nB] = b0.w;
        Bs[kB0 + 4][nB] = b1.x; Bs[kB0 + 5][nB] = b1.y;
        Bs[kB0 + 6][nB] = b1.z; Bs[kB0 + 7][nB] = b1.w;
        __syncthreads();

#pragma unroll
        for (int kk = 0; kk < 16; kk++) {
            float4 av = *(const float4*)(&As[kk][tm * 4]);
            unsigned long long ap[4];
            ap[0] = pack2(av.x, av.x); ap[1] = pack2(av.y, av.y);
            ap[2] = pack2(av.z, av.z); ap[3] = pack2(av.w, av.w);
            const unsigned long long* bp =
                (const unsigned long long*)(&Bs[kk][tn * 8]);
            unsigned long long bq0 = bp[0], bq1 = bp[1], bq2 = bp[2], bq3 = bp[3];
#pragma unroll
            for (int i = 0; i < 4; i++) {
                acc[i][0] = fma2(ap[i], bq0, acc[i][0]);
                acc[i][1] = fma2(ap[i], bq1, acc[i][1]);
                acc[i][2] = fma2(ap[i], bq2, acc[i][2]);
                acc[i][3] = fma2(ap[i], bq3, acc[i][3]);
            }
        }
    }

#pragma unroll
    for (int i = 0; i < 4; i++) {
        int m = m0 + tm * 4 + i;
        if (m >= NN) continue;
#pragma unroll
        for (int j = 0; j < 4; j++) {
            float2 v = unpack2(acc[i][j]);
            int n = tn * 8 + 2 * j;
            if (n < Fo) {
                float o0 = v.x + bl[n];
                if (RELU) o0 = fmaxf(o0, 0.f);
                Out[(size_t)m * Fo + n] = o0;
            }
            if (n + 1 < Fo) {
                float o1 = v.y + bl[n + 1];
                if (RELU) o1 = fmaxf(o1, 0.f);
                Out[(size_t)m * Fo + n + 1] = o1;
            }
        }
    }
}

// ---------------------------------------------------------------------------
// host launcher
// ---------------------------------------------------------------------------
extern "C" void kernel_launch(void* const* d_in, const int* in_sizes, int n_in,
                              void* d_out, int out_size)
{
    (void)in_sizes; (void)n_in; (void)out_size;
    const float* x   = (const float*)d_in[0];
    const int*   src = (const int*)d_in[1];

    const float* P[21];
    for (int i = 0; i < 21; i++) P[i] = (const float*)d_in[2 + i];

    float *a1 = nullptr, *a2 = nullptr;
    cudaGetSymbolAddress((void**)&a1, g_A1);
    cudaGetSymbolAddress((void**)&a2, g_A2);

    static bool attr_set = false;
    if (!attr_set) {
        cudaFuncSetAttribute(fused_lstm_mma,
                             cudaFuncAttributeMaxDynamicSharedMemorySize,
                             SM_TOTAL);
        attr_set = true;
    }

    const dim3 blk(256);
    const dim3 gPre((NN + 63) / 64, 4);
    const dim3 gOut((NN + 63) / 64, 1);
    const int  gFused = (NN + BMF - 1) / BMF;
    const int  gConv  = (GDIM * FDIM + 255) / 256;

    const float* Xin = x;
    for (int l = 0; l < 3; l++) {
        const float* Wih = P[7 * l + 0];
        const float* Whh = P[7 * l + 1];
        const float* bih = P[7 * l + 2];
        const float* bhh = P[7 * l + 3];
        const float* Wl  = P[7 * l + 4];
        const float* bl  = P[7 * l + 5];
        const float* Wr  = P[7 * l + 6];

        conv_whh<<<gConv, blk>>>(Whh);
        pre_kernel<<<gPre, blk>>>(Xin, Wih, bih, bhh);
        fused_lstm_mma<<<gFused, blk, SM_TOTAL>>>(src);

        if (l == 0) {
            out_kernel<true><<<gOut, blk>>>(Xin, Wl, Wr, bl, a1, 128);
            Xin = a1;
        } else if (l == 1) {
            out_kernel<true><<<gOut, blk>>>(Xin, Wl, Wr, bl, a2, 128);
            Xin = a2;
        } else {
            out_kernel<false><<<gOut, blk>>>(Xin, Wl, Wr, bl, (float*)d_out, 64);
        }
    }
}

// round 9
// speedup vs baseline: 5.5704x; 1.1231x over previous
#include <cuda_runtime.h>
#include <cuda_fp16.h>
#include <cstdint>

// ---------------------------------------------------------------------------
// GraphSAGE with LSTM aggregation, 3 layers — round 8.
// Recurrence on mma.sync.m16n8k16 (f16 in, f32 acc), fragments via ldmatrix.
//   conv_whh:  Whh -> fp16, K-major gate-permuted image [128][520] (g_Whk)
//   pre:       P = X @ Wih^T + (bih+bhh)
//   fused:     block = 64 nodes, 16 steps, D=(h_hi+h_lo)@Whh^T, pointwise
//   out:       lin_l(h) + lin_r(x) (+ReLU)
// ---------------------------------------------------------------------------

#define NN   50000
#define DEG  16
#define FDIM 128
#define GDIM 512
#define BMF  64

__device__ float g_H [NN * FDIM];
__device__ float g_P [NN * GDIM];
__device__ float g_A1[NN * FDIM];
__device__ float g_A2[NN * FDIM];
__device__ uint4 g_Whk[8320];            // 133120 B: fp16 Whh, [k][n_perm] pad 520

// SMEM (bytes): B 133120 | A 2 bufs x (hi 17408 + lo 17408) | src ids 4096
#define SM_B     0
#define SM_A     133120
#define SM_SS    202752
#define SM_TOTAL 206848

// ---- packed f32x2 helpers (pre/out kernels) --------------------------------
__device__ __forceinline__ unsigned long long pack2(float x, float y) {
    unsigned long long r;
    unsigned int xi = __float_as_uint(x), yi = __float_as_uint(y);
    asm("mov.b64 %0, {%1, %2};" : "=l"(r) : "r"(xi), "r"(yi));
    return r;
}
__device__ __forceinline__ unsigned long long fma2(unsigned long long a,
                                                   unsigned long long b,
                                                   unsigned long long c) {
    unsigned long long d;
    asm("fma.rn.f32x2 %0, %1, %2, %3;" : "=l"(d) : "l"(a), "l"(b), "l"(c));
    return d;
}
__device__ __forceinline__ float2 unpack2(unsigned long long v) {
    unsigned int lo, hi;
    asm("mov.b64 {%0, %1}, %2;" : "=r"(lo), "=r"(hi) : "l"(v));
    return make_float2(__uint_as_float(lo), __uint_as_float(hi));
}

// ---- fast activations (HW tanh) --------------------------------------------
__device__ __forceinline__ float htanh(float x) {
    float y;
    asm("tanh.approx.f32 %0, %1;" : "=f"(y) : "f"(x));
    return y;
}
__device__ __forceinline__ float fsig(float x) {
    return fmaf(0.5f, htanh(0.5f * x), 0.5f);
}

// ---- cp.async --------------------------------------------------------------
__device__ __forceinline__ void cp16(uint32_t saddr, const void* gaddr) {
    asm volatile("cp.async.cg.shared.global [%0], [%1], 16;"
                 :: "r"(saddr), "l"(gaddr));
}
__device__ __forceinline__ void cp_commit() { asm volatile("cp.async.commit_group;"); }
__device__ __forceinline__ void cp_wait0()  { asm volatile("cp.async.wait_group 0;"); }

// ---- mma / ldmatrix --------------------------------------------------------
__device__ __forceinline__ void mma16816(float* d, const uint32_t* a,
                                         uint32_t b0, uint32_t b1) {
    asm volatile(
        "mma.sync.aligned.m16n8k16.row.col.f32.f16.f16.f32 "
        "{%0,%1,%2,%3},{%4,%5,%6,%7},{%8,%9},{%0,%1,%2,%3};"
        : "+f"(d[0]), "+f"(d[1]), "+f"(d[2]), "+f"(d[3])
        : "r"(a[0]), "r"(a[1]), "r"(a[2]), "r"(a[3]), "r"(b0), "r"(b1));
}
__device__ __forceinline__ void ldsm4(uint32_t* r, uint32_t a) {
    asm volatile("ldmatrix.sync.aligned.m8n8.x4.shared.b16 {%0,%1,%2,%3}, [%4];"
                 : "=r"(r[0]), "=r"(r[1]), "=r"(r[2]), "=r"(r[3]) : "r"(a));
}
__device__ __forceinline__ void ldsm4t(uint32_t* r, uint32_t a) {
    asm volatile("ldmatrix.sync.aligned.m8n8.x4.trans.shared.b16 {%0,%1,%2,%3}, [%4];"
                 : "=r"(r[0]), "=r"(r[1]), "=r"(r[2]), "=r"(r[3]) : "r"(a));
}
__device__ __forceinline__ uint32_t packh2(__half a, __half b) {
    return ((uint32_t)__half_as_ushort(b) << 16) | (uint32_t)__half_as_ushort(a);
}

// ---------------------------------------------------------------------------
// Whh [512][128] fp32 -> g_Whk fp16 [k][n_perm], row-padded to 520 halfs.
// Permuted col n = w*64 + g*16 + f  <-  Whh row r = g*128 + w*16 + f
// ---------------------------------------------------------------------------
__global__ void conv_whh(const float* __restrict__ Whh)
{
    int idx = blockIdx.x * blockDim.x + threadIdx.x;
    if (idx >= GDIM * FDIM) return;
    int r = idx >> 7, k = idx & 127;
    int g = r >> 7, w = (r >> 4) & 7, f = r & 15;
    int n = w * 64 + g * 16 + f;
    ((__half*)g_Whk)[k * 520 + n] = __float2half_rn(Whh[idx]);
}

// ---------------------------------------------------------------------------
// P = X @ Wih^T + (bih + bhh)   (R5-proven SIMT f32x2 GEMM)
// ---------------------------------------------------------------------------
__global__ __launch_bounds__(256)
void pre_kernel(const float* __restrict__ X, const float* __restrict__ Wih,
                const float* __restrict__ bih, const float* __restrict__ bhh)
{
    __shared__ float As[16][72];
    __shared__ float Bs[16][136];

    const int tid = threadIdx.x;
    const int m0 = blockIdx.x * 64;
    const int n0 = blockIdx.y * 128;
    const int tm = tid & 15;
    const int tn = tid >> 4;

    unsigned long long acc[4][4];
#pragma unroll
    for (int i = 0; i < 4; i++)
#pragma unroll
        for (int j = 0; j < 4; j++) acc[i][j] = 0ull;

    const int mA  = tid >> 1;
    const int kA0 = (tid & 1) * 8;
    const float* arow = nullptr;
    if (tid < 128) {
        int node = m0 + mA;
        if (node < NN) arow = X + (size_t)node * FDIM;
    }
    const int nB  = tid >> 1;
    const int kB0 = (tid & 1) * 8;
    const float* brow = Wih + (size_t)(n0 + nB) * FDIM;

    for (int k0 = 0; k0 < 128; k0 += 16) {
        float4 a0 = make_float4(0.f, 0.f, 0.f, 0.f), a1 = a0;
        if (tid < 128 && arow) {
            a0 = *(const float4*)(arow + k0 + kA0);
            a1 = *(const float4*)(arow + k0 + kA0 + 4);
        }
        float4 b0 = *(const float4*)(brow + k0 + kB0);
        float4 b1 = *(const float4*)(brow + k0 + kB0 + 4);

        __syncthreads();
        if (tid < 128) {
            As[kA0 + 0][mA] = a0.x; As[kA0 + 1][mA] = a0.y;
            As[kA0 + 2][mA] = a0.z; As[kA0 + 3][mA] = a0.w;
            As[kA0 + 4][mA] = a1.x; As[kA0 + 5][mA] = a1.y;
            As[kA0 + 6][mA] = a1.z; As[kA0 + 7][mA] = a1.w;
        }
        Bs[kB0 + 0][nB] = b0.x; Bs[kB0 + 1][nB] = b0.y;
        Bs[kB0 + 2][nB] = b0.z; Bs[kB0 + 3][nB] = b0.w;
        Bs[kB0 + 4][nB] = b1.x; Bs[kB0 + 5][nB] = b1.y;
        Bs[kB0 + 6][nB] = b1.z; Bs[kB0 + 7][nB] = b1.w;
        __syncthreads();

#pragma unroll
        for (int kk = 0; kk < 16; kk++) {
            float4 av = *(const float4*)(&As[kk][tm * 4]);
            unsigned long long ap[4];
            ap[0] = pack2(av.x, av.x); ap[1] = pack2(av.y, av.y);
            ap[2] = pack2(av.z, av.z); ap[3] = pack2(av.w, av.w);
            const unsigned long long* bp =
                (const unsigned long long*)(&Bs[kk][tn * 8]);
            unsigned long long bq0 = bp[0], bq1 = bp[1], bq2 = bp[2], bq3 = bp[3];
#pragma unroll
            for (int i = 0; i < 4; i++) {
                acc[i][0] = fma2(ap[i], bq0, acc[i][0]);
                acc[i][1] = fma2(ap[i], bq1, acc[i][1]);
                acc[i][2] = fma2(ap[i], bq2, acc[i][2]);
                acc[i][3] = fma2(ap[i], bq3, acc[i][3]);
            }
        }
    }

#pragma unroll
    for (int i = 0; i < 4; i++) {
        int m = m0 + tm * 4 + i;
        if (m >= NN) continue;
        float* gout = g_P + (size_t)m * GDIM + n0 + tn * 8;
#pragma unroll
        for (int j = 0; j < 4; j++) {
            float2 v = unpack2(acc[i][j]);
            int n = n0 + tn * 8 + 2 * j;
            gout[2 * j + 0] = v.x + bih[n + 0] + bhh[n + 0];
            gout[2 * j + 1] = v.y + bih[n + 1] + bhh[n + 1];
        }
    }
}

// ---------------------------------------------------------------------------
// Fused LSTM on mma.sync + ldmatrix. 782 blocks x 256 threads, 1 CTA/SM.
// Warp w owns all 64 M rows x 64 permuted N cols (= 16 features x 4 gates).
// A (h fp16 hi/lo) double-buffered by step parity; B SMEM-resident.
// ---------------------------------------------------------------------------
__global__ __launch_bounds__(256, 1)
void fused_lstm_mma(const int* __restrict__ src)
{
    extern __shared__ char sm[];
    const uint32_t smb = (uint32_t)__cvta_generic_to_shared(sm);
    const uint32_t Bk  = smb + SM_B;
    int* Ss = (int*)(sm + SM_SS);

    const int tid  = threadIdx.x;
    const int wid  = tid >> 5;
    const int lane = tid & 31;
    const int grp  = lane >> 2;
    const int tig  = lane & 3;
    const int m0   = blockIdx.x * BMF;

    // stage B image (133120 B = 8320 uint4)
#pragma unroll
    for (int r = 0; r < 33; r++) {
        int q = tid + 256 * r;
        if (q < 8320) cp16(Bk + (uint32_t)q * 16, g_Whk + q);
    }
    cp_commit();

    for (int i = tid; i < BMF * DEG; i += 256) {
        int node = m0 + i / DEG;
        Ss[i] = (node < NN) ? src[node * DEG + i % DEG] : 0;
    }
    __syncthreads();

    float c[32];
#pragma unroll
    for (int i = 0; i < 32; i++) c[i] = 0.f;

    // per-thread ldmatrix address components
    const int aRow = ((lane >> 3) & 1) * 8 + (lane & 7);
    const int aCol = (lane >> 4) * 16;                     // bytes (k+8 half)
    const int bRow = ((lane >> 3) & 1) * 8 + (lane & 7);   // k within 16
    const int bCol = ((lane >> 4) & 1) * 16;               // bytes (nt odd)

#pragma unroll 1
    for (int t = 0; t < DEG; t++) {
        const uint32_t Ard = smb + SM_A + (uint32_t)((t & 1) * 34816);
        const uint32_t Awr = smb + SM_A + (uint32_t)(((t + 1) & 1) * 34816);

#pragma unroll
        for (int mh = 0; mh < 2; mh++) {
            float acc[2][8][4];
#pragma unroll
            for (int i = 0; i < 2; i++)
#pragma unroll
                for (int j = 0; j < 8; j++)
#pragma unroll
                    for (int q = 0; q < 4; q++) acc[i][j][q] = 0.f;

            if (t > 0) {
#pragma unroll
                for (int kt = 0; kt < 8; kt++) {
                    uint32_t bfr[4][4];
#pragma unroll
                    for (int q = 0; q < 4; q++) {
                        uint32_t ba = Bk + (uint32_t)((kt * 16 + bRow) * 1040 +
                                       (wid * 64 + q * 16) * 2 + bCol);
                        ldsm4t(bfr[q], ba);
                    }
#pragma unroll
                    for (int mti = 0; mti < 2; mti++) {
                        const int mt = mh * 2 + mti;
                        uint32_t aa = Ard + (uint32_t)((mt * 16 + aRow) * 272 +
                                        kt * 32 + aCol);
                        uint32_t afh[4], afl[4];
                        ldsm4(afh, aa);
                        ldsm4(afl, aa + 17408);
#pragma unroll
                        for (int nt = 0; nt < 8; nt++) {
                            uint32_t b0 = bfr[nt >> 1][(nt & 1) * 2];
                            uint32_t b1 = bfr[nt >> 1][(nt & 1) * 2 + 1];
                            mma16816(acc[mti][nt], afh, b0, b1);
                            mma16816(acc[mti][nt], afl, b0, b1);
                        }
                    }
                }
            }

            // pointwise LSTM update for this m-half (gate order i,f,g,o)
#pragma unroll
            for (int mti = 0; mti < 2; mti++) {
                const int mt = mh * 2 + mti;
#pragma unroll
                for (int rsel = 0; rsel < 2; rsel++) {
                    const int ml   = mt * 16 + grp + rsel * 8;
                    const int node = m0 + ml;
                    const float* pr = g_P + (size_t)Ss[ml * DEG + t] * GDIM
                                          + wid * 16 + 2 * tig;
                    float2 Pv[4][2];
#pragma unroll
                    for (int g = 0; g < 4; g++) {
                        Pv[g][0] = *(const float2*)(pr + g * 128);
                        Pv[g][1] = *(const float2*)(pr + g * 128 + 8);
                    }
#pragma unroll
                    for (int fp = 0; fp < 2; fp++) {
                        float hv[2];
#pragma unroll
                        for (int p = 0; p < 2; p++) {
                            float gi = (p ? Pv[0][fp].y : Pv[0][fp].x);
                            float gf = (p ? Pv[1][fp].y : Pv[1][fp].x);
                            float gg = (p ? Pv[2][fp].y : Pv[2][fp].x);
                            float go = (p ? Pv[3][fp].y : Pv[3][fp].x);
                            if (t > 0) {
                                gi += acc[mti][0 + fp][rsel * 2 + p];
                                gf += acc[mti][2 + fp][rsel * 2 + p];
                                gg += acc[mti][4 + fp][rsel * 2 + p];
                                go += acc[mti][6 + fp][rsel * 2 + p];
                            }
                            const int ci = (mt * 2 + rsel) * 4 + fp * 2 + p;
                            float cn = fsig(gf) * c[ci] + fsig(gi) * htanh(gg);
                            c[ci] = cn;
                            hv[p] = fsig(go) * htanh(cn);
                        }
                        __half h0 = __float2half_rn(hv[0]);
                        __half h1 = __float2half_rn(hv[1]);
                        float  l0 = hv[0] - __half2float(h0);
                        float  l1 = hv[1] - __half2float(h1);
                        const uint32_t aw = Awr + (uint32_t)(ml * 272 +
                                            (wid * 16 + fp * 8 + 2 * tig) * 2);
                        uint32_t hipk = packh2(h0, h1);
                        uint32_t lopk = packh2(__float2half_rn(l0),
                                               __float2half_rn(l1));
                        asm volatile("st.shared.b32 [%0], %1;" :: "r"(aw), "r"(hipk));
                        asm volatile("st.shared.b32 [%0], %1;"
                                     :: "r"(aw + 17408), "r"(lopk));
                        if (t == DEG - 1 && node < NN) {
                            *(float2*)(g_H + (size_t)node * FDIM +
                                       wid * 16 + fp * 8 + 2 * tig) =
                                make_float2(hv[0], hv[1]);
                        }
                    }
                }
            }
        }
        if (t == 0) cp_wait0();     // B resident before first mma (t=1)
        __syncthreads();            // A buffer handoff
    }
}

// ---------------------------------------------------------------------------
// output GEMM: Out[m, n] = aggr[m]@Wl[n] + X[m]@Wr[n] + bl[n]  (opt ReLU)
// ---------------------------------------------------------------------------
template<bool RELU>
__global__ __launch_bounds__(256)
void out_kernel(const float* __restrict__ X,
                const float* __restrict__ Wl, const float* __restrict__ Wr,
                const float* __restrict__ bl, float* __restrict__ Out, int Fo)
{
    __shared__ float As[16][72];
    __shared__ float Bs[16][136];

    const int tid = threadIdx.x;
    const int m0 = blockIdx.x * 64;
    const int tm = tid & 15;
    const int tn = tid >> 4;

    unsigned long long acc[4][4];
#pragma unroll
    for (int i = 0; i < 4; i++)
#pragma unroll
        for (int j = 0; j < 4; j++) acc[i][j] = 0ull;

    const int mA  = tid >> 1;
    const int kA0 = (tid & 1) * 8;
    const float* arowa = nullptr;
    const float* arowx = nullptr;
    if (tid < 128) {
        int node = m0 + mA;
        if (node < NN) {
            arowa = g_H + (size_t)node * FDIM;
            arowx = X + (size_t)node * FDIM;
        }
    }
    const int nB  = tid >> 1;
    const int kB0 = (tid & 1) * 8;
    const bool nb_ok = (nB < Fo);
    const float* browl = Wl + (size_t)nB * FDIM;
    const float* browr = Wr + (size_t)nB * FDIM;

    for (int k0 = 0; k0 < 256; k0 += 16) {
        float4 a0 = make_float4(0.f, 0.f, 0.f, 0.f), a1 = a0;
        if (tid < 128 && arowa) {
            const float* ar = (k0 < 128) ? (arowa + k0) : (arowx + k0 - 128);
            a0 = *(const float4*)(ar + kA0);
            a1 = *(const float4*)(ar + kA0 + 4);
        }
        float4 b0 = make_float4(0.f, 0.f, 0.f, 0.f), b1 = b0;
        if (nb_ok) {
            const float* br = (k0 < 128) ? (browl + k0) : (browr + k0 - 128);
            b0 = *(const float4*)(br + kB0);
            b1 = *(const float4*)(br + kB0 + 4);
        }

        __syncthreads();
        if (tid < 128) {
            As[kA0 + 0][mA] = a0.x; As[kA0 + 1][mA] = a0.y;
            As[kA0 + 2][mA] = a0.z; As[kA0 + 3][mA] = a0.w;
            As[kA0 + 4][mA] = a1.x; As[kA0 + 5][mA] = a1.y;
            As[kA0 + 6][mA] = a1.z; As[kA0 + 7][mA] = a1.w;
        }
        Bs[kB0 + 0][nB] = b0.x; Bs[kB0 + 1][nB] = b0.y;
        Bs[kB0 + 2][nB] = b0.z; Bs[kB0 + 3][nB] = b0.w;
        Bs[kB0 + 4][nB] = b1.x; Bs[kB0 + 5][nB] = b1.y;
        Bs[kB0 + 6][nB] = b1.z; Bs[kB0 + 7][nB] = b1.w;
        __syncthreads();

#pragma unroll
        for (int kk = 0; kk < 16; kk++) {
            float4 av = *(const float4*)(&As[kk][tm * 4]);
            unsigned long long ap[4];
            ap[0] = pack2(av.x, av.x); ap[1] = pack2(av.y, av.y);
            ap[2] = pack2(av.z, av.z); ap[3] = pack2(av.w, av.w);
            const unsigned long long* bp =
                (const unsigned long long*)(&Bs[kk][tn * 8]);
            unsigned long long bq0 = bp[0], bq1 = bp[1], bq2 = bp[2], bq3 = bp[3];
#pragma unroll
            for (int i = 0; i < 4; i++) {
                acc[i][0] = fma2(ap[i], bq0, acc[i][0]);
                acc[i][1] = fma2(ap[i], bq1, acc[i][1]);
                acc[i][2] = fma2(ap[i], bq2, acc[i][2]);
                acc[i][3] = fma2(ap[i], bq3, acc[i][3]);
            }
        }
    }

#pragma unroll
    for (int i = 0; i < 4; i++) {
        int m = m0 + tm * 4 + i;
        if (m >= NN) continue;
#pragma unroll
        for (int j = 0; j < 4; j++) {
            float2 v = unpack2(acc[i][j]);
            int n = tn * 8 + 2 * j;
            if (n < Fo) {
                float o0 = v.x + bl[n];
                if (RELU) o0 = fmaxf(o0, 0.f);
                Out[(size_t)m * Fo + n] = o0;
            }
            if (n + 1 < Fo) {
                float o1 = v.y + bl[n + 1];
                if (RELU) o1 = fmaxf(o1, 0.f);
                Out[(size_t)m * Fo + n + 1] = o1;
            }
        }
    }
}

// ---------------------------------------------------------------------------
// host launcher
// ---------------------------------------------------------------------------
extern "C" void kernel_launch(void* const* d_in, const int* in_sizes, int n_in,
                              void* d_out, int out_size)
{
    (void)in_sizes; (void)n_in; (void)out_size;
    const float* x   = (const float*)d_in[0];
    const int*   src = (const int*)d_in[1];

    const float* P[21];
    for (int i = 0; i < 21; i++) P[i] = (const float*)d_in[2 + i];

    float *a1 = nullptr, *a2 = nullptr;
    cudaGetSymbolAddress((void**)&a1, g_A1);
    cudaGetSymbolAddress((void**)&a2, g_A2);

    static bool attr_set = false;
    if (!attr_set) {
        cudaFuncSetAttribute(fused_lstm_mma,
                             cudaFuncAttributeMaxDynamicSharedMemorySize,
                             SM_TOTAL);
        attr_set = true;
    }

    const dim3 blk(256);
    const dim3 gPre((NN + 63) / 64, 4);
    const dim3 gOut((NN + 63) / 64, 1);
    const int  gFused = (NN + BMF - 1) / BMF;
    const int  gConv  = (GDIM * FDIM + 255) / 256;

    const float* Xin = x;
    for (int l = 0; l < 3; l++) {
        const float* Wih = P[7 * l + 0];
        const float* Whh = P[7 * l + 1];
        const float* bih = P[7 * l + 2];
        const float* bhh = P[7 * l + 3];
        const float* Wl  = P[7 * l + 4];
        const float* bl  = P[7 * l + 5];
        const float* Wr  = P[7 * l + 6];

        conv_whh<<<gConv, blk>>>(Whh);
        pre_kernel<<<gPre, blk>>>(Xin, Wih, bih, bhh);
        fused_lstm_mma<<<gFused, blk, SM_TOTAL>>>(src);

        if (l == 0) {
            out_kernel<true><<<gOut, blk>>>(Xin, Wl, Wr, bl, a1, 128);
            Xin = a1;
        } else if (l == 1) {
            out_kernel<true><<<gOut, blk>>>(Xin, Wl, Wr, bl, a2, 128);
            Xin = a2;
        } else {
            out_kernel<false><<<gOut, blk>>>(Xin, Wl, Wr, bl, (float*)d_out, 64);
        }
    }
}

// round 11
// speedup vs baseline: 6.4498x; 1.1579x over previous
#include <cuda_runtime.h>
#include <cuda_fp16.h>
#include <cstdint>

// ---------------------------------------------------------------------------
// GraphSAGE with LSTM aggregation, 3 layers — round 9.
// Recurrence on mma.sync.m16n8k16 (f16 in, f32 acc), fragments via ldmatrix.
// Single fp16 pass for h (lo-residual split removed: measured error budget
// shows fp16 h-quantization lands ~1e-4 end-to-end, well under 1e-3).
// ---------------------------------------------------------------------------

#define NN   50000
#define DEG  16
#define FDIM 128
#define GDIM 512
#define BMF  64

__device__ float g_H [NN * FDIM];
__device__ float g_P [NN * GDIM];
__device__ float g_A1[NN * FDIM];
__device__ float g_A2[NN * FDIM];
__device__ uint4 g_Whk[8320];            // 133120 B: fp16 Whh, [k][n_perm] pad 520

// SMEM (bytes): B 133120 | A 2 bufs x 17408 | src ids 4096
#define SM_B     0
#define SM_A     133120
#define SM_SS    167936
#define SM_TOTAL 172032

// ---- packed f32x2 helpers (pre/out kernels) --------------------------------
__device__ __forceinline__ unsigned long long pack2(float x, float y) {
    unsigned long long r;
    unsigned int xi = __float_as_uint(x), yi = __float_as_uint(y);
    asm("mov.b64 %0, {%1, %2};" : "=l"(r) : "r"(xi), "r"(yi));
    return r;
}
__device__ __forceinline__ unsigned long long fma2(unsigned long long a,
                                                   unsigned long long b,
                                                   unsigned long long c) {
    unsigned long long d;
    asm("fma.rn.f32x2 %0, %1, %2, %3;" : "=l"(d) : "l"(a), "l"(b), "l"(c));
    return d;
}
__device__ __forceinline__ float2 unpack2(unsigned long long v) {
    unsigned int lo, hi;
    asm("mov.b64 {%0, %1}, %2;" : "=r"(lo), "=r"(hi) : "l"(v));
    return make_float2(__uint_as_float(lo), __uint_as_float(hi));
}

// ---- fast activations (HW tanh; accuracy proven R8) ------------------------
__device__ __forceinline__ float htanh(float x) {
    float y;
    asm("tanh.approx.f32 %0, %1;" : "=f"(y) : "f"(x));
    return y;
}
__device__ __forceinline__ float fsig(float x) {
    return fmaf(0.5f, htanh(0.5f * x), 0.5f);
}

// ---- cp.async --------------------------------------------------------------
__device__ __forceinline__ void cp16(uint32_t saddr, const void* gaddr) {
    asm volatile("cp.async.cg.shared.global [%0], [%1], 16;"
                 :: "r"(saddr), "l"(gaddr));
}
__device__ __forceinline__ void cp_commit() { asm volatile("cp.async.commit_group;"); }
__device__ __forceinline__ void cp_wait0()  { asm volatile("cp.async.wait_group 0;"); }

// ---- mma / ldmatrix --------------------------------------------------------
__device__ __forceinline__ void mma16816(float* d, const uint32_t* a,
                                         uint32_t b0, uint32_t b1) {
    asm volatile(
        "mma.sync.aligned.m16n8k16.row.col.f32.f16.f16.f32 "
        "{%0,%1,%2,%3},{%4,%5,%6,%7},{%8,%9},{%0,%1,%2,%3};"
        : "+f"(d[0]), "+f"(d[1]), "+f"(d[2]), "+f"(d[3])
        : "r"(a[0]), "r"(a[1]), "r"(a[2]), "r"(a[3]), "r"(b0), "r"(b1));
}
__device__ __forceinline__ void ldsm4(uint32_t* r, uint32_t a) {
    asm volatile("ldmatrix.sync.aligned.m8n8.x4.shared.b16 {%0,%1,%2,%3}, [%4];"
                 : "=r"(r[0]), "=r"(r[1]), "=r"(r[2]), "=r"(r[3]) : "r"(a));
}
__device__ __forceinline__ void ldsm4t(uint32_t* r, uint32_t a) {
    asm volatile("ldmatrix.sync.aligned.m8n8.x4.trans.shared.b16 {%0,%1,%2,%3}, [%4];"
                 : "=r"(r[0]), "=r"(r[1]), "=r"(r[2]), "=r"(r[3]) : "r"(a));
}
__device__ __forceinline__ uint32_t packh2(__half a, __half b) {
    return ((uint32_t)__half_as_ushort(b) << 16) | (uint32_t)__half_as_ushort(a);
}

// ---------------------------------------------------------------------------
// Whh [512][128] fp32 -> g_Whk fp16 [k][n_perm], row-padded to 520 halfs.
// Permuted col n = w*64 + g*16 + f  <-  Whh row r = g*128 + w*16 + f
// ---------------------------------------------------------------------------
__global__ void conv_whh(const float* __restrict__ Whh)
{
    int idx = blockIdx.x * blockDim.x + threadIdx.x;
    if (idx >= GDIM * FDIM) return;
    int r = idx >> 7, k = idx & 127;
    int g = r >> 7, w = (r >> 4) & 7, f = r & 15;
    int n = w * 64 + g * 16 + f;
    ((__half*)g_Whk)[k * 520 + n] = __float2half_rn(Whh[idx]);
}

// ---------------------------------------------------------------------------
// P = X @ Wih^T + (bih + bhh)   (R5-proven SIMT f32x2 GEMM)
// ---------------------------------------------------------------------------
__global__ __launch_bounds__(256)
void pre_kernel(const float* __restrict__ X, const float* __restrict__ Wih,
                const float* __restrict__ bih, const float* __restrict__ bhh)
{
    __shared__ float As[16][72];
    __shared__ float Bs[16][136];

    const int tid = threadIdx.x;
    const int m0 = blockIdx.x * 64;
    const int n0 = blockIdx.y * 128;
    const int tm = tid & 15;
    const int tn = tid >> 4;

    unsigned long long acc[4][4];
#pragma unroll
    for (int i = 0; i < 4; i++)
#pragma unroll
        for (int j = 0; j < 4; j++) acc[i][j] = 0ull;

    const int mA  = tid >> 1;
    const int kA0 = (tid & 1) * 8;
    const float* arow = nullptr;
    if (tid < 128) {
        int node = m0 + mA;
        if (node < NN) arow = X + (size_t)node * FDIM;
    }
    const int nB  = tid >> 1;
    const int kB0 = (tid & 1) * 8;
    const float* brow = Wih + (size_t)(n0 + nB) * FDIM;

    for (int k0 = 0; k0 < 128; k0 += 16) {
        float4 a0 = make_float4(0.f, 0.f, 0.f, 0.f), a1 = a0;
        if (tid < 128 && arow) {
            a0 = *(const float4*)(arow + k0 + kA0);
            a1 = *(const float4*)(arow + k0 + kA0 + 4);
        }
        float4 b0 = *(const float4*)(brow + k0 + kB0);
        float4 b1 = *(const float4*)(brow + k0 + kB0 + 4);

        __syncthreads();
        if (tid < 128) {
            As[kA0 + 0][mA] = a0.x; As[kA0 + 1][mA] = a0.y;
            As[kA0 + 2][mA] = a0.z; As[kA0 + 3][mA] = a0.w;
            As[kA0 + 4][mA] = a1.x; As[kA0 + 5][mA] = a1.y;
            As[kA0 + 6][mA] = a1.z; As[kA0 + 7][mA] = a1.w;
        }
        Bs[kB0 + 0][nB] = b0.x; Bs[kB0 + 1][nB] = b0.y;
        Bs[kB0 + 2][nB] = b0.z; Bs[kB0 + 3][nB] = b0.w;
        Bs[kB0 + 4][nB] = b1.x; Bs[kB0 + 5][nB] = b1.y;
        Bs[kB0 + 6][nB] = b1.z; Bs[kB0 + 7][nB] = b1.w;
        __syncthreads();

#pragma unroll
        for (int kk = 0; kk < 16; kk++) {
            float4 av = *(const float4*)(&As[kk][tm * 4]);
            unsigned long long ap[4];
            ap[0] = pack2(av.x, av.x); ap[1] = pack2(av.y, av.y);
            ap[2] = pack2(av.z, av.z); ap[3] = pack2(av.w, av.w);
            const unsigned long long* bp =
                (const unsigned long long*)(&Bs[kk][tn * 8]);
            unsigned long long bq0 = bp[0], bq1 = bp[1], bq2 = bp[2], bq3 = bp[3];
#pragma unroll
            for (int i = 0; i < 4; i++) {
                acc[i][0] = fma2(ap[i], bq0, acc[i][0]);
                acc[i][1] = fma2(ap[i], bq1, acc[i][1]);
                acc[i][2] = fma2(ap[i], bq2, acc[i][2]);
                acc[i][3] = fma2(ap[i], bq3, acc[i][3]);
            }
        }
    }

#pragma unroll
    for (int i = 0; i < 4; i++) {
        int m = m0 + tm * 4 + i;
        if (m >= NN) continue;
        float* gout = g_P + (size_t)m * GDIM + n0 + tn * 8;
#pragma unroll
        for (int j = 0; j < 4; j++) {
            float2 v = unpack2(acc[i][j]);
            int n = n0 + tn * 8 + 2 * j;
            gout[2 * j + 0] = v.x + bih[n + 0] + bhh[n + 0];
            gout[2 * j + 1] = v.y + bih[n + 1] + bhh[n + 1];
        }
    }
}

// ---------------------------------------------------------------------------
// Fused LSTM on mma.sync + ldmatrix, single fp16 pass.
// 782 blocks x 256 threads, 1 CTA/SM. Warp w owns all 64 M rows x 64 permuted
// N cols (= 16 features x 4 gates). A (h fp16) double-buffered by step parity.
// ---------------------------------------------------------------------------
__global__ __launch_bounds__(256, 1)
void fused_lstm_mma(const int* __restrict__ src)
{
    extern __shared__ char sm[];
    const uint32_t smb = (uint32_t)__cvta_generic_to_shared(sm);
    const uint32_t Bk  = smb + SM_B;
    int* Ss = (int*)(sm + SM_SS);

    const int tid  = threadIdx.x;
    const int wid  = tid >> 5;
    const int lane = tid & 31;
    const int grp  = lane >> 2;
    const int tig  = lane & 3;
    const int m0   = blockIdx.x * BMF;

    // stage B image (133120 B = 8320 uint4)
#pragma unroll
    for (int r = 0; r < 33; r++) {
        int q = tid + 256 * r;
        if (q < 8320) cp16(Bk + (uint32_t)q * 16, g_Whk + q);
    }
    cp_commit();

    for (int i = tid; i < BMF * DEG; i += 256) {
        int node = m0 + i / DEG;
        Ss[i] = (node < NN) ? src[node * DEG + i % DEG] : 0;
    }
    __syncthreads();

    float c[32];
#pragma unroll
    for (int i = 0; i < 32; i++) c[i] = 0.f;

    // per-thread ldmatrix address components
    const int aRow = ((lane >> 3) & 1) * 8 + (lane & 7);
    const int aCol = (lane >> 4) * 16;                     // bytes (k+8 half)
    const int bRow = ((lane >> 3) & 1) * 8 + (lane & 7);   // k within 16
    const int bCol = ((lane >> 4) & 1) * 16;               // bytes (nt odd)

#pragma unroll 1
    for (int t = 0; t < DEG; t++) {
        const uint32_t Ard = smb + SM_A + (uint32_t)((t & 1) * 17408);
        const uint32_t Awr = smb + SM_A + (uint32_t)(((t + 1) & 1) * 17408);

#pragma unroll
        for (int mh = 0; mh < 2; mh++) {
            float acc[2][8][4];
#pragma unroll
            for (int i = 0; i < 2; i++)
#pragma unroll
                for (int j = 0; j < 8; j++)
#pragma unroll
                    for (int q = 0; q < 4; q++) acc[i][j][q] = 0.f;

            if (t > 0) {
#pragma unroll
                for (int kt = 0; kt < 8; kt++) {
                    uint32_t bfr[4][4];
#pragma unroll
                    for (int q = 0; q < 4; q++) {
                        uint32_t ba = Bk + (uint32_t)((kt * 16 + bRow) * 1040 +
                                       (wid * 64 + q * 16) * 2 + bCol);
                        ldsm4t(bfr[q], ba);
                    }
#pragma unroll
                    for (int mti = 0; mti < 2; mti++) {
                        const int mt = mh * 2 + mti;
                        uint32_t aa = Ard + (uint32_t)((mt * 16 + aRow) * 272 +
                                        kt * 32 + aCol);
                        uint32_t afh[4];
                        ldsm4(afh, aa);
#pragma unroll
                        for (int nt = 0; nt < 8; nt++) {
                            uint32_t b0 = bfr[nt >> 1][(nt & 1) * 2];
                            uint32_t b1 = bfr[nt >> 1][(nt & 1) * 2 + 1];
                            mma16816(acc[mti][nt], afh, b0, b1);
                        }
                    }
                }
            }

            // pointwise LSTM update for this m-half (gate order i,f,g,o)
#pragma unroll
            for (int mti = 0; mti < 2; mti++) {
                const int mt = mh * 2 + mti;
#pragma unroll
                for (int rsel = 0; rsel < 2; rsel++) {
                    const int ml   = mt * 16 + grp + rsel * 8;
                    const int node = m0 + ml;
                    const float* pr = g_P + (size_t)Ss[ml * DEG + t] * GDIM
                                          + wid * 16 + 2 * tig;
                    float2 Pv[4][2];
#pragma unroll
                    for (int g = 0; g < 4; g++) {
                        Pv[g][0] = *(const float2*)(pr + g * 128);
                        Pv[g][1] = *(const float2*)(pr + g * 128 + 8);
                    }
#pragma unroll
                    for (int fp = 0; fp < 2; fp++) {
                        float hv[2];
#pragma unroll
                        for (int p = 0; p < 2; p++) {
                            float gi = (p ? Pv[0][fp].y : Pv[0][fp].x);
                            float gf = (p ? Pv[1][fp].y : Pv[1][fp].x);
                            float gg = (p ? Pv[2][fp].y : Pv[2][fp].x);
                            float go = (p ? Pv[3][fp].y : Pv[3][fp].x);
                            if (t > 0) {
                                gi += acc[mti][0 + fp][rsel * 2 + p];
                                gf += acc[mti][2 + fp][rsel * 2 + p];
                                gg += acc[mti][4 + fp][rsel * 2 + p];
                                go += acc[mti][6 + fp][rsel * 2 + p];
                            }
                            const int ci = (mt * 2 + rsel) * 4 + fp * 2 + p;
                            float cn = fsig(gf) * c[ci] + fsig(gi) * htanh(gg);
                            c[ci] = cn;
                            hv[p] = fsig(go) * htanh(cn);
                        }
                        __half h0 = __float2half_rn(hv[0]);
                        __half h1 = __float2half_rn(hv[1]);
                        const uint32_t aw = Awr + (uint32_t)(ml * 272 +
                                            (wid * 16 + fp * 8 + 2 * tig) * 2);
                        uint32_t hipk = packh2(h0, h1);
                        asm volatile("st.shared.b32 [%0], %1;" :: "r"(aw), "r"(hipk));
                        if (t == DEG - 1 && node < NN) {
                            *(float2*)(g_H + (size_t)node * FDIM +
                                       wid * 16 + fp * 8 + 2 * tig) =
                                make_float2(hv[0], hv[1]);
                        }
                    }
                }
            }
        }
        if (t == 0) cp_wait0();     // B resident before first mma (t=1)
        __syncthreads();            // A buffer handoff
    }
}

// ---------------------------------------------------------------------------
// output GEMM: Out[m, n] = aggr[m]@Wl[n] + X[m]@Wr[n] + bl[n]  (opt ReLU)
// ---------------------------------------------------------------------------
template<bool RELU>
__global__ __launch_bounds__(256)
void out_kernel(const float* __restrict__ X,
                const float* __restrict__ Wl, const float* __restrict__ Wr,
                const float* __restrict__ bl, float* __restrict__ Out, int Fo)
{
    __shared__ float As[16][72];
    __shared__ float Bs[16][136];

    const int tid = threadIdx.x;
    const int m0 = blockIdx.x * 64;
    const int tm = tid & 15;
    const int tn = tid >> 4;

    unsigned long long acc[4][4];
#pragma unroll
    for (int i = 0; i < 4; i++)
#pragma unroll
        for (int j = 0; j < 4; j++) acc[i][j] = 0ull;

    const int mA  = tid >> 1;
    const int kA0 = (tid & 1) * 8;
    const float* arowa = nullptr;
    const float* arowx = nullptr;
    if (tid < 128) {
        int node = m0 + mA;
        if (node < NN) {
            arowa = g_H + (size_t)node * FDIM;
            arowx = X + (size_t)node * FDIM;
        }
    }
    const int nB  = tid >> 1;
    const int kB0 = (tid & 1) * 8;
    const bool nb_ok = (nB < Fo);
    const float* browl = Wl + (size_t)nB * FDIM;
    const float* browr = Wr + (size_t)nB * FDIM;

    for (int k0 = 0; k0 < 256; k0 += 16) {
        float4 a0 = make_float4(0.f, 0.f, 0.f, 0.f), a1 = a0;
        if (tid < 128 && arowa) {
            const float* ar = (k0 < 128) ? (arowa + k0) : (arowx + k0 - 128);
            a0 = *(const float4*)(ar + kA0);
            a1 = *(const float4*)(ar + kA0 + 4);
        }
        float4 b0 = make_float4(0.f, 0.f, 0.f, 0.f), b1 = b0;
        if (nb_ok) {
            const float* br = (k0 < 128) ? (browl + k0) : (browr + k0 - 128);
            b0 = *(const float4*)(br + kB0);
            b1 = *(const float4*)(br + kB0 + 4);
        }

        __syncthreads();
        if (tid < 128) {
            As[kA0 + 0][mA] = a0.x; As[kA0 + 1][mA] = a0.y;
            As[kA0 + 2][mA] = a0.z; As[kA0 + 3][mA] = a0.w;
            As[kA0 + 4][mA] = a1.x; As[kA0 + 5][mA] = a1.y;
            As[kA0 + 6][mA] = a1.z; As[kA0 + 7][mA] = a1.w;
        }
        Bs[kB0 + 0][nB] = b0.x; Bs[kB0 + 1][nB] = b0.y;
        Bs[kB0 + 2][nB] = b0.z; Bs[kB0 + 3][nB] = b0.w;
        Bs[kB0 + 4][nB] = b1.x; Bs[kB0 + 5][nB] = b1.y;
        Bs[kB0 + 6][nB] = b1.z; Bs[kB0 + 7][nB] = b1.w;
        __syncthreads();

#pragma unroll
        for (int kk = 0; kk < 16; kk++) {
            float4 av = *(const float4*)(&As[kk][tm * 4]);
            unsigned long long ap[4];
            ap[0] = pack2(av.x, av.x); ap[1] = pack2(av.y, av.y);
            ap[2] = pack2(av.z, av.z); ap[3] = pack2(av.w, av.w);
            const unsigned long long* bp =
                (const unsigned long long*)(&Bs[kk][tn * 8]);
            unsigned long long bq0 = bp[0], bq1 = bp[1], bq2 = bp[2], bq3 = bp[3];
#pragma unroll
            for (int i = 0; i < 4; i++) {
                acc[i][0] = fma2(ap[i], bq0, acc[i][0]);
                acc[i][1] = fma2(ap[i], bq1, acc[i][1]);
                acc[i][2] = fma2(ap[i], bq2, acc[i][2]);
                acc[i][3] = fma2(ap[i], bq3, acc[i][3]);
            }
        }
    }

#pragma unroll
    for (int i = 0; i < 4; i++) {
        int m = m0 + tm * 4 + i;
        if (m >= NN) continue;
#pragma unroll
        for (int j = 0; j < 4; j++) {
            float2 v = unpack2(acc[i][j]);
            int n = tn * 8 + 2 * j;
            if (n < Fo) {
                float o0 = v.x + bl[n];
                if (RELU) o0 = fmaxf(o0, 0.f);
                Out[(size_t)m * Fo + n] = o0;
            }
            if (n + 1 < Fo) {
                float o1 = v.y + bl[n + 1];
                if (RELU) o1 = fmaxf(o1, 0.f);
                Out[(size_t)m * Fo + n + 1] = o1;
            }
        }
    }
}

// ---------------------------------------------------------------------------
// host launcher
// ---------------------------------------------------------------------------
extern "C" void kernel_launch(void* const* d_in, const int* in_sizes, int n_in,
                              void* d_out, int out_size)
{
    (void)in_sizes; (void)n_in; (void)out_size;
    const float* x   = (const float*)d_in[0];
    const int*   src = (const int*)d_in[1];

    const float* P[21];
    for (int i = 0; i < 21; i++) P[i] = (const float*)d_in[2 + i];

    float *a1 = nullptr, *a2 = nullptr;
    cudaGetSymbolAddress((void**)&a1, g_A1);
    cudaGetSymbolAddress((void**)&a2, g_A2);

    static bool attr_set = false;
    if (!attr_set) {
        cudaFuncSetAttribute(fused_lstm_mma,
                             cudaFuncAttributeMaxDynamicSharedMemorySize,
                             SM_TOTAL);
        attr_set = true;
    }

    const dim3 blk(256);
    const dim3 gPre((NN + 63) / 64, 4);
    const dim3 gOut((NN + 63) / 64, 1);
    const int  gFused = (NN + BMF - 1) / BMF;
    const int  gConv  = (GDIM * FDIM + 255) / 256;

    const float* Xin = x;
    for (int l = 0; l < 3; l++) {
        const float* Wih = P[7 * l + 0];
        const float* Whh = P[7 * l + 1];
        const float* bih = P[7 * l + 2];
        const float* bhh = P[7 * l + 3];
        const float* Wl  = P[7 * l + 4];
        const float* bl  = P[7 * l + 5];
        const float* Wr  = P[7 * l + 6];

        conv_whh<<<gConv, blk>>>(Whh);
        pre_kernel<<<gPre, blk>>>(Xin, Wih, bih, bhh);
        fused_lstm_mma<<<gFused, blk, SM_TOTAL>>>(src);

        if (l == 0) {
            out_kernel<true><<<gOut, blk>>>(Xin, Wl, Wr, bl, a1, 128);
            Xin = a1;
        } else if (l == 1) {
            out_kernel<true><<<gOut, blk>>>(Xin, Wl, Wr, bl, a2, 128);
            Xin = a2;
        } else {
            out_kernel<false><<<gOut, blk>>>(Xin, Wl, Wr, bl, (float*)d_out, 64);
        }
    }
}

// round 12
// speedup vs baseline: 12.4000x; 1.9225x over previous
#include <cuda_runtime.h>
#include <cuda_fp16.h>
#include <cstdint>

// ---------------------------------------------------------------------------
// GraphSAGE with LSTM aggregation, 3 layers — round 10. All GEMMs on
// mma.sync.m16n8k16 (fp16 in, fp32 acc), fragments via ldmatrix.
//   conv_x:    input x -> fp16 image g_Xh (once)
//   conv_*:    per-layer fp16 weight images (Whh permuted, Wih K-major,
//              [Wl|Wr] K-major)
//   pre_mma:   P = X@Wih^T + (bih+bhh)  -> fp16, gather-permuted layout g_Pp
//   fused:     block=64 nodes, 16 LSTM steps, D = h@Whh^T (mma), pointwise;
//              P-gather = 2 LDG.128 per row (layout matches fragment owners)
//   out_mma:   lin_l(h)+lin_r(x)+bl; ReLU+fp16 g_Xh for layers 1-2,
//              fp32 d_out for layer 3
// ---------------------------------------------------------------------------

#define NN   50000
#define DEG  16
#define FDIM 128
#define GDIM 512
#define BMF  64

__device__ uint4 g_Whk[8320];      // fused B: Whh fp16 [k][520] (gate-permuted n)
__device__ uint4 g_Wik[8320];      // pre  B: Wih fp16 [k][520] (original n)
__device__ uint4 g_Wout[4352];     // out  B: [Wl|Wr] fp16 [256][136 or 72]
__device__ uint4 g_Xh[800000];     // layer input fp16 [m][128]
__device__ uint4 g_Hh[800000];     // aggr h fp16 [m][128]
__device__ uint4 g_Pp[3200000];    // P fp16, permuted [m][512]

// fused SMEM (bytes): B 133120 | A 2 bufs x 17408 | src ids 4096
#define SM_B     0
#define SM_A     133120
#define SM_SS    167936
#define SM_TOTAL 172032

// ---- fast activations (HW tanh; accuracy proven R8/R9) ---------------------
__device__ __forceinline__ float htanh(float x) {
    float y;
    asm("tanh.approx.f32 %0, %1;" : "=f"(y) : "f"(x));
    return y;
}
__device__ __forceinline__ float fsig(float x) {
    return fmaf(0.5f, htanh(0.5f * x), 0.5f);
}

// ---- cp.async --------------------------------------------------------------
__device__ __forceinline__ void cp16(uint32_t saddr, const void* gaddr) {
    asm volatile("cp.async.cg.shared.global [%0], [%1], 16;"
                 :: "r"(saddr), "l"(gaddr));
}
__device__ __forceinline__ void cp_commit() { asm volatile("cp.async.commit_group;"); }
__device__ __forceinline__ void cp_wait0()  { asm volatile("cp.async.wait_group 0;"); }

// ---- mma / ldmatrix --------------------------------------------------------
__device__ __forceinline__ void mma16816(float* d, const uint32_t* a,
                                         uint32_t b0, uint32_t b1) {
    asm volatile(
        "mma.sync.aligned.m16n8k16.row.col.f32.f16.f16.f32 "
        "{%0,%1,%2,%3},{%4,%5,%6,%7},{%8,%9},{%0,%1,%2,%3};"
        : "+f"(d[0]), "+f"(d[1]), "+f"(d[2]), "+f"(d[3])
        : "r"(a[0]), "r"(a[1]), "r"(a[2]), "r"(a[3]), "r"(b0), "r"(b1));
}
__device__ __forceinline__ void ldsm4(uint32_t* r, uint32_t a) {
    asm volatile("ldmatrix.sync.aligned.m8n8.x4.shared.b16 {%0,%1,%2,%3}, [%4];"
                 : "=r"(r[0]), "=r"(r[1]), "=r"(r[2]), "=r"(r[3]) : "r"(a));
}
__device__ __forceinline__ void ldsm4t(uint32_t* r, uint32_t a) {
    asm volatile("ldmatrix.sync.aligned.m8n8.x4.trans.shared.b16 {%0,%1,%2,%3}, [%4];"
                 : "=r"(r[0]), "=r"(r[1]), "=r"(r[2]), "=r"(r[3]) : "r"(a));
}
__device__ __forceinline__ uint32_t packh2(__half a, __half b) {
    return ((uint32_t)__half_as_ushort(b) << 16) | (uint32_t)__half_as_ushort(a);
}

// ---------------------------------------------------------------------------
// conversion kernels
// ---------------------------------------------------------------------------
__global__ void conv_x(const float* __restrict__ x)
{
    int i = blockIdx.x * blockDim.x + threadIdx.x;
    if (i >= NN * 64) return;
    float2 v = ((const float2*)x)[i];
    ((__half2*)g_Xh)[i] = __floats2half2_rn(v.x, v.y);
}

// Whh [512][128] -> [k][520], permuted col n = w*64 + g*16 + f (r = g*128+w*16+f)
__global__ void conv_whh(const float* __restrict__ W)
{
    int idx = blockIdx.x * blockDim.x + threadIdx.x;
    if (idx >= GDIM * FDIM) return;
    int r = idx >> 7, k = idx & 127;
    int g = r >> 7, w = (r >> 4) & 7, f = r & 15;
    int n = w * 64 + g * 16 + f;
    ((__half*)g_Whk)[k * 520 + n] = __float2half_rn(W[idx]);
}

// Wih [512][128] -> [k][520], original n order
__global__ void conv_wih(const float* __restrict__ W)
{
    int idx = blockIdx.x * blockDim.x + threadIdx.x;
    if (idx >= GDIM * FDIM) return;
    int n = idx >> 7, k = idx & 127;
    ((__half*)g_Wik)[k * 520 + n] = __float2half_rn(W[idx]);
}

// [Wl|Wr] -> [k=0..255][n], row padded to BPAD halfs
__global__ void conv_wout(const float* __restrict__ Wl,
                          const float* __restrict__ Wr, int FO, int BPAD)
{
    int idx = blockIdx.x * blockDim.x + threadIdx.x;
    if (idx >= FO * 256) return;
    int n = idx >> 8, k = idx & 255;
    float v = (k < 128) ? Wl[n * 128 + k] : Wr[n * 128 + (k - 128)];
    ((__half*)g_Wout)[k * BPAD + n] = __float2half_rn(v);
}

// ---------------------------------------------------------------------------
// pre_mma: P = X @ Wih^T + (bih+bhh), fp16 output in gather-permuted layout.
// Grid (391, 4); BM=128, BN=128, K=128. Warp (wm 0-1)x(wn 0-3): 64m x 32n.
// Permuted store pos (within 512): w*64 + tig*16 + g*4 + fp*2 + p,
// where original n = g*128 + w*16 + (fp*8 + 2*tig + p).
// ---------------------------------------------------------------------------
__global__ __launch_bounds__(256)
void pre_mma(const float* __restrict__ bih, const float* __restrict__ bhh)
{
    extern __shared__ char sm[];
    const uint32_t smb = (uint32_t)__cvta_generic_to_shared(sm);
    const uint32_t Asm = smb, Bsm = smb + 34816;
    const int tid = threadIdx.x, wid = tid >> 5, lane = tid & 31;
    const int m0 = blockIdx.x * 128, n0 = blockIdx.y * 128;

    for (int i = tid; i < 2048; i += 256) {
        int r = i >> 4, j = i & 15;
        int node = m0 + r; if (node >= NN) node = NN - 1;
        cp16(Asm + (uint32_t)(r * 272 + j * 16),
             (const char*)g_Xh + (size_t)node * 256 + j * 16);
    }
    for (int i = tid; i < 2048; i += 256) {
        int r = i >> 4, j = i & 15;
        cp16(Bsm + (uint32_t)(r * 272 + j * 16),
             (const char*)g_Wik + (size_t)r * 1040 + n0 * 2 + j * 16);
    }
    cp_commit(); cp_wait0(); __syncthreads();

    const int wm = wid >> 2, wn = wid & 3;
    const int aRow = ((lane >> 3) & 1) * 8 + (lane & 7);
    const int aCol = (lane >> 4) * 16;
    const int bRow = aRow;
    const int bCol = ((lane >> 4) & 1) * 16;

    float acc[4][4][4];
#pragma unroll
    for (int a = 0; a < 4; a++)
#pragma unroll
        for (int b = 0; b < 4; b++)
#pragma unroll
            for (int q = 0; q < 4; q++) acc[a][b][q] = 0.f;

#pragma unroll
    for (int kt = 0; kt < 8; kt++) {
        uint32_t bfr[2][4];
#pragma unroll
        for (int q = 0; q < 2; q++)
            ldsm4t(bfr[q], Bsm + (uint32_t)((kt * 16 + bRow) * 272 +
                   (wn * 32 + q * 16) * 2 + bCol));
#pragma unroll
        for (int mt = 0; mt < 4; mt++) {
            uint32_t af[4];
            ldsm4(af, Asm + (uint32_t)((wm * 64 + mt * 16 + aRow) * 272 +
                   kt * 32 + aCol));
#pragma unroll
            for (int nt = 0; nt < 4; nt++)
                mma16816(acc[mt][nt], af, bfr[nt >> 1][(nt & 1) * 2],
                         bfr[nt >> 1][(nt & 1) * 2 + 1]);
        }
    }

    const int grp = lane >> 2, tig = lane & 3;
#pragma unroll
    for (int nt = 0; nt < 4; nt++) {
        int n = n0 + wn * 32 + nt * 8 + 2 * tig;
        float b0 = bih[n] + bhh[n];
        float b1 = bih[n + 1] + bhh[n + 1];
        int g = n >> 7, w = (n >> 4) & 7, f = n & 15;
        int dsti = w * 64 + ((f >> 1) & 3) * 16 + g * 4 + (f >> 3) * 2;
#pragma unroll
        for (int mt = 0; mt < 4; mt++) {
            int r0 = m0 + wm * 64 + mt * 16 + grp;
            if (r0 < NN)
                ((__half2*)g_Pp)[((size_t)r0 * 512 + dsti) >> 1] =
                    __floats2half2_rn(acc[mt][nt][0] + b0, acc[mt][nt][1] + b1);
            int r1 = r0 + 8;
            if (r1 < NN)
                ((__half2*)g_Pp)[((size_t)r1 * 512 + dsti) >> 1] =
                    __floats2half2_rn(acc[mt][nt][2] + b0, acc[mt][nt][3] + b1);
        }
    }
}

// ---------------------------------------------------------------------------
// Fused LSTM on mma.sync + ldmatrix, fp16 h, fp16 permuted P gather.
// 782 blocks x 256 threads, 1 CTA/SM.
// ---------------------------------------------------------------------------
__global__ __launch_bounds__(256, 1)
void fused_lstm_mma(const int* __restrict__ src)
{
    extern __shared__ char sm[];
    const uint32_t smb = (uint32_t)__cvta_generic_to_shared(sm);
    const uint32_t Bk  = smb + SM_B;
    int* Ss = (int*)(sm + SM_SS);

    const int tid  = threadIdx.x;
    const int wid  = tid >> 5;
    const int lane = tid & 31;
    const int grp  = lane >> 2;
    const int tig  = lane & 3;
    const int m0   = blockIdx.x * BMF;

#pragma unroll
    for (int r = 0; r < 33; r++) {
        int q = tid + 256 * r;
        if (q < 8320) cp16(Bk + (uint32_t)q * 16, g_Whk + q);
    }
    cp_commit();

    for (int i = tid; i < BMF * DEG; i += 256) {
        int node = m0 + i / DEG;
        Ss[i] = (node < NN) ? src[node * DEG + i % DEG] : 0;
    }
    __syncthreads();

    float c[32];
#pragma unroll
    for (int i = 0; i < 32; i++) c[i] = 0.f;

    const int aRow = ((lane >> 3) & 1) * 8 + (lane & 7);
    const int aCol = (lane >> 4) * 16;
    const int bRow = aRow;
    const int bCol = ((lane >> 4) & 1) * 16;

#pragma unroll 1
    for (int t = 0; t < DEG; t++) {
        const uint32_t Ard = smb + SM_A + (uint32_t)((t & 1) * 17408);
        const uint32_t Awr = smb + SM_A + (uint32_t)(((t + 1) & 1) * 17408);

#pragma unroll
        for (int mh = 0; mh < 2; mh++) {
            // prefetch permuted P rows for this m-half (2 LDG.128 per row)
            uint4 pf[4][2];
#pragma unroll
            for (int mti = 0; mti < 2; mti++)
#pragma unroll
                for (int rsel = 0; rsel < 2; rsel++) {
                    const int ml = (mh * 2 + mti) * 16 + grp + rsel * 8;
                    const uint4* pb = g_Pp +
                        ((size_t)Ss[ml * DEG + t] * 64 + wid * 8 + tig * 2);
                    pf[mti * 2 + rsel][0] = pb[0];
                    pf[mti * 2 + rsel][1] = pb[1];
                }

            float acc[2][8][4];
#pragma unroll
            for (int i = 0; i < 2; i++)
#pragma unroll
                for (int j = 0; j < 8; j++)
#pragma unroll
                    for (int q = 0; q < 4; q++) acc[i][j][q] = 0.f;

            if (t > 0) {
#pragma unroll
                for (int kt = 0; kt < 8; kt++) {
                    uint32_t bfr[4][4];
#pragma unroll
                    for (int q = 0; q < 4; q++) {
                        uint32_t ba = Bk + (uint32_t)((kt * 16 + bRow) * 1040 +
                                       (wid * 64 + q * 16) * 2 + bCol);
                        ldsm4t(bfr[q], ba);
                    }
#pragma unroll
                    for (int mti = 0; mti < 2; mti++) {
                        const int mt = mh * 2 + mti;
                        uint32_t aa = Ard + (uint32_t)((mt * 16 + aRow) * 272 +
                                        kt * 32 + aCol);
                        uint32_t afh[4];
                        ldsm4(afh, aa);
#pragma unroll
                        for (int nt = 0; nt < 8; nt++) {
                            uint32_t b0 = bfr[nt >> 1][(nt & 1) * 2];
                            uint32_t b1 = bfr[nt >> 1][(nt & 1) * 2 + 1];
                            mma16816(acc[mti][nt], afh, b0, b1);
                        }
                    }
                }
            }

            // pointwise LSTM update (gate order i,f,g,o)
#pragma unroll
            for (int mti = 0; mti < 2; mti++) {
                const int mt = mh * 2 + mti;
#pragma unroll
                for (int rsel = 0; rsel < 2; rsel++) {
                    const int ml   = mt * 16 + grp + rsel * 8;
                    const int node = m0 + ml;
                    const __half2* hp =
                        (const __half2*)&pf[mti * 2 + rsel][0];
#pragma unroll
                    for (int fp = 0; fp < 2; fp++) {
                        float2 PI = __half22float2(hp[0 + fp]);
                        float2 PF = __half22float2(hp[2 + fp]);
                        float2 PG = __half22float2(hp[4 + fp]);
                        float2 PO = __half22float2(hp[6 + fp]);
                        float hv[2];
#pragma unroll
                        for (int p = 0; p < 2; p++) {
                            float gi = p ? PI.y : PI.x;
                            float gf = p ? PF.y : PF.x;
                            float gg = p ? PG.y : PG.x;
                            float go = p ? PO.y : PO.x;
                            if (t > 0) {
                                gi += acc[mti][0 + fp][rsel * 2 + p];
                                gf += acc[mti][2 + fp][rsel * 2 + p];
                                gg += acc[mti][4 + fp][rsel * 2 + p];
                                go += acc[mti][6 + fp][rsel * 2 + p];
                            }
                            const int ci = (mt * 2 + rsel) * 4 + fp * 2 + p;
                            float cn = fsig(gf) * c[ci] + fsig(gi) * htanh(gg);
                            c[ci] = cn;
                            hv[p] = fsig(go) * htanh(cn);
                        }
                        uint32_t hipk = packh2(__float2half_rn(hv[0]),
                                               __float2half_rn(hv[1]));
                        const uint32_t aw = Awr + (uint32_t)(ml * 272 +
                                            (wid * 16 + fp * 8 + 2 * tig) * 2);
                        asm volatile("st.shared.b32 [%0], %1;" :: "r"(aw), "r"(hipk));
                        if (t == DEG - 1 && node < NN) {
                            *((uint32_t*)((__half*)g_Hh + (size_t)node * 128 +
                                          wid * 16 + fp * 8 + 2 * tig)) = hipk;
                        }
                    }
                }
            }
        }
        if (t == 0) cp_wait0();     // B resident before first mma (t=1)
        __syncthreads();            // A buffer handoff
    }
}

// ---------------------------------------------------------------------------
// out_mma: Out = h@Wl^T + x@Wr^T + bl.  BM=128, BN=FO, K=256 ([h|x]).
// FO=128+ReLU -> fp16 g_Xh; FO=64 -> fp32 d_out.
// ---------------------------------------------------------------------------
template<int FO, bool RELU>
__global__ __launch_bounds__(256)
void out_mma(const float* __restrict__ bl, float* __restrict__ OutF)
{
    constexpr int BROW = (FO == 128) ? 272 : 144;   // B smem row bytes
    constexpr int BCH  = BROW / 16;
    constexpr int WN   = FO / 32;
    constexpr int MT   = (FO == 128) ? 4 : 2;

    extern __shared__ char sm[];
    const uint32_t smb = (uint32_t)__cvta_generic_to_shared(sm);
    const uint32_t Asm = smb, Bsm = smb + 69632;
    const int tid = threadIdx.x, wid = tid >> 5, lane = tid & 31;
    const int m0 = blockIdx.x * 128;

    for (int i = tid; i < 4096; i += 256) {
        int r = i >> 5, j = i & 31;
        int node = m0 + r; if (node >= NN) node = NN - 1;
        const char* srcp = (j < 16)
            ? (const char*)g_Hh + (size_t)node * 256 + j * 16
            : (const char*)g_Xh + (size_t)node * 256 + (j - 16) * 16;
        cp16(Asm + (uint32_t)(r * 544 + j * 16), srcp);
    }
    for (int i = tid; i < 256 * BCH; i += 256) {
        int r = i / BCH, j = i % BCH;
        cp16(Bsm + (uint32_t)(r * BROW + j * 16),
             (const char*)g_Wout + (size_t)r * BROW + j * 16);
    }
    cp_commit(); cp_wait0(); __syncthreads();

    const int wn = wid % WN, wm = wid / WN;
    const int aRow = ((lane >> 3) & 1) * 8 + (lane & 7);
    const int aCol = (lane >> 4) * 16;
    const int bRow = aRow;
    const int bCol = ((lane >> 4) & 1) * 16;

    float acc[MT][4][4];
#pragma unroll
    for (int a = 0; a < MT; a++)
#pragma unroll
        for (int b = 0; b < 4; b++)
#pragma unroll
            for (int q = 0; q < 4; q++) acc[a][b][q] = 0.f;

#pragma unroll
    for (int kt = 0; kt < 16; kt++) {
        uint32_t bfr[2][4];
#pragma unroll
        for (int q = 0; q < 2; q++)
            ldsm4t(bfr[q], Bsm + (uint32_t)((kt * 16 + bRow) * BROW +
                   (wn * 32 + q * 16) * 2 + bCol));
#pragma unroll
        for (int mt = 0; mt < MT; mt++) {
            uint32_t af[4];
            ldsm4(af, Asm + (uint32_t)((wm * MT * 16 + mt * 16 + aRow) * 544 +
                   kt * 32 + aCol));
#pragma unroll
            for (int nt = 0; nt < 4; nt++)
                mma16816(acc[mt][nt], af, bfr[nt >> 1][(nt & 1) * 2],
                         bfr[nt >> 1][(nt & 1) * 2 + 1]);
        }
    }

    const int grp = lane >> 2, tig = lane & 3;
#pragma unroll
    for (int nt = 0; nt < 4; nt++) {
        int n = wn * 32 + nt * 8 + 2 * tig;
        float b0 = bl[n], b1 = bl[n + 1];
#pragma unroll
        for (int mt = 0; mt < MT; mt++) {
            int r0 = m0 + wm * MT * 16 + mt * 16 + grp;
#pragma unroll
            for (int half = 0; half < 2; half++) {
                int r = r0 + half * 8;
                if (r >= NN) continue;
                float v0 = acc[mt][nt][half * 2 + 0] + b0;
                float v1 = acc[mt][nt][half * 2 + 1] + b1;
                if (RELU) {
                    v0 = fmaxf(v0, 0.f); v1 = fmaxf(v1, 0.f);
                    ((__half2*)g_Xh)[((size_t)r * 128 + n) >> 1] =
                        __floats2half2_rn(v0, v1);
                } else {
                    *(float2*)(OutF + (size_t)r * FO + n) = make_float2(v0, v1);
                }
            }
        }
    }
}

// ---------------------------------------------------------------------------
// host launcher
// ---------------------------------------------------------------------------
extern "C" void kernel_launch(void* const* d_in, const int* in_sizes, int n_in,
                              void* d_out, int out_size)
{
    (void)in_sizes; (void)n_in; (void)out_size;
    const float* x   = (const float*)d_in[0];
    const int*   src = (const int*)d_in[1];

    const float* P[21];
    for (int i = 0; i < 21; i++) P[i] = (const float*)d_in[2 + i];

    static bool attr_set = false;
    if (!attr_set) {
        cudaFuncSetAttribute(fused_lstm_mma,
                             cudaFuncAttributeMaxDynamicSharedMemorySize, SM_TOTAL);
        cudaFuncSetAttribute(pre_mma,
                             cudaFuncAttributeMaxDynamicSharedMemorySize, 69632);
        cudaFuncSetAttribute(out_mma<128, true>,
                             cudaFuncAttributeMaxDynamicSharedMemorySize, 139264);
        cudaFuncSetAttribute(out_mma<64, false>,
                             cudaFuncAttributeMaxDynamicSharedMemorySize, 106496);
        attr_set = true;
    }

    const dim3 blk(256);
    const int  gConv = (GDIM * FDIM + 255) / 256;     // 256 blocks

    conv_x<<<(NN * 64 + 255) / 256, blk>>>(x);

    for (int l = 0; l < 3; l++) {
        const float* Wih = P[7 * l + 0];
        const float* Whh = P[7 * l + 1];
        const float* bih = P[7 * l + 2];
        const float* bhh = P[7 * l + 3];
        const float* Wl  = P[7 * l + 4];
        const float* bl  = P[7 * l + 5];
        const float* Wr  = P[7 * l + 6];

        conv_whh<<<gConv, blk>>>(Whh);
        conv_wih<<<gConv, blk>>>(Wih);
        if (l < 2)
            conv_wout<<<(128 * 256 + 255) / 256, blk>>>(Wl, Wr, 128, 136);
        else
            conv_wout<<<(64 * 256 + 255) / 256, blk>>>(Wl, Wr, 64, 72);

        pre_mma<<<dim3((NN + 127) / 128, 4), blk, 69632>>>(bih, bhh);
        fused_lstm_mma<<<(NN + BMF - 1) / BMF, blk, SM_TOTAL>>>(src);

        if (l < 2)
            out_mma<128, true><<<(NN + 127) / 128, blk, 139264>>>(bl, nullptr);
        else
            out_mma<64, false><<<(NN + 127) / 128, blk, 106496>>>(bl, (float*)d_out);
    }
}

// round 13
// speedup vs baseline: 12.8003x; 1.0323x over previous
#include <cuda_runtime.h>
#include <cuda_fp16.h>
#include <cstdint>

// ---------------------------------------------------------------------------
// GraphSAGE with LSTM aggregation, 3 layers — round 12.
// All GEMMs on mma.sync.m16n8k16 (fp16 in, fp32 acc) via ldmatrix.
// Fused LSTM now runs 512 threads/CTA (16 warps = 8 N-blocks x 2 row-halves)
// so tensor/MUFU/FMA/LSU pipes overlap across 4 warps per SMSP.
// Numerics identical to round 11 (rel_err ~5.3e-4, deterministic inputs).
// ---------------------------------------------------------------------------

#define NN   50000
#define DEG  16
#define FDIM 128
#define GDIM 512
#define BMF  64

__device__ uint4 g_Whk[8320];      // fused B: Whh fp16 [k][520] (gate-permuted n)
__device__ uint4 g_Wik[8320];      // pre  B: Wih fp16 [k][520] (original n)
__device__ uint4 g_Wout[4352];     // out  B: [Wl|Wr] fp16 [256][136 or 72]
__device__ uint4 g_Xh[800000];     // layer input fp16 [m][128]
__device__ uint4 g_Hh[800000];     // aggr h fp16 [m][128]
__device__ uint4 g_Pp[3200000];    // P fp16, permuted [m][512]

// fused SMEM (bytes): B 133120 | A 2 bufs x 17408 | src ids 4096
#define SM_B     0
#define SM_A     133120
#define SM_SS    167936
#define SM_TOTAL 172032

// ---- fast activations (HW tanh) --------------------------------------------
__device__ __forceinline__ float htanh(float x) {
    float y;
    asm("tanh.approx.f32 %0, %1;" : "=f"(y) : "f"(x));
    return y;
}
__device__ __forceinline__ float fsig(float x) {
    return fmaf(0.5f, htanh(0.5f * x), 0.5f);
}

// ---- cp.async --------------------------------------------------------------
__device__ __forceinline__ void cp16(uint32_t saddr, const void* gaddr) {
    asm volatile("cp.async.cg.shared.global [%0], [%1], 16;"
                 :: "r"(saddr), "l"(gaddr));
}
__device__ __forceinline__ void cp_commit() { asm volatile("cp.async.commit_group;"); }
__device__ __forceinline__ void cp_wait0()  { asm volatile("cp.async.wait_group 0;"); }

// ---- mma / ldmatrix --------------------------------------------------------
__device__ __forceinline__ void mma16816(float* d, const uint32_t* a,
                                         uint32_t b0, uint32_t b1) {
    asm volatile(
        "mma.sync.aligned.m16n8k16.row.col.f32.f16.f16.f32 "
        "{%0,%1,%2,%3},{%4,%5,%6,%7},{%8,%9},{%0,%1,%2,%3};"
        : "+f"(d[0]), "+f"(d[1]), "+f"(d[2]), "+f"(d[3])
        : "r"(a[0]), "r"(a[1]), "r"(a[2]), "r"(a[3]), "r"(b0), "r"(b1));
}
__device__ __forceinline__ void ldsm4(uint32_t* r, uint32_t a) {
    asm volatile("ldmatrix.sync.aligned.m8n8.x4.shared.b16 {%0,%1,%2,%3}, [%4];"
                 : "=r"(r[0]), "=r"(r[1]), "=r"(r[2]), "=r"(r[3]) : "r"(a));
}
__device__ __forceinline__ void ldsm4t(uint32_t* r, uint32_t a) {
    asm volatile("ldmatrix.sync.aligned.m8n8.x4.trans.shared.b16 {%0,%1,%2,%3}, [%4];"
                 : "=r"(r[0]), "=r"(r[1]), "=r"(r[2]), "=r"(r[3]) : "r"(a));
}
__device__ __forceinline__ uint32_t packh2(__half a, __half b) {
    return ((uint32_t)__half_as_ushort(b) << 16) | (uint32_t)__half_as_ushort(a);
}

// ---------------------------------------------------------------------------
// conversion kernels
// ---------------------------------------------------------------------------
__global__ void conv_x(const float* __restrict__ x)
{
    int i = blockIdx.x * blockDim.x + threadIdx.x;
    if (i >= NN * 64) return;
    float2 v = ((const float2*)x)[i];
    ((__half2*)g_Xh)[i] = __floats2half2_rn(v.x, v.y);
}

// Whh -> [k][520] gate-permuted  AND  Wih -> [k][520] original, one kernel.
__global__ void conv_wrec(const float* __restrict__ Whh,
                          const float* __restrict__ Wih)
{
    int idx = blockIdx.x * blockDim.x + threadIdx.x;
    if (idx < GDIM * FDIM) {
        int r = idx >> 7, k = idx & 127;
        int g = r >> 7, w = (r >> 4) & 7, f = r & 15;
        int n = w * 64 + g * 16 + f;
        ((__half*)g_Whk)[k * 520 + n] = __float2half_rn(Whh[idx]);
    } else if (idx < 2 * GDIM * FDIM) {
        int j = idx - GDIM * FDIM;
        int n = j >> 7, k = j & 127;
        ((__half*)g_Wik)[k * 520 + n] = __float2half_rn(Wih[j]);
    }
}

// [Wl|Wr] -> [k=0..255][n], row padded to BPAD halfs
__global__ void conv_wout(const float* __restrict__ Wl,
                          const float* __restrict__ Wr, int FO, int BPAD)
{
    int idx = blockIdx.x * blockDim.x + threadIdx.x;
    if (idx >= FO * 256) return;
    int n = idx >> 8, k = idx & 255;
    float v = (k < 128) ? Wl[n * 128 + k] : Wr[n * 128 + (k - 128)];
    ((__half*)g_Wout)[k * BPAD + n] = __float2half_rn(v);
}

// ---------------------------------------------------------------------------
// pre_mma: P = X @ Wih^T + (bih+bhh), fp16 output in gather-permuted layout.
// ---------------------------------------------------------------------------
__global__ __launch_bounds__(256)
void pre_mma(const float* __restrict__ bih, const float* __restrict__ bhh)
{
    extern __shared__ char sm[];
    const uint32_t smb = (uint32_t)__cvta_generic_to_shared(sm);
    const uint32_t Asm = smb, Bsm = smb + 34816;
    const int tid = threadIdx.x, wid = tid >> 5, lane = tid & 31;
    const int m0 = blockIdx.x * 128, n0 = blockIdx.y * 128;

    for (int i = tid; i < 2048; i += 256) {
        int r = i >> 4, j = i & 15;
        int node = m0 + r; if (node >= NN) node = NN - 1;
        cp16(Asm + (uint32_t)(r * 272 + j * 16),
             (const char*)g_Xh + (size_t)node * 256 + j * 16);
    }
    for (int i = tid; i < 2048; i += 256) {
        int r = i >> 4, j = i & 15;
        cp16(Bsm + (uint32_t)(r * 272 + j * 16),
             (const char*)g_Wik + (size_t)r * 1040 + n0 * 2 + j * 16);
    }
    cp_commit(); cp_wait0(); __syncthreads();

    const int wm = wid >> 2, wn = wid & 3;
    const int aRow = ((lane >> 3) & 1) * 8 + (lane & 7);
    const int aCol = (lane >> 4) * 16;
    const int bRow = aRow;
    const int bCol = ((lane >> 4) & 1) * 16;

    float acc[4][4][4];
#pragma unroll
    for (int a = 0; a < 4; a++)
#pragma unroll
        for (int b = 0; b < 4; b++)
#pragma unroll
            for (int q = 0; q < 4; q++) acc[a][b][q] = 0.f;

#pragma unroll
    for (int kt = 0; kt < 8; kt++) {
        uint32_t bfr[2][4];
#pragma unroll
        for (int q = 0; q < 2; q++)
            ldsm4t(bfr[q], Bsm + (uint32_t)((kt * 16 + bRow) * 272 +
                   (wn * 32 + q * 16) * 2 + bCol));
#pragma unroll
        for (int mt = 0; mt < 4; mt++) {
            uint32_t af[4];
            ldsm4(af, Asm + (uint32_t)((wm * 64 + mt * 16 + aRow) * 272 +
                   kt * 32 + aCol));
#pragma unroll
            for (int nt = 0; nt < 4; nt++)
                mma16816(acc[mt][nt], af, bfr[nt >> 1][(nt & 1) * 2],
                         bfr[nt >> 1][(nt & 1) * 2 + 1]);
        }
    }

    const int grp = lane >> 2, tig = lane & 3;
#pragma unroll
    for (int nt = 0; nt < 4; nt++) {
        int n = n0 + wn * 32 + nt * 8 + 2 * tig;
        float b0 = bih[n] + bhh[n];
        float b1 = bih[n + 1] + bhh[n + 1];
        int g = n >> 7, w = (n >> 4) & 7, f = n & 15;
        int dsti = w * 64 + ((f >> 1) & 3) * 16 + g * 4 + (f >> 3) * 2;
#pragma unroll
        for (int mt = 0; mt < 4; mt++) {
            int r0 = m0 + wm * 64 + mt * 16 + grp;
            if (r0 < NN)
                ((__half2*)g_Pp)[((size_t)r0 * 512 + dsti) >> 1] =
                    __floats2half2_rn(acc[mt][nt][0] + b0, acc[mt][nt][1] + b1);
            int r1 = r0 + 8;
            if (r1 < NN)
                ((__half2*)g_Pp)[((size_t)r1 * 512 + dsti) >> 1] =
                    __floats2half2_rn(acc[mt][nt][2] + b0, acc[mt][nt][3] + b1);
        }
    }
}

// ---------------------------------------------------------------------------
// Fused LSTM on mma.sync + ldmatrix. 782 blocks x 512 threads, 1 CTA/SM.
// Warp = (w8 = wid>>1: N-block of 64 permuted cols, mh = wid&1: 32-row half).
// Same layouts as round 11; per-warp M halved for pipe overlap.
// ---------------------------------------------------------------------------
__global__ __launch_bounds__(512, 1)
void fused_lstm_mma(const int* __restrict__ src)
{
    extern __shared__ char sm[];
    const uint32_t smb = (uint32_t)__cvta_generic_to_shared(sm);
    const uint32_t Bk  = smb + SM_B;
    int* Ss = (int*)(sm + SM_SS);

    const int tid  = threadIdx.x;
    const int wid  = tid >> 5;
    const int w8   = wid >> 1;      // N block 0..7
    const int mh   = wid & 1;       // row half 0..1
    const int lane = tid & 31;
    const int grp  = lane >> 2;
    const int tig  = lane & 3;
    const int m0   = blockIdx.x * BMF;

#pragma unroll
    for (int r = 0; r < 17; r++) {
        int q = tid + 512 * r;
        if (q < 8320) cp16(Bk + (uint32_t)q * 16, g_Whk + q);
    }
    cp_commit();

    for (int i = tid; i < BMF * DEG; i += 512) {
        int node = m0 + i / DEG;
        Ss[i] = (node < NN) ? src[node * DEG + i % DEG] : 0;
    }
    __syncthreads();

    float c[16];
#pragma unroll
    for (int i = 0; i < 16; i++) c[i] = 0.f;

    const int aRow = ((lane >> 3) & 1) * 8 + (lane & 7);
    const int aCol = (lane >> 4) * 16;
    const int bRow = aRow;
    const int bCol = ((lane >> 4) & 1) * 16;

#pragma unroll 1
    for (int t = 0; t < DEG; t++) {
        const uint32_t Ard = smb + SM_A + (uint32_t)((t & 1) * 17408);
        const uint32_t Awr = smb + SM_A + (uint32_t)(((t + 1) & 1) * 17408);

        float acc[2][8][4];
#pragma unroll
        for (int i = 0; i < 2; i++)
#pragma unroll
            for (int j = 0; j < 8; j++)
#pragma unroll
                for (int q = 0; q < 4; q++) acc[i][j][q] = 0.f;

        if (t > 0) {
#pragma unroll
            for (int kt = 0; kt < 8; kt++) {
                uint32_t bfr[4][4];
#pragma unroll
                for (int q = 0; q < 4; q++) {
                    uint32_t ba = Bk + (uint32_t)((kt * 16 + bRow) * 1040 +
                                   (w8 * 64 + q * 16) * 2 + bCol);
                    ldsm4t(bfr[q], ba);
                }
#pragma unroll
                for (int mt = 0; mt < 2; mt++) {
                    uint32_t aa = Ard + (uint32_t)((mh * 32 + mt * 16 + aRow) * 272 +
                                    kt * 32 + aCol);
                    uint32_t afh[4];
                    ldsm4(afh, aa);
#pragma unroll
                    for (int nt = 0; nt < 8; nt++) {
                        uint32_t b0 = bfr[nt >> 1][(nt & 1) * 2];
                        uint32_t b1 = bfr[nt >> 1][(nt & 1) * 2 + 1];
                        mma16816(acc[mt][nt], afh, b0, b1);
                    }
                }
            }
        }

        // pointwise LSTM update (gate order i,f,g,o)
#pragma unroll
        for (int mt = 0; mt < 2; mt++) {
#pragma unroll
            for (int rsel = 0; rsel < 2; rsel++) {
                const int ml   = mh * 32 + mt * 16 + grp + rsel * 8;
                const int node = m0 + ml;
                uint4 pf[2];
                {
                    const uint4* pb = g_Pp +
                        ((size_t)Ss[ml * DEG + t] * 64 + w8 * 8 + tig * 2);
                    pf[0] = pb[0];
                    pf[1] = pb[1];
                }
                const __half2* hp = (const __half2*)pf;
#pragma unroll
                for (int fp = 0; fp < 2; fp++) {
                    float2 PI = __half22float2(hp[0 + fp]);
                    float2 PF = __half22float2(hp[2 + fp]);
                    float2 PG = __half22float2(hp[4 + fp]);
                    float2 PO = __half22float2(hp[6 + fp]);
                    float hv[2];
#pragma unroll
                    for (int p = 0; p < 2; p++) {
                        float gi = p ? PI.y : PI.x;
                        float gf = p ? PF.y : PF.x;
                        float gg = p ? PG.y : PG.x;
                        float go = p ? PO.y : PO.x;
                        if (t > 0) {
                            gi += acc[mt][0 + fp][rsel * 2 + p];
                            gf += acc[mt][2 + fp][rsel * 2 + p];
                            gg += acc[mt][4 + fp][rsel * 2 + p];
                            go += acc[mt][6 + fp][rsel * 2 + p];
                        }
                        const int ci = (mt * 2 + rsel) * 4 + fp * 2 + p;
                        float cn = fsig(gf) * c[ci] + fsig(gi) * htanh(gg);
                        c[ci] = cn;
                        hv[p] = fsig(go) * htanh(cn);
                    }
                    uint32_t hipk = packh2(__float2half_rn(hv[0]),
                                           __float2half_rn(hv[1]));
                    const uint32_t aw = Awr + (uint32_t)(ml * 272 +
                                        (w8 * 16 + fp * 8 + 2 * tig) * 2);
                    asm volatile("st.shared.b32 [%0], %1;" :: "r"(aw), "r"(hipk));
                    if (t == DEG - 1 && node < NN) {
                        *((uint32_t*)((__half*)g_Hh + (size_t)node * 128 +
                                      w8 * 16 + fp * 8 + 2 * tig)) = hipk;
                    }
                }
            }
        }
        if (t == 0) cp_wait0();     // B resident before first mma (t=1)
        __syncthreads();            // A buffer handoff
    }
}

// ---------------------------------------------------------------------------
// out_mma: Out = h@Wl^T + x@Wr^T + bl.  BM=128, BN=FO, K=256 ([h|x]).
// ---------------------------------------------------------------------------
template<int FO, bool RELU>
__global__ __launch_bounds__(256)
void out_mma(const float* __restrict__ bl, float* __restrict__ OutF)
{
    constexpr int BROW = (FO == 128) ? 272 : 144;
    constexpr int BCH  = BROW / 16;
    constexpr int WN   = FO / 32;
    constexpr int MT   = (FO == 128) ? 4 : 2;

    extern __shared__ char sm[];
    const uint32_t smb = (uint32_t)__cvta_generic_to_shared(sm);
    const uint32_t Asm = smb, Bsm = smb + 69632;
    const int tid = threadIdx.x, wid = tid >> 5, lane = tid & 31;
    const int m0 = blockIdx.x * 128;

    for (int i = tid; i < 4096; i += 256) {
        int r = i >> 5, j = i & 31;
        int node = m0 + r; if (node >= NN) node = NN - 1;
        const char* srcp = (j < 16)
            ? (const char*)g_Hh + (size_t)node * 256 + j * 16
            : (const char*)g_Xh + (size_t)node * 256 + (j - 16) * 16;
        cp16(Asm + (uint32_t)(r * 544 + j * 16), srcp);
    }
    for (int i = tid; i < 256 * BCH; i += 256) {
        int r = i / BCH, j = i % BCH;
        cp16(Bsm + (uint32_t)(r * BROW + j * 16),
             (const char*)g_Wout + (size_t)r * BROW + j * 16);
    }
    cp_commit(); cp_wait0(); __syncthreads();

    const int wn = wid % WN, wm = wid / WN;
    const int aRow = ((lane >> 3) & 1) * 8 + (lane & 7);
    const int aCol = (lane >> 4) * 16;
    const int bRow = aRow;
    const int bCol = ((lane >> 4) & 1) * 16;

    float acc[MT][4][4];
#pragma unroll
    for (int a = 0; a < MT; a++)
#pragma unroll
        for (int b = 0; b < 4; b++)
#pragma unroll
            for (int q = 0; q < 4; q++) acc[a][b][q] = 0.f;

#pragma unroll
    for (int kt = 0; kt < 16; kt++) {
        uint32_t bfr[2][4];
#pragma unroll
        for (int q = 0; q < 2; q++)
            ldsm4t(bfr[q], Bsm + (uint32_t)((kt * 16 + bRow) * BROW +
                   (wn * 32 + q * 16) * 2 + bCol));
#pragma unroll
        for (int mt = 0; mt < MT; mt++) {
            uint32_t af[4];
            ldsm4(af, Asm + (uint32_t)((wm * MT * 16 + mt * 16 + aRow) * 544 +
                   kt * 32 + aCol));
#pragma unroll
            for (int nt = 0; nt < 4; nt++)
                mma16816(acc[mt][nt], af, bfr[nt >> 1][(nt & 1) * 2],
                         bfr[nt >> 1][(nt & 1) * 2 + 1]);
        }
    }

    const int grp = lane >> 2, tig = lane & 3;
#pragma unroll
    for (int nt = 0; nt < 4; nt++) {
        int n = wn * 32 + nt * 8 + 2 * tig;
        float b0 = bl[n], b1 = bl[n + 1];
#pragma unroll
        for (int mt = 0; mt < MT; mt++) {
            int r0 = m0 + wm * MT * 16 + mt * 16 + grp;
#pragma unroll
            for (int half = 0; half < 2; half++) {
                int r = r0 + half * 8;
                if (r >= NN) continue;
                float v0 = acc[mt][nt][half * 2 + 0] + b0;
                float v1 = acc[mt][nt][half * 2 + 1] + b1;
                if (RELU) {
                    v0 = fmaxf(v0, 0.f); v1 = fmaxf(v1, 0.f);
                    ((__half2*)g_Xh)[((size_t)r * 128 + n) >> 1] =
                        __floats2half2_rn(v0, v1);
                } else {
                    *(float2*)(OutF + (size_t)r * FO + n) = make_float2(v0, v1);
                }
            }
        }
    }
}

// ---------------------------------------------------------------------------
// host launcher
// ---------------------------------------------------------------------------
extern "C" void kernel_launch(void* const* d_in, const int* in_sizes, int n_in,
                              void* d_out, int out_size)
{
    (void)in_sizes; (void)n_in; (void)out_size;
    const float* x   = (const float*)d_in[0];
    const int*   src = (const int*)d_in[1];

    const float* P[21];
    for (int i = 0; i < 21; i++) P[i] = (const float*)d_in[2 + i];

    static bool attr_set = false;
    if (!attr_set) {
        cudaFuncSetAttribute(fused_lstm_mma,
                             cudaFuncAttributeMaxDynamicSharedMemorySize, SM_TOTAL);
        cudaFuncSetAttribute(pre_mma,
                             cudaFuncAttributeMaxDynamicSharedMemorySize, 69632);
        cudaFuncSetAttribute(out_mma<128, true>,
                             cudaFuncAttributeMaxDynamicSharedMemorySize, 139264);
        cudaFuncSetAttribute(out_mma<64, false>,
                             cudaFuncAttributeMaxDynamicSharedMemorySize, 106496);
        attr_set = true;
    }

    const dim3 blk(256);

    conv_x<<<(NN * 64 + 255) / 256, blk>>>(x);

    for (int l = 0; l < 3; l++) {
        const float* Wih = P[7 * l + 0];
        const float* Whh = P[7 * l + 1];
        const float* bih = P[7 * l + 2];
        const float* bhh = P[7 * l + 3];
        const float* Wl  = P[7 * l + 4];
        const float* bl  = P[7 * l + 5];
        const float* Wr  = P[7 * l + 6];

        conv_wrec<<<(2 * GDIM * FDIM + 255) / 256, blk>>>(Whh, Wih);
        if (l < 2)
            conv_wout<<<(128 * 256 + 255) / 256, blk>>>(Wl, Wr, 128, 136);
        else
            conv_wout<<<(64 * 256 + 255) / 256, blk>>>(Wl, Wr, 64, 72);

        pre_mma<<<dim3((NN + 127) / 128, 4), blk, 69632>>>(bih, bhh);
        fused_lstm_mma<<<(NN + BMF - 1) / BMF, dim3(512), SM_TOTAL>>>(src);

        if (l < 2)
            out_mma<128, true><<<(NN + 127) / 128, blk, 139264>>>(bl, nullptr);
        else
            out_mma<64, false><<<(NN + 127) / 128, blk, 106496>>>(bl, (float*)d_out);
    }
}

// round 14
// speedup vs baseline: 13.3391x; 1.0421x over previous
#include <cuda_runtime.h>
#include <cuda_fp16.h>
#include <cstdint>

// ---------------------------------------------------------------------------
// GraphSAGE with LSTM aggregation, 3 layers — round 13.
// All GEMMs on mma.sync.m16n8k16 (fp16 in, fp32 acc) via ldmatrix.
// Fused LSTM at the legacy-HMMA floor (512 MAC/cyc/SM). This round: pre_mma
// computes the full N=512 strip per CTA, stages the permuted P tile in SMEM,
// and writes it out fully coalesced (1KB contiguous per row).
// ---------------------------------------------------------------------------

#define NN   50000
#define DEG  16
#define FDIM 128
#define GDIM 512
#define BMF  64

__device__ uint4 g_Whk[8320];      // fused B: Whh fp16 [k][520] (gate-permuted n)
__device__ uint4 g_Wik[8320];      // pre  B: Wih fp16 [k][520] (original n)
__device__ uint4 g_Wout[4352];     // out  B: [Wl|Wr] fp16 [256][136 or 72]
__device__ uint4 g_Xh[800000];     // layer input fp16 [m][128]
__device__ uint4 g_Hh[800000];     // aggr h fp16 [m][128]
__device__ uint4 g_Pp[3200000];    // P fp16, permuted [m][512]

// fused SMEM (bytes): B 133120 | A 2 bufs x 17408 | src ids 4096
#define SM_B     0
#define SM_A     133120
#define SM_SS    167936
#define SM_TOTAL 172032

// pre SMEM: A 34816 | B 34816 | Ptile 128 x 1056 B = 135168  -> 204800 total
#define PRE_A    0
#define PRE_B    34816
#define PRE_PT   69632
#define PRE_TOT  204800
#define PT_ROW   1056

// ---- fast activations (HW tanh) --------------------------------------------
__device__ __forceinline__ float htanh(float x) {
    float y;
    asm("tanh.approx.f32 %0, %1;" : "=f"(y) : "f"(x));
    return y;
}
__device__ __forceinline__ float fsig(float x) {
    return fmaf(0.5f, htanh(0.5f * x), 0.5f);
}

// ---- cp.async --------------------------------------------------------------
__device__ __forceinline__ void cp16(uint32_t saddr, const void* gaddr) {
    asm volatile("cp.async.cg.shared.global [%0], [%1], 16;"
                 :: "r"(saddr), "l"(gaddr));
}
__device__ __forceinline__ void cp_commit() { asm volatile("cp.async.commit_group;"); }
__device__ __forceinline__ void cp_wait0()  { asm volatile("cp.async.wait_group 0;"); }

// ---- mma / ldmatrix --------------------------------------------------------
__device__ __forceinline__ void mma16816(float* d, const uint32_t* a,
                                         uint32_t b0, uint32_t b1) {
    asm volatile(
        "mma.sync.aligned.m16n8k16.row.col.f32.f16.f16.f32 "
        "{%0,%1,%2,%3},{%4,%5,%6,%7},{%8,%9},{%0,%1,%2,%3};"
        : "+f"(d[0]), "+f"(d[1]), "+f"(d[2]), "+f"(d[3])
        : "r"(a[0]), "r"(a[1]), "r"(a[2]), "r"(a[3]), "r"(b0), "r"(b1));
}
__device__ __forceinline__ void ldsm4(uint32_t* r, uint32_t a) {
    asm volatile("ldmatrix.sync.aligned.m8n8.x4.shared.b16 {%0,%1,%2,%3}, [%4];"
                 : "=r"(r[0]), "=r"(r[1]), "=r"(r[2]), "=r"(r[3]) : "r"(a));
}
__device__ __forceinline__ void ldsm4t(uint32_t* r, uint32_t a) {
    asm volatile("ldmatrix.sync.aligned.m8n8.x4.trans.shared.b16 {%0,%1,%2,%3}, [%4];"
                 : "=r"(r[0]), "=r"(r[1]), "=r"(r[2]), "=r"(r[3]) : "r"(a));
}
__device__ __forceinline__ uint32_t packh2(__half a, __half b) {
    return ((uint32_t)__half_as_ushort(b) << 16) | (uint32_t)__half_as_ushort(a);
}

// ---------------------------------------------------------------------------
// conversion kernels
// ---------------------------------------------------------------------------
__global__ void conv_x(const float* __restrict__ x)
{
    int i = blockIdx.x * blockDim.x + threadIdx.x;
    if (i >= NN * 64) return;
    float2 v = ((const float2*)x)[i];
    ((__half2*)g_Xh)[i] = __floats2half2_rn(v.x, v.y);
}

// all per-layer weights in one launch
__global__ void conv_weights(const float* __restrict__ Whh,
                             const float* __restrict__ Wih,
                             const float* __restrict__ Wl,
                             const float* __restrict__ Wr, int FO, int BPAD)
{
    int idx = blockIdx.x * blockDim.x + threadIdx.x;
    if (idx < GDIM * FDIM) {
        int r = idx >> 7, k = idx & 127;
        int g = r >> 7, w = (r >> 4) & 7, f = r & 15;
        int n = w * 64 + g * 16 + f;
        ((__half*)g_Whk)[k * 520 + n] = __float2half_rn(Whh[idx]);
    } else if (idx < 2 * GDIM * FDIM) {
        int j = idx - GDIM * FDIM;
        int n = j >> 7, k = j & 127;
        ((__half*)g_Wik)[k * 520 + n] = __float2half_rn(Wih[j]);
    } else if (idx < 2 * GDIM * FDIM + FO * 256) {
        int j = idx - 2 * GDIM * FDIM;
        int n = j >> 8, k = j & 255;
        float v = (k < 128) ? Wl[n * 128 + k] : Wr[n * 128 + (k - 128)];
        ((__half*)g_Wout)[k * BPAD + n] = __float2half_rn(v);
    }
}

// ---------------------------------------------------------------------------
// pre_mma: P = X @ Wih^T + (bih+bhh), fp16, gather-permuted, SMEM-staged.
// Grid 391, block 256. Per CTA: 128 rows x full N=512 (y-loop over 4 slices),
// A loaded once; P tile staged in SMEM then written coalesced (1KB/row).
// ---------------------------------------------------------------------------
__global__ __launch_bounds__(256)
void pre_mma(const float* __restrict__ bih, const float* __restrict__ bhh)
{
    extern __shared__ char sm[];
    const uint32_t smb = (uint32_t)__cvta_generic_to_shared(sm);
    const uint32_t Asm = smb + PRE_A, Bsm = smb + PRE_B, Pts = smb + PRE_PT;
    const int tid = threadIdx.x, wid = tid >> 5, lane = tid & 31;
    const int m0 = blockIdx.x * 128;

    // stage A (128 rows x 256 B) once
    for (int i = tid; i < 2048; i += 256) {
        int r = i >> 4, j = i & 15;
        int node = m0 + r; if (node >= NN) node = NN - 1;
        cp16(Asm + (uint32_t)(r * 272 + j * 16),
             (const char*)g_Xh + (size_t)node * 256 + j * 16);
    }
    // stage B slice y=0
    for (int i = tid; i < 2048; i += 256) {
        int r = i >> 4, j = i & 15;
        cp16(Bsm + (uint32_t)(r * 272 + j * 16),
             (const char*)g_Wik + (size_t)r * 1040 + j * 16);
    }
    cp_commit(); cp_wait0(); __syncthreads();

    const int wm = wid >> 2, wn = wid & 3;
    const int aRow = ((lane >> 3) & 1) * 8 + (lane & 7);
    const int aCol = (lane >> 4) * 16;
    const int bRow = aRow;
    const int bCol = ((lane >> 4) & 1) * 16;
    const int grp = lane >> 2, tig = lane & 3;

#pragma unroll 1
    for (int y = 0; y < 4; y++) {
        float acc[4][4][4];
#pragma unroll
        for (int a = 0; a < 4; a++)
#pragma unroll
            for (int b = 0; b < 4; b++)
#pragma unroll
                for (int q = 0; q < 4; q++) acc[a][b][q] = 0.f;

#pragma unroll
        for (int kt = 0; kt < 8; kt++) {
            uint32_t bfr[2][4];
#pragma unroll
            for (int q = 0; q < 2; q++)
                ldsm4t(bfr[q], Bsm + (uint32_t)((kt * 16 + bRow) * 272 +
                       (wn * 32 + q * 16) * 2 + bCol));
#pragma unroll
            for (int mt = 0; mt < 4; mt++) {
                uint32_t af[4];
                ldsm4(af, Asm + (uint32_t)((wm * 64 + mt * 16 + aRow) * 272 +
                       kt * 32 + aCol));
#pragma unroll
                for (int nt = 0; nt < 4; nt++)
                    mma16816(acc[mt][nt], af, bfr[nt >> 1][(nt & 1) * 2],
                             bfr[nt >> 1][(nt & 1) * 2 + 1]);
            }
        }

        // epilogue: bias + permuted store into SMEM P tile
#pragma unroll
        for (int nt = 0; nt < 4; nt++) {
            int n = y * 128 + wn * 32 + nt * 8 + 2 * tig;
            float b0 = bih[n] + bhh[n];
            float b1 = bih[n + 1] + bhh[n + 1];
            int w = (n >> 4) & 7, f = n & 15;
            int dsti = w * 64 + ((f >> 1) & 3) * 16 + y * 4 + (f >> 3) * 2;
#pragma unroll
            for (int mt = 0; mt < 4; mt++) {
                int r0 = wm * 64 + mt * 16 + grp;
                uint32_t a0 = Pts + (uint32_t)(r0 * PT_ROW + dsti * 2);
                uint32_t v0 = packh2(__float2half_rn(acc[mt][nt][0] + b0),
                                     __float2half_rn(acc[mt][nt][1] + b1));
                asm volatile("st.shared.b32 [%0], %1;" :: "r"(a0), "r"(v0));
                uint32_t a1 = a0 + 8 * PT_ROW;
                uint32_t v1 = packh2(__float2half_rn(acc[mt][nt][2] + b0),
                                     __float2half_rn(acc[mt][nt][3] + b1));
                asm volatile("st.shared.b32 [%0], %1;" :: "r"(a1), "r"(v1));
            }
        }

        if (y < 3) {
            __syncthreads();                    // all warps done with B(y)
            for (int i = tid; i < 2048; i += 256) {
                int r = i >> 4, j = i & 15;
                cp16(Bsm + (uint32_t)(r * 272 + j * 16),
                     (const char*)g_Wik + (size_t)r * 1040 +
                     (y + 1) * 256 + j * 16);
            }
            cp_commit(); cp_wait0(); __syncthreads();
        }
    }
    __syncthreads();

    // coalesced writeout: 1KB contiguous per row
    for (int q = tid; q < 8192; q += 256) {
        int row = q >> 6, off = q & 63;
        if (m0 + row < NN) {
            uint4 v;
            uint32_t sa = Pts + (uint32_t)(row * PT_ROW + off * 16);
            asm volatile("ld.shared.v4.u32 {%0,%1,%2,%3}, [%4];"
                         : "=r"(v.x), "=r"(v.y), "=r"(v.z), "=r"(v.w) : "r"(sa));
            g_Pp[(size_t)(m0 + row) * 64 + off] = v;
        }
    }
}

// ---------------------------------------------------------------------------
// Fused LSTM on mma.sync + ldmatrix. 782 blocks x 512 threads, 1 CTA/SM.
// (unchanged from round 12 — at the legacy tensor-pipe floor)
// ---------------------------------------------------------------------------
__global__ __launch_bounds__(512, 1)
void fused_lstm_mma(const int* __restrict__ src)
{
    extern __shared__ char sm[];
    const uint32_t smb = (uint32_t)__cvta_generic_to_shared(sm);
    const uint32_t Bk  = smb + SM_B;
    int* Ss = (int*)(sm + SM_SS);

    const int tid  = threadIdx.x;
    const int wid  = tid >> 5;
    const int w8   = wid >> 1;
    const int mh   = wid & 1;
    const int lane = tid & 31;
    const int grp  = lane >> 2;
    const int tig  = lane & 3;
    const int m0   = blockIdx.x * BMF;

#pragma unroll
    for (int r = 0; r < 17; r++) {
        int q = tid + 512 * r;
        if (q < 8320) cp16(Bk + (uint32_t)q * 16, g_Whk + q);
    }
    cp_commit();

    for (int i = tid; i < BMF * DEG; i += 512) {
        int node = m0 + i / DEG;
        Ss[i] = (node < NN) ? src[node * DEG + i % DEG] : 0;
    }
    __syncthreads();

    float c[16];
#pragma unroll
    for (int i = 0; i < 16; i++) c[i] = 0.f;

    const int aRow = ((lane >> 3) & 1) * 8 + (lane & 7);
    const int aCol = (lane >> 4) * 16;
    const int bRow = aRow;
    const int bCol = ((lane >> 4) & 1) * 16;

#pragma unroll 1
    for (int t = 0; t < DEG; t++) {
        const uint32_t Ard = smb + SM_A + (uint32_t)((t & 1) * 17408);
        const uint32_t Awr = smb + SM_A + (uint32_t)(((t + 1) & 1) * 17408);

        float acc[2][8][4];
#pragma unroll
        for (int i = 0; i < 2; i++)
#pragma unroll
            for (int j = 0; j < 8; j++)
#pragma unroll
                for (int q = 0; q < 4; q++) acc[i][j][q] = 0.f;

        if (t > 0) {
#pragma unroll
            for (int kt = 0; kt < 8; kt++) {
                uint32_t bfr[4][4];
#pragma unroll
                for (int q = 0; q < 4; q++) {
                    uint32_t ba = Bk + (uint32_t)((kt * 16 + bRow) * 1040 +
                                   (w8 * 64 + q * 16) * 2 + bCol);
                    ldsm4t(bfr[q], ba);
                }
#pragma unroll
                for (int mt = 0; mt < 2; mt++) {
                    uint32_t aa = Ard + (uint32_t)((mh * 32 + mt * 16 + aRow) * 272 +
                                    kt * 32 + aCol);
                    uint32_t afh[4];
                    ldsm4(afh, aa);
#pragma unroll
                    for (int nt = 0; nt < 8; nt++) {
                        uint32_t b0 = bfr[nt >> 1][(nt & 1) * 2];
                        uint32_t b1 = bfr[nt >> 1][(nt & 1) * 2 + 1];
                        mma16816(acc[mt][nt], afh, b0, b1);
                    }
                }
            }
        }

        // pointwise LSTM update (gate order i,f,g,o)
#pragma unroll
        for (int mt = 0; mt < 2; mt++) {
#pragma unroll
            for (int rsel = 0; rsel < 2; rsel++) {
                const int ml   = mh * 32 + mt * 16 + grp + rsel * 8;
                const int node = m0 + ml;
                uint4 pf[2];
                {
                    const uint4* pb = g_Pp +
                        ((size_t)Ss[ml * DEG + t] * 64 + w8 * 8 + tig * 2);
                    pf[0] = pb[0];
                    pf[1] = pb[1];
                }
                const __half2* hp = (const __half2*)pf;
#pragma unroll
                for (int fp = 0; fp < 2; fp++) {
                    float2 PI = __half22float2(hp[0 + fp]);
                    float2 PF = __half22float2(hp[2 + fp]);
                    float2 PG = __half22float2(hp[4 + fp]);
                    float2 PO = __half22float2(hp[6 + fp]);
                    float hv[2];
#pragma unroll
                    for (int p = 0; p < 2; p++) {
                        float gi = p ? PI.y : PI.x;
                        float gf = p ? PF.y : PF.x;
                        float gg = p ? PG.y : PG.x;
                        float go = p ? PO.y : PO.x;
                        if (t > 0) {
                            gi += acc[mt][0 + fp][rsel * 2 + p];
                            gf += acc[mt][2 + fp][rsel * 2 + p];
                            gg += acc[mt][4 + fp][rsel * 2 + p];
                            go += acc[mt][6 + fp][rsel * 2 + p];
                        }
                        const int ci = (mt * 2 + rsel) * 4 + fp * 2 + p;
                        float cn = fsig(gf) * c[ci] + fsig(gi) * htanh(gg);
                        c[ci] = cn;
                        hv[p] = fsig(go) * htanh(cn);
                    }
                    uint32_t hipk = packh2(__float2half_rn(hv[0]),
                                           __float2half_rn(hv[1]));
                    const uint32_t aw = Awr + (uint32_t)(ml * 272 +
                                        (w8 * 16 + fp * 8 + 2 * tig) * 2);
                    asm volatile("st.shared.b32 [%0], %1;" :: "r"(aw), "r"(hipk));
                    if (t == DEG - 1 && node < NN) {
                        *((uint32_t*)((__half*)g_Hh + (size_t)node * 128 +
                                      w8 * 16 + fp * 8 + 2 * tig)) = hipk;
                    }
                }
            }
        }
        if (t == 0) cp_wait0();
        __syncthreads();
    }
}

// ---------------------------------------------------------------------------
// out_mma: Out = h@Wl^T + x@Wr^T + bl.  BM=128, BN=FO, K=256 ([h|x]).
// ---------------------------------------------------------------------------
template<int FO, bool RELU>
__global__ __launch_bounds__(256)
void out_mma(const float* __restrict__ bl, float* __restrict__ OutF)
{
    constexpr int BROW = (FO == 128) ? 272 : 144;
    constexpr int BCH  = BROW / 16;
    constexpr int WN   = FO / 32;
    constexpr int MT   = (FO == 128) ? 4 : 2;

    extern __shared__ char sm[];
    const uint32_t smb = (uint32_t)__cvta_generic_to_shared(sm);
    const uint32_t Asm = smb, Bsm = smb + 69632;
    const int tid = threadIdx.x, wid = tid >> 5, lane = tid & 31;
    const int m0 = blockIdx.x * 128;

    for (int i = tid; i < 4096; i += 256) {
        int r = i >> 5, j = i & 31;
        int node = m0 + r; if (node >= NN) node = NN - 1;
        const char* srcp = (j < 16)
            ? (const char*)g_Hh + (size_t)node * 256 + j * 16
            : (const char*)g_Xh + (size_t)node * 256 + (j - 16) * 16;
        cp16(Asm + (uint32_t)(r * 544 + j * 16), srcp);
    }
    for (int i = tid; i < 256 * BCH; i += 256) {
        int r = i / BCH, j = i % BCH;
        cp16(Bsm + (uint32_t)(r * BROW + j * 16),
             (const char*)g_Wout + (size_t)r * BROW + j * 16);
    }
    cp_commit(); cp_wait0(); __syncthreads();

    const int wn = wid % WN, wm = wid / WN;
    const int aRow = ((lane >> 3) & 1) * 8 + (lane & 7);
    const int aCol = (lane >> 4) * 16;
    const int bRow = aRow;
    const int bCol = ((lane >> 4) & 1) * 16;

    float acc[MT][4][4];
#pragma unroll
    for (int a = 0; a < MT; a++)
#pragma unroll
        for (int b = 0; b < 4; b++)
#pragma unroll
            for (int q = 0; q < 4; q++) acc[a][b][q] = 0.f;

#pragma unroll
    for (int kt = 0; kt < 16; kt++) {
        uint32_t bfr[2][4];
#pragma unroll
        for (int q = 0; q < 2; q++)
            ldsm4t(bfr[q], Bsm + (uint32_t)((kt * 16 + bRow) * BROW +
                   (wn * 32 + q * 16) * 2 + bCol));
#pragma unroll
        for (int mt = 0; mt < MT; mt++) {
            uint32_t af[4];
            ldsm4(af, Asm + (uint32_t)((wm * MT * 16 + mt * 16 + aRow) * 544 +
                   kt * 32 + aCol));
#pragma unroll
            for (int nt = 0; nt < 4; nt++)
                mma16816(acc[mt][nt], af, bfr[nt >> 1][(nt & 1) * 2],
                         bfr[nt >> 1][(nt & 1) * 2 + 1]);
        }
    }

    const int grp = lane >> 2, tig = lane & 3;
#pragma unroll
    for (int nt = 0; nt < 4; nt++) {
        int n = wn * 32 + nt * 8 + 2 * tig;
        float b0 = bl[n], b1 = bl[n + 1];
#pragma unroll
        for (int mt = 0; mt < MT; mt++) {
            int r0 = m0 + wm * MT * 16 + mt * 16 + grp;
#pragma unroll
            for (int half = 0; half < 2; half++) {
                int r = r0 + half * 8;
                if (r >= NN) continue;
                float v0 = acc[mt][nt][half * 2 + 0] + b0;
                float v1 = acc[mt][nt][half * 2 + 1] + b1;
                if (RELU) {
                    v0 = fmaxf(v0, 0.f); v1 = fmaxf(v1, 0.f);
                    ((__half2*)g_Xh)[((size_t)r * 128 + n) >> 1] =
                        __floats2half2_rn(v0, v1);
                } else {
                    *(float2*)(OutF + (size_t)r * FO + n) = make_float2(v0, v1);
                }
            }
        }
    }
}

// ---------------------------------------------------------------------------
// host launcher
// ---------------------------------------------------------------------------
extern "C" void kernel_launch(void* const* d_in, const int* in_sizes, int n_in,
                              void* d_out, int out_size)
{
    (void)in_sizes; (void)n_in; (void)out_size;
    const float* x   = (const float*)d_in[0];
    const int*   src = (const int*)d_in[1];

    const float* P[21];
    for (int i = 0; i < 21; i++) P[i] = (const float*)d_in[2 + i];

    static bool attr_set = false;
    if (!attr_set) {
        cudaFuncSetAttribute(fused_lstm_mma,
                             cudaFuncAttributeMaxDynamicSharedMemorySize, SM_TOTAL);
        cudaFuncSetAttribute(pre_mma,
                             cudaFuncAttributeMaxDynamicSharedMemorySize, PRE_TOT);
        cudaFuncSetAttribute(out_mma<128, true>,
                             cudaFuncAttributeMaxDynamicSharedMemorySize, 139264);
        cudaFuncSetAttribute(out_mma<64, false>,
                             cudaFuncAttributeMaxDynamicSharedMemorySize, 106496);
        attr_set = true;
    }

    const dim3 blk(256);

    conv_x<<<(NN * 64 + 255) / 256, blk>>>(x);

    for (int l = 0; l < 3; l++) {
        const float* Wih = P[7 * l + 0];
        const float* Whh = P[7 * l + 1];
        const float* bih = P[7 * l + 2];
        const float* bhh = P[7 * l + 3];
        const float* Wl  = P[7 * l + 4];
        const float* bl  = P[7 * l + 5];
        const float* Wr  = P[7 * l + 6];

        const int FO   = (l < 2) ? 128 : 64;
        const int BPAD = (l < 2) ? 136 : 72;
        const int convN = 2 * GDIM * FDIM + FO * 256;
        conv_weights<<<(convN + 255) / 256, blk>>>(Whh, Wih, Wl, Wr, FO, BPAD);

        pre_mma<<<(NN + 127) / 128, blk, PRE_TOT>>>(bih, bhh);
        fused_lstm_mma<<<(NN + BMF - 1) / BMF, dim3(512), SM_TOTAL>>>(src);

        if (l < 2)
            out_mma<128, true><<<(NN + 127) / 128, blk, 139264>>>(bl, nullptr);
        else
            out_mma<64, false><<<(NN + 127) / 128, blk, 106496>>>(bl, (float*)d_out);
    }
}

// round 15
// speedup vs baseline: 13.7635x; 1.0318x over previous
#include <cuda_runtime.h>
#include <cuda_fp16.h>
#include <cstdint>

// ---------------------------------------------------------------------------
// GraphSAGE with LSTM aggregation, 3 layers — round 14.
// Fused LSTM restructured for pipe overlap: 256 threads (8 warps, warp = one
// 64-col N-block over all 64 rows), per step: mma(rows 0-31) -> mma(rows
// 32-63) interleaved with pointwise(rows 0-31) -> pointwise(rows 32-63),
// with a distance-2 P-gather register pipeline. Numerics bit-identical to
// rounds 11-13 (rel_err 0.000534982).
// ---------------------------------------------------------------------------

#define NN   50000
#define DEG  16
#define FDIM 128
#define GDIM 512
#define BMF  64

__device__ uint4 g_Whk[8320];      // fused B: Whh fp16 [k][520] (gate-permuted n)
__device__ uint4 g_Wik[8320];      // pre  B: Wih fp16 [k][520] (original n)
__device__ uint4 g_Wout[4352];     // out  B: [Wl|Wr] fp16 [256][136 or 72]
__device__ uint4 g_Xh[800000];     // layer input fp16 [m][128]
__device__ uint4 g_Hh[800000];     // aggr h fp16 [m][128]
__device__ uint4 g_Pp[3200000];    // P fp16, permuted [m][512]

// fused SMEM (bytes): B 133120 | A 2 bufs x 17408 | src ids 4096
#define SM_B     0
#define SM_A     133120
#define SM_SS    167936
#define SM_TOTAL 172032

// pre SMEM: A 34816 | B 34816 | Ptile 128 x 1056 B = 135168  -> 204800 total
#define PRE_A    0
#define PRE_B    34816
#define PRE_PT   69632
#define PRE_TOT  204800
#define PT_ROW   1056

// ---- fast activations (HW tanh) --------------------------------------------
__device__ __forceinline__ float htanh(float x) {
    float y;
    asm("tanh.approx.f32 %0, %1;" : "=f"(y) : "f"(x));
    return y;
}
__device__ __forceinline__ float fsig(float x) {
    return fmaf(0.5f, htanh(0.5f * x), 0.5f);
}

// ---- cp.async --------------------------------------------------------------
__device__ __forceinline__ void cp16(uint32_t saddr, const void* gaddr) {
    asm volatile("cp.async.cg.shared.global [%0], [%1], 16;"
                 :: "r"(saddr), "l"(gaddr));
}
__device__ __forceinline__ void cp_commit() { asm volatile("cp.async.commit_group;"); }
__device__ __forceinline__ void cp_wait0()  { asm volatile("cp.async.wait_group 0;"); }

// ---- mma / ldmatrix --------------------------------------------------------
__device__ __forceinline__ void mma16816(float* d, const uint32_t* a,
                                         uint32_t b0, uint32_t b1) {
    asm volatile(
        "mma.sync.aligned.m16n8k16.row.col.f32.f16.f16.f32 "
        "{%0,%1,%2,%3},{%4,%5,%6,%7},{%8,%9},{%0,%1,%2,%3};"
        : "+f"(d[0]), "+f"(d[1]), "+f"(d[2]), "+f"(d[3])
        : "r"(a[0]), "r"(a[1]), "r"(a[2]), "r"(a[3]), "r"(b0), "r"(b1));
}
__device__ __forceinline__ void ldsm4(uint32_t* r, uint32_t a) {
    asm volatile("ldmatrix.sync.aligned.m8n8.x4.shared.b16 {%0,%1,%2,%3}, [%4];"
                 : "=r"(r[0]), "=r"(r[1]), "=r"(r[2]), "=r"(r[3]) : "r"(a));
}
__device__ __forceinline__ void ldsm4t(uint32_t* r, uint32_t a) {
    asm volatile("ldmatrix.sync.aligned.m8n8.x4.trans.shared.b16 {%0,%1,%2,%3}, [%4];"
                 : "=r"(r[0]), "=r"(r[1]), "=r"(r[2]), "=r"(r[3]) : "r"(a));
}
__device__ __forceinline__ uint32_t packh2(__half a, __half b) {
    return ((uint32_t)__half_as_ushort(b) << 16) | (uint32_t)__half_as_ushort(a);
}

// ---------------------------------------------------------------------------
// conversion kernels
// ---------------------------------------------------------------------------
__global__ void conv_x(const float* __restrict__ x)
{
    int i = blockIdx.x * blockDim.x + threadIdx.x;
    if (i >= NN * 64) return;
    float2 v = ((const float2*)x)[i];
    ((__half2*)g_Xh)[i] = __floats2half2_rn(v.x, v.y);
}

__global__ void conv_weights(const float* __restrict__ Whh,
                             const float* __restrict__ Wih,
                             const float* __restrict__ Wl,
                             const float* __restrict__ Wr, int FO, int BPAD)
{
    int idx = blockIdx.x * blockDim.x + threadIdx.x;
    if (idx < GDIM * FDIM) {
        int r = idx >> 7, k = idx & 127;
        int g = r >> 7, w = (r >> 4) & 7, f = r & 15;
        int n = w * 64 + g * 16 + f;
        ((__half*)g_Whk)[k * 520 + n] = __float2half_rn(Whh[idx]);
    } else if (idx < 2 * GDIM * FDIM) {
        int j = idx - GDIM * FDIM;
        int n = j >> 7, k = j & 127;
        ((__half*)g_Wik)[k * 520 + n] = __float2half_rn(Wih[j]);
    } else if (idx < 2 * GDIM * FDIM + FO * 256) {
        int j = idx - 2 * GDIM * FDIM;
        int n = j >> 8, k = j & 255;
        float v = (k < 128) ? Wl[n * 128 + k] : Wr[n * 128 + (k - 128)];
        ((__half*)g_Wout)[k * BPAD + n] = __float2half_rn(v);
    }
}

// ---------------------------------------------------------------------------
// pre_mma (unchanged from round 13)
// ---------------------------------------------------------------------------
__global__ __launch_bounds__(256)
void pre_mma(const float* __restrict__ bih, const float* __restrict__ bhh)
{
    extern __shared__ char sm[];
    const uint32_t smb = (uint32_t)__cvta_generic_to_shared(sm);
    const uint32_t Asm = smb + PRE_A, Bsm = smb + PRE_B, Pts = smb + PRE_PT;
    const int tid = threadIdx.x, wid = tid >> 5, lane = tid & 31;
    const int m0 = blockIdx.x * 128;

    for (int i = tid; i < 2048; i += 256) {
        int r = i >> 4, j = i & 15;
        int node = m0 + r; if (node >= NN) node = NN - 1;
        cp16(Asm + (uint32_t)(r * 272 + j * 16),
             (const char*)g_Xh + (size_t)node * 256 + j * 16);
    }
    for (int i = tid; i < 2048; i += 256) {
        int r = i >> 4, j = i & 15;
        cp16(Bsm + (uint32_t)(r * 272 + j * 16),
             (const char*)g_Wik + (size_t)r * 1040 + j * 16);
    }
    cp_commit(); cp_wait0(); __syncthreads();

    const int wm = wid >> 2, wn = wid & 3;
    const int aRow = ((lane >> 3) & 1) * 8 + (lane & 7);
    const int aCol = (lane >> 4) * 16;
    const int bRow = aRow;
    const int bCol = ((lane >> 4) & 1) * 16;
    const int grp = lane >> 2, tig = lane & 3;

#pragma unroll 1
    for (int y = 0; y < 4; y++) {
        float acc[4][4][4];
#pragma unroll
        for (int a = 0; a < 4; a++)
#pragma unroll
            for (int b = 0; b < 4; b++)
#pragma unroll
                for (int q = 0; q < 4; q++) acc[a][b][q] = 0.f;

#pragma unroll
        for (int kt = 0; kt < 8; kt++) {
            uint32_t bfr[2][4];
#pragma unroll
            for (int q = 0; q < 2; q++)
                ldsm4t(bfr[q], Bsm + (uint32_t)((kt * 16 + bRow) * 272 +
                       (wn * 32 + q * 16) * 2 + bCol));
#pragma unroll
            for (int mt = 0; mt < 4; mt++) {
                uint32_t af[4];
                ldsm4(af, Asm + (uint32_t)((wm * 64 + mt * 16 + aRow) * 272 +
                       kt * 32 + aCol));
#pragma unroll
                for (int nt = 0; nt < 4; nt++)
                    mma16816(acc[mt][nt], af, bfr[nt >> 1][(nt & 1) * 2],
                             bfr[nt >> 1][(nt & 1) * 2 + 1]);
            }
        }

#pragma unroll
        for (int nt = 0; nt < 4; nt++) {
            int n = y * 128 + wn * 32 + nt * 8 + 2 * tig;
            float b0 = bih[n] + bhh[n];
            float b1 = bih[n + 1] + bhh[n + 1];
            int w = (n >> 4) & 7, f = n & 15;
            int dsti = w * 64 + ((f >> 1) & 3) * 16 + y * 4 + (f >> 3) * 2;
#pragma unroll
            for (int mt = 0; mt < 4; mt++) {
                int r0 = wm * 64 + mt * 16 + grp;
                uint32_t a0 = Pts + (uint32_t)(r0 * PT_ROW + dsti * 2);
                uint32_t v0 = packh2(__float2half_rn(acc[mt][nt][0] + b0),
                                     __float2half_rn(acc[mt][nt][1] + b1));
                asm volatile("st.shared.b32 [%0], %1;" :: "r"(a0), "r"(v0));
                uint32_t a1 = a0 + 8 * PT_ROW;
                uint32_t v1 = packh2(__float2half_rn(acc[mt][nt][2] + b0),
                                     __float2half_rn(acc[mt][nt][3] + b1));
                asm volatile("st.shared.b32 [%0], %1;" :: "r"(a1), "r"(v1));
            }
        }

        if (y < 3) {
            __syncthreads();
            for (int i = tid; i < 2048; i += 256) {
                int r = i >> 4, j = i & 15;
                cp16(Bsm + (uint32_t)(r * 272 + j * 16),
                     (const char*)g_Wik + (size_t)r * 1040 +
                     (y + 1) * 256 + j * 16);
            }
            cp_commit(); cp_wait0(); __syncthreads();
        }
    }
    __syncthreads();

    for (int q = tid; q < 8192; q += 256) {
        int row = q >> 6, off = q & 63;
        if (m0 + row < NN) {
            uint4 v;
            uint32_t sa = Pts + (uint32_t)(row * PT_ROW + off * 16);
            asm volatile("ld.shared.v4.u32 {%0,%1,%2,%3}, [%4];"
                         : "=r"(v.x), "=r"(v.y), "=r"(v.z), "=r"(v.w) : "r"(sa));
            g_Pp[(size_t)(m0 + row) * 64 + off] = v;
        }
    }
}

// ---------------------------------------------------------------------------
// pointwise LSTM row update (gate order i,f,g,o). WACC: add mma D term.
// cc = c + j*4 (4 cells: fp x p). Bit-identical math to rounds 11-13.
// ---------------------------------------------------------------------------
template<bool WACC>
__device__ __forceinline__ void pw_row(const float (*am)[4], int rsel,
                                       float* cc, uint4 cur0, uint4 cur1,
                                       uint32_t aw, uint32_t* ghp)
{
    uint4 pfv[2]; pfv[0] = cur0; pfv[1] = cur1;
    const __half2* hp = (const __half2*)pfv;
#pragma unroll
    for (int fp = 0; fp < 2; fp++) {
        float2 PI = __half22float2(hp[0 + fp]);
        float2 PF = __half22float2(hp[2 + fp]);
        float2 PG = __half22float2(hp[4 + fp]);
        float2 PO = __half22float2(hp[6 + fp]);
        float hv[2];
#pragma unroll
        for (int p = 0; p < 2; p++) {
            float gi = p ? PI.y : PI.x;
            float gf = p ? PF.y : PF.x;
            float gg = p ? PG.y : PG.x;
            float go = p ? PO.y : PO.x;
            if (WACC) {
                gi += am[0 + fp][rsel * 2 + p];
                gf += am[2 + fp][rsel * 2 + p];
                gg += am[4 + fp][rsel * 2 + p];
                go += am[6 + fp][rsel * 2 + p];
            }
            float cn = fsig(gf) * cc[fp * 2 + p] + fsig(gi) * htanh(gg);
            cc[fp * 2 + p] = cn;
            hv[p] = fsig(go) * htanh(cn);
        }
        uint32_t hipk = packh2(__float2half_rn(hv[0]), __float2half_rn(hv[1]));
        asm volatile("st.shared.b32 [%0], %1;" :: "r"(aw + fp * 16), "r"(hipk));
        if (ghp) ghp[fp * 4] = hipk;
    }
}

// ---------------------------------------------------------------------------
// Fused LSTM, pipelined. 782 blocks x 256 threads, 1 CTA/SM.
// Warp w (0..7) owns permuted cols [w*64, w*64+64) over all 64 rows.
// Row-iter j (0..7): mt=j>>1, rsel=j&1 -> row = mt*16 + grp + rsel*8.
// Step: ph1 mma(mt0,1) | ph2 mma(mt2,3) + pw(j=0..3) | ph3 pw(j=4..7).
// ---------------------------------------------------------------------------
__global__ __launch_bounds__(256, 1)
void fused_lstm_mma(const int* __restrict__ src)
{
    extern __shared__ char sm[];
    const uint32_t smb = (uint32_t)__cvta_generic_to_shared(sm);
    const uint32_t Bk  = smb + SM_B;
    int* Ss = (int*)(sm + SM_SS);

    const int tid  = threadIdx.x;
    const int wid  = tid >> 5;
    const int lane = tid & 31;
    const int grp  = lane >> 2;
    const int tig  = lane & 3;
    const int m0   = blockIdx.x * BMF;

#pragma unroll
    for (int r = 0; r < 33; r++) {
        int q = tid + 256 * r;
        if (q < 8320) cp16(Bk + (uint32_t)q * 16, g_Whk + q);
    }
    cp_commit();

    for (int i = tid; i < BMF * DEG; i += 256) {
        int node = m0 + i / DEG;
        Ss[i] = (node < NN) ? src[node * DEG + i % DEG] : 0;
    }
    __syncthreads();

    float c[32];
#pragma unroll
    for (int i = 0; i < 32; i++) c[i] = 0.f;

    const int aRow = ((lane >> 3) & 1) * 8 + (lane & 7);
    const int aCol = (lane >> 4) * 16;
    const int bRow = aRow;
    const int bCol = ((lane >> 4) & 1) * 16;

#define PREF(j, slot) do {                                                    \
        int _ml = ((j) >> 1) * 16 + grp + ((j) & 1) * 8;                      \
        const uint4* _pb = g_Pp +                                             \
            ((size_t)Ss[_ml * DEG + t] * 64 + wid * 8 + tig * 2);             \
        pf[slot][0] = _pb[0]; pf[slot][1] = _pb[1];                           \
    } while (0)

#define ROWARGS(j)                                                            \
        const int ml = ((j) >> 1) * 16 + grp + ((j) & 1) * 8;                 \
        const int node = m0 + ml;                                             \
        uint32_t* ghp = (t == DEG - 1 && node < NN)                           \
            ? (uint32_t*)((__half*)g_Hh + (size_t)node * 128 +                \
                          wid * 16 + 2 * tig) : nullptr;                      \
        const uint32_t aw = Awr + (uint32_t)(ml * 272 +                       \
                          (wid * 16 + 2 * tig) * 2);

#pragma unroll 1
    for (int t = 0; t < DEG; t++) {
        const uint32_t Ard = smb + SM_A + (uint32_t)((t & 1) * 17408);
        const uint32_t Awr = smb + SM_A + (uint32_t)(((t + 1) & 1) * 17408);

        uint4 pf[2][2];
        PREF(0, 0);

        if (t > 0) {
            float acc0[2][8][4], acc1[2][8][4];
#pragma unroll
            for (int i = 0; i < 2; i++)
#pragma unroll
                for (int j = 0; j < 8; j++)
#pragma unroll
                    for (int q = 0; q < 4; q++) {
                        acc0[i][j][q] = 0.f; acc1[i][j][q] = 0.f;
                    }

            // ph1: mma rows 0-31 (mt 0,1)
#pragma unroll
            for (int kt = 0; kt < 8; kt++) {
                uint32_t bfr[4][4];
#pragma unroll
                for (int q = 0; q < 4; q++)
                    ldsm4t(bfr[q], Bk + (uint32_t)((kt * 16 + bRow) * 1040 +
                           (wid * 64 + q * 16) * 2 + bCol));
#pragma unroll
                for (int mti = 0; mti < 2; mti++) {
                    uint32_t af[4];
                    ldsm4(af, Ard + (uint32_t)((mti * 16 + aRow) * 272 +
                           kt * 32 + aCol));
#pragma unroll
                    for (int nt = 0; nt < 8; nt++)
                        mma16816(acc0[mti][nt], af, bfr[nt >> 1][(nt & 1) * 2],
                                 bfr[nt >> 1][(nt & 1) * 2 + 1]);
                }
                if (kt == 3) PREF(1, 1);
            }

            // ph2: mma rows 32-63 (mt 2,3) interleaved with pw rows j=0..3
#pragma unroll
            for (int kt = 0; kt < 8; kt++) {
                uint32_t bfr[4][4];
#pragma unroll
                for (int q = 0; q < 4; q++)
                    ldsm4t(bfr[q], Bk + (uint32_t)((kt * 16 + bRow) * 1040 +
                           (wid * 64 + q * 16) * 2 + bCol));
#pragma unroll
                for (int mti = 0; mti < 2; mti++) {
                    uint32_t af[4];
                    ldsm4(af, Ard + (uint32_t)(((2 + mti) * 16 + aRow) * 272 +
                           kt * 32 + aCol));
#pragma unroll
                    for (int nt = 0; nt < 8; nt++)
                        mma16816(acc1[mti][nt], af, bfr[nt >> 1][(nt & 1) * 2],
                                 bfr[nt >> 1][(nt & 1) * 2 + 1]);
                }
                if (kt & 1) {
                    const int j = kt >> 1;                     // 0..3
                    uint4 cur0 = pf[j & 1][0], cur1 = pf[j & 1][1];
                    PREF(j + 2, j & 1);
                    ROWARGS(j);
                    pw_row<true>(acc0[j >> 1], j & 1, c + j * 4,
                                 cur0, cur1, aw, ghp);
                }
            }

            // ph3: pw rows j=4..7
#pragma unroll
            for (int j = 4; j < 8; j++) {
                uint4 cur0 = pf[j & 1][0], cur1 = pf[j & 1][1];
                if (j + 2 < 8) PREF(j + 2, j & 1);
                ROWARGS(j);
                pw_row<true>(acc1[(j >> 1) - 2], j & 1, c + j * 4,
                             cur0, cur1, aw, ghp);
            }
        } else {
            // t == 0: no recurrent term, pw all 8 rows
            PREF(1, 1);
#pragma unroll
            for (int j = 0; j < 8; j++) {
                uint4 cur0 = pf[j & 1][0], cur1 = pf[j & 1][1];
                if (j + 2 < 8) PREF(j + 2, j & 1);
                ROWARGS(j);
                pw_row<false>(nullptr, j & 1, c + j * 4, cur0, cur1, aw, ghp);
            }
        }

        if (t == 0) cp_wait0();     // B resident before first mma (t=1)
        __syncthreads();            // A buffer handoff
    }
#undef PREF
#undef ROWARGS
}

// ---------------------------------------------------------------------------
// out_mma (unchanged from round 13)
// ---------------------------------------------------------------------------
template<int FO, bool RELU>
__global__ __launch_bounds__(256)
void out_mma(const float* __restrict__ bl, float* __restrict__ OutF)
{
    constexpr int BROW = (FO == 128) ? 272 : 144;
    constexpr int BCH  = BROW / 16;
    constexpr int WN   = FO / 32;
    constexpr int MT   = (FO == 128) ? 4 : 2;

    extern __shared__ char sm[];
    const uint32_t smb = (uint32_t)__cvta_generic_to_shared(sm);
    const uint32_t Asm = smb, Bsm = smb + 69632;
    const int tid = threadIdx.x, wid = tid >> 5, lane = tid & 31;
    const int m0 = blockIdx.x * 128;

    for (int i = tid; i < 4096; i += 256) {
        int r = i >> 5, j = i & 31;
        int node = m0 + r; if (node >= NN) node = NN - 1;
        const char* srcp = (j < 16)
            ? (const char*)g_Hh + (size_t)node * 256 + j * 16
            : (const char*)g_Xh + (size_t)node * 256 + (j - 16) * 16;
        cp16(Asm + (uint32_t)(r * 544 + j * 16), srcp);
    }
    for (int i = tid; i < 256 * BCH; i += 256) {
        int r = i / BCH, j = i % BCH;
        cp16(Bsm + (uint32_t)(r * BROW + j * 16),
             (const char*)g_Wout + (size_t)r * BROW + j * 16);
    }
    cp_commit(); cp_wait0(); __syncthreads();

    const int wn = wid % WN, wm = wid / WN;
    const int aRow = ((lane >> 3) & 1) * 8 + (lane & 7);
    const int aCol = (lane >> 4) * 16;
    const int bRow = aRow;
    const int bCol = ((lane >> 4) & 1) * 16;

    float acc[MT][4][4];
#pragma unroll
    for (int a = 0; a < MT; a++)
#pragma unroll
        for (int b = 0; b < 4; b++)
#pragma unroll
            for (int q = 0; q < 4; q++) acc[a][b][q] = 0.f;

#pragma unroll
    for (int kt = 0; kt < 16; kt++) {
        uint32_t bfr[2][4];
#pragma unroll
        for (int q = 0; q < 2; q++)
            ldsm4t(bfr[q], Bsm + (uint32_t)((kt * 16 + bRow) * BROW +
                   (wn * 32 + q * 16) * 2 + bCol));
#pragma unroll
        for (int mt = 0; mt < MT; mt++) {
            uint32_t af[4];
            ldsm4(af, Asm + (uint32_t)((wm * MT * 16 + mt * 16 + aRow) * 544 +
                   kt * 32 + aCol));
#pragma unroll
            for (int nt = 0; nt < 4; nt++)
                mma16816(acc[mt][nt], af, bfr[nt >> 1][(nt & 1) * 2],
                         bfr[nt >> 1][(nt & 1) * 2 + 1]);
        }
    }

    const int grp = lane >> 2, tig = lane & 3;
#pragma unroll
    for (int nt = 0; nt < 4; nt++) {
        int n = wn * 32 + nt * 8 + 2 * tig;
        float b0 = bl[n], b1 = bl[n + 1];
#pragma unroll
        for (int mt = 0; mt < MT; mt++) {
            int r0 = m0 + wm * MT * 16 + mt * 16 + grp;
#pragma unroll
            for (int half = 0; half < 2; half++) {
                int r = r0 + half * 8;
                if (r >= NN) continue;
                float v0 = acc[mt][nt][half * 2 + 0] + b0;
                float v1 = acc[mt][nt][half * 2 + 1] + b1;
                if (RELU) {
                    v0 = fmaxf(v0, 0.f); v1 = fmaxf(v1, 0.f);
                    ((__half2*)g_Xh)[((size_t)r * 128 + n) >> 1] =
                        __floats2half2_rn(v0, v1);
                } else {
                    *(float2*)(OutF + (size_t)r * FO + n) = make_float2(v0, v1);
                }
            }
        }
    }
}

// ---------------------------------------------------------------------------
// host launcher
// ---------------------------------------------------------------------------
extern "C" void kernel_launch(void* const* d_in, const int* in_sizes, int n_in,
                              void* d_out, int out_size)
{
    (void)in_sizes; (void)n_in; (void)out_size;
    const float* x   = (const float*)d_in[0];
    const int*   src = (const int*)d_in[1];

    const float* P[21];
    for (int i = 0; i < 21; i++) P[i] = (const float*)d_in[2 + i];

    static bool attr_set = false;
    if (!attr_set) {
        cudaFuncSetAttribute(fused_lstm_mma,
                             cudaFuncAttributeMaxDynamicSharedMemorySize, SM_TOTAL);
        cudaFuncSetAttribute(pre_mma,
                             cudaFuncAttributeMaxDynamicSharedMemorySize, PRE_TOT);
        cudaFuncSetAttribute(out_mma<128, true>,
                             cudaFuncAttributeMaxDynamicSharedMemorySize, 139264);
        cudaFuncSetAttribute(out_mma<64, false>,
                             cudaFuncAttributeMaxDynamicSharedMemorySize, 106496);
        attr_set = true;
    }

    const dim3 blk(256);

    conv_x<<<(NN * 64 + 255) / 256, blk>>>(x);

    for (int l = 0; l < 3; l++) {
        const float* Wih = P[7 * l + 0];
        const float* Whh = P[7 * l + 1];
        const float* bih = P[7 * l + 2];
        const float* bhh = P[7 * l + 3];
        const float* Wl  = P[7 * l + 4];
        const float* bl  = P[7 * l + 5];
        const float* Wr  = P[7 * l + 6];

        const int FO   = (l < 2) ? 128 : 64;
        const int BPAD = (l < 2) ? 136 : 72;
        const int convN = 2 * GDIM * FDIM + FO * 256;
        conv_weights<<<(convN + 255) / 256, blk>>>(Whh, Wih, Wl, Wr, FO, BPAD);

        pre_mma<<<(NN + 127) / 128, blk, PRE_TOT>>>(bih, bhh);
        fused_lstm_mma<<<(NN + BMF - 1) / BMF, blk, SM_TOTAL>>>(src);

        if (l < 2)
            out_mma<128, true><<<(NN + 127) / 128, blk, 139264>>>(bl, nullptr);
        else
            out_mma<64, false><<<(NN + 127) / 128, blk, 106496>>>(bl, (float*)d_out);
    }
}